// round 1
// baseline (speedup 1.0000x reference)
#include <cuda_runtime.h>

#define SLEN  2048
#define DDIM  1024
#define NHEAD 16
#define HDIM  64
#define MAXB  2

// ---------------- scratch (device globals; no runtime allocation) ------------
__device__ float g_W  [3 * DDIM * DDIM];                       // 12 MB
__device__ float g_b  [3 * DDIM];
__device__ float g_qkv[3 * MAXB * SLEN * DDIM];                // 48 MB
__device__ float g_sc [(long long)MAXB * NHEAD * SLEN * SLEN]; // 512 MB
__device__ float g_ctx[MAXB * SLEN * DDIM];                    // 16 MB

// ---------------- generic tiled SGEMM ---------------------------------------
// C[m,n] = alpha * sum_k A[m,k] * B(k,n)  (+ bias[n])
// TRB=true  -> B accessed as B[n,k]   (NT gemm)
// Per-z offsets: off = (z % zdiv)*s1 + (z / zdiv)*s2   for A, B, C (and bias s1)
template <int BM, int BN, int BK, int TM, int TN, bool TRB, bool BIAS>
__global__ void __launch_bounds__((BM / TM) * (BN / TN))
sgemm(const float* __restrict__ A, const float* __restrict__ Bm,
      const float* __restrict__ bias, float* __restrict__ C,
      int K, int lda, int ldb, int ldc, int zdiv,
      long sA1, long sA2, long sB1, long sB2, long sC1, long sC2, long sb1,
      float alpha)
{
    constexpr int NT = (BM / TM) * (BN / TN);
    const int tid = threadIdx.x;
    const int z   = blockIdx.z;
    const int zi  = z % zdiv, zo = z / zdiv;
    A  += zi * sA1 + zo * sA2;
    Bm += zi * sB1 + zo * sB2;
    C  += zi * sC1 + zo * sC2;
    if (BIAS) bias += zi * sb1;

    const int m0 = blockIdx.y * BM;
    const int n0 = blockIdx.x * BN;
    const int tx = tid % (BN / TN);
    const int ty = tid / (BN / TN);

    __shared__ __align__(16) float As[BK][BM + 4];
    __shared__ __align__(16) float Bs[BK][BN + 4];

    float acc[TM][TN];
#pragma unroll
    for (int i = 0; i < TM; ++i)
#pragma unroll
        for (int j = 0; j < TN; ++j) acc[i][j] = 0.f;

    for (int k0 = 0; k0 < K; k0 += BK) {
        // ---- load A tile (BM x BK), store transposed As[k][m]
#pragma unroll
        for (int i = 0; i < BM * BK / NT; ++i) {
            int lin = tid + i * NT;
            int k = lin % BK, m = lin / BK;
            As[k][m] = A[(long)(m0 + m) * lda + k0 + k];
        }
        // ---- load B tile -> Bs[k][n]
#pragma unroll
        for (int i = 0; i < BK * BN / NT; ++i) {
            int lin = tid + i * NT;
            if (TRB) {
                int k = lin % BK, n = lin / BK;
                Bs[k][n] = Bm[(long)(n0 + n) * ldb + k0 + k];
            } else {
                int n = lin % BN, k = lin / BN;
                Bs[k][n] = Bm[(long)(k0 + k) * ldb + n0 + n];
            }
        }
        __syncthreads();

#pragma unroll
        for (int kk = 0; kk < BK; ++kk) {
            float a[TM], b[TN];
#pragma unroll
            for (int i = 0; i < TM; i += 4) {
                float4 t = *(const float4*)&As[kk][ty * TM + i];
                a[i] = t.x; a[i + 1] = t.y; a[i + 2] = t.z; a[i + 3] = t.w;
            }
#pragma unroll
            for (int j = 0; j < TN; j += 4) {
                float4 t = *(const float4*)&Bs[kk][tx * TN + j];
                b[j] = t.x; b[j + 1] = t.y; b[j + 2] = t.z; b[j + 3] = t.w;
            }
#pragma unroll
            for (int i = 0; i < TM; ++i)
#pragma unroll
                for (int j = 0; j < TN; ++j) acc[i][j] += a[i] * b[j];
        }
        __syncthreads();
    }

    // ---- epilogue
#pragma unroll
    for (int i = 0; i < TM; ++i) {
        int m = m0 + ty * TM + i;
#pragma unroll
        for (int j = 0; j < TN; j += 4) {
            int n = n0 + tx * TN + j;
            float4 v;
            v.x = acc[i][j + 0] * alpha;
            v.y = acc[i][j + 1] * alpha;
            v.z = acc[i][j + 2] * alpha;
            v.w = acc[i][j + 3] * alpha;
            if (BIAS) {
                v.x += bias[n + 0]; v.y += bias[n + 1];
                v.z += bias[n + 2]; v.w += bias[n + 3];
            }
            *(float4*)&C[(long)m * ldc + n] = v;
        }
    }
}

// ---------------- softmax + attn_mean ----------------------------------------
__device__ __forceinline__ float block_red_max(float v, float* red)
{
#pragma unroll
    for (int o = 16; o > 0; o >>= 1) v = fmaxf(v, __shfl_xor_sync(0xffffffffu, v, o));
    int w = threadIdx.x >> 5;
    if ((threadIdx.x & 31) == 0) red[w] = v;
    __syncthreads();
    if (threadIdx.x == 0) {
        float r = red[0];
#pragma unroll
        for (int i = 1; i < 8; ++i) r = fmaxf(r, red[i]);
        red[8] = r;
    }
    __syncthreads();
    v = red[8];
    __syncthreads();
    return v;
}

__device__ __forceinline__ float block_red_sum(float v, float* red)
{
#pragma unroll
    for (int o = 16; o > 0; o >>= 1) v += __shfl_xor_sync(0xffffffffu, v, o);
    int w = threadIdx.x >> 5;
    if ((threadIdx.x & 31) == 0) red[w] = v;
    __syncthreads();
    if (threadIdx.x == 0) {
        float r = red[0];
#pragma unroll
        for (int i = 1; i < 8; ++i) r += red[i];
        red[8] = r;
    }
    __syncthreads();
    v = red[8];
    __syncthreads();
    return v;
}

// One block per (q, b). In-place softmax over all 16 head rows + head-mean.
__global__ void __launch_bounds__(256)
softmax_attn(float* __restrict__ P, float* __restrict__ attn)
{
    const int q = blockIdx.x, b = blockIdx.y, tid = threadIdx.x;
    __shared__ float red[16];
    float4 a0 = make_float4(0.f, 0.f, 0.f, 0.f);
    float4 a1 = a0;

    for (int h = 0; h < NHEAD; ++h) {
        float4* row = (float4*)(P + (((long)b * NHEAD + h) * SLEN + q) * SLEN);
        float4 v0 = row[tid];
        float4 v1 = row[tid + 256];
        float m = fmaxf(fmaxf(fmaxf(v0.x, v0.y), fmaxf(v0.z, v0.w)),
                        fmaxf(fmaxf(v1.x, v1.y), fmaxf(v1.z, v1.w)));
        m = block_red_max(m, red);

        float4 e0, e1;
        e0.x = __expf(v0.x - m); e0.y = __expf(v0.y - m);
        e0.z = __expf(v0.z - m); e0.w = __expf(v0.w - m);
        e1.x = __expf(v1.x - m); e1.y = __expf(v1.y - m);
        e1.z = __expf(v1.z - m); e1.w = __expf(v1.w - m);

        float s = (e0.x + e0.y + e0.z + e0.w) + (e1.x + e1.y + e1.z + e1.w);
        s = block_red_sum(s, red);
        float inv = 1.f / s;

        e0.x *= inv; e0.y *= inv; e0.z *= inv; e0.w *= inv;
        e1.x *= inv; e1.y *= inv; e1.z *= inv; e1.w *= inv;
        row[tid]       = e0;
        row[tid + 256] = e1;

        a0.x += e0.x; a0.y += e0.y; a0.z += e0.z; a0.w += e0.w;
        a1.x += e1.x; a1.y += e1.y; a1.z += e1.z; a1.w += e1.w;
    }

    const float sc = 1.f / (float)NHEAD;
    a0.x *= sc; a0.y *= sc; a0.z *= sc; a0.w *= sc;
    a1.x *= sc; a1.y *= sc; a1.z *= sc; a1.w *= sc;
    float4* out4 = (float4*)(attn + ((long)b * SLEN + q) * SLEN);
    out4[tid]       = a0;
    out4[tid + 256] = a1;
}

// ---------------- launch ------------------------------------------------------
extern "C" void kernel_launch(void* const* d_in, const int* in_sizes, int n_in,
                              void* d_out, int out_size)
{
    const float* x  = (const float*)d_in[0];
    const float* Wq = (const float*)d_in[1];
    const float* bq = (const float*)d_in[2];
    const float* Wk = (const float*)d_in[3];
    const float* bk = (const float*)d_in[4];
    const float* Wv = (const float*)d_in[5];
    const float* bv = (const float*)d_in[6];
    const float* Wo = (const float*)d_in[7];
    const float* bo = (const float*)d_in[8];
    float* out = (float*)d_out;

    const int Bsz = in_sizes[0] / (SLEN * DDIM);   // = 2
    const long NB = (long)Bsz * SLEN * DDIM;       // per-tensor Q/K/V size

    float *W, *bb, *qkv, *sc, *ctx;
    cudaGetSymbolAddress((void**)&W,   g_W);
    cudaGetSymbolAddress((void**)&bb,  g_b);
    cudaGetSymbolAddress((void**)&qkv, g_qkv);
    cudaGetSymbolAddress((void**)&sc,  g_sc);
    cudaGetSymbolAddress((void**)&ctx, g_ctx);

    // gather weights/biases so the projection runs as one batched launch
    cudaMemcpyAsync(W + 0 * DDIM * DDIM, Wq, sizeof(float) * DDIM * DDIM, cudaMemcpyDeviceToDevice);
    cudaMemcpyAsync(W + 1 * DDIM * DDIM, Wk, sizeof(float) * DDIM * DDIM, cudaMemcpyDeviceToDevice);
    cudaMemcpyAsync(W + 2 * DDIM * DDIM, Wv, sizeof(float) * DDIM * DDIM, cudaMemcpyDeviceToDevice);
    cudaMemcpyAsync(bb + 0 * DDIM, bq, sizeof(float) * DDIM, cudaMemcpyDeviceToDevice);
    cudaMemcpyAsync(bb + 1 * DDIM, bk, sizeof(float) * DDIM, cudaMemcpyDeviceToDevice);
    cudaMemcpyAsync(bb + 2 * DDIM, bv, sizeof(float) * DDIM, cudaMemcpyDeviceToDevice);

    // 1) QKV projection: [Bsz*2048,1024] x [1024,1024], z = {Q,K,V}
    {
        dim3 g(DDIM / 128, (Bsz * SLEN) / 128, 3);
        sgemm<128, 128, 16, 8, 8, false, true><<<g, 256>>>(
            x, W, bb, qkv,
            DDIM, DDIM, DDIM, DDIM,
            3, 0, 0, (long)DDIM * DDIM, 0, NB, 0, DDIM, 1.f);
    }

    // 2) scores = Q K^T / 8 : 32 batches of [2048,2048,64] (NT)
    {
        dim3 g(SLEN / 128, SLEN / 128, Bsz * NHEAD);
        sgemm<128, 128, 16, 8, 8, true, false><<<g, 256>>>(
            qkv, qkv + NB, nullptr, sc,
            HDIM, DDIM, DDIM, SLEN,
            NHEAD, 64, (long)SLEN * DDIM, 64, (long)SLEN * DDIM,
            (long)SLEN * SLEN, (long)NHEAD * SLEN * SLEN, 0, 0.125f);
    }

    // 3) in-place softmax + attn_mean (second output section)
    {
        dim3 g(SLEN, Bsz);
        softmax_attn<<<g, 256>>>(sc, out + NB);
    }

    // 4) ctx = P V : 32 batches of [2048,64,2048] (NN), written into [B,S,D]
    {
        dim3 g(1, SLEN / 128, Bsz * NHEAD);
        sgemm<128, 64, 16, 8, 8, false, false><<<g, 128>>>(
            sc, qkv + 2 * NB, nullptr, ctx,
            SLEN, SLEN, DDIM, DDIM,
            NHEAD, (long)SLEN * SLEN, (long)NHEAD * SLEN * SLEN,
            64, (long)SLEN * DDIM, 64, (long)SLEN * DDIM, 0, 1.f);
    }

    // 5) out = ctx Wo + bo  (first output section)
    {
        dim3 g(DDIM / 128, (Bsz * SLEN) / 128, 1);
        sgemm<128, 128, 16, 8, 8, false, true><<<g, 256>>>(
            ctx, Wo, bo, out,
            DDIM, DDIM, DDIM, DDIM,
            1, 0, 0, 0, 0, 0, 0, 0, 1.f);
    }
}

// round 2
// speedup vs baseline: 2.4862x; 2.4862x over previous
#include <cuda_runtime.h>
#include <cstdint>

#define SLEN  2048
#define DDIM  1024
#define NHEAD 16
#define HDIM  64
#define MAXB  2

// ---------------- scratch (device globals; no runtime allocation) ------------
__device__ float g_W  [3 * DDIM * DDIM];
__device__ float g_b  [3 * DDIM];
__device__ float g_qkv[3 * MAXB * SLEN * DDIM];
__device__ float g_sc [(long long)MAXB * NHEAD * SLEN * SLEN]; // 512 MB
__device__ float g_ctx[MAXB * SLEN * DDIM];

// ---------------- helpers -----------------------------------------------------
__device__ __forceinline__ float tf32r(float x) {
    uint32_t u; asm("cvt.rna.tf32.f32 %0, %1;" : "=r"(u) : "f"(x));
    return __uint_as_float(u);
}

__device__ __forceinline__ void mma8(float* c, const float* a, const float* b) {
    asm volatile(
        "mma.sync.aligned.m16n8k8.row.col.f32.tf32.tf32.f32 "
        "{%0,%1,%2,%3},{%4,%5,%6,%7},{%8,%9},{%0,%1,%2,%3};\n"
        : "+f"(c[0]), "+f"(c[1]), "+f"(c[2]), "+f"(c[3])
        : "r"(__float_as_uint(a[0])), "r"(__float_as_uint(a[1])),
          "r"(__float_as_uint(a[2])), "r"(__float_as_uint(a[3])),
          "r"(__float_as_uint(b[0])), "r"(__float_as_uint(b[1])));
}

// ---------------- TF32 tensor-core GEMM ---------------------------------------
// C[m,n] = alpha * sum_k A[m,k] * B(k,n)  (+ bias[n])
// TRB=true -> B accessed as B[n,k] (NT). Per-z offsets as in round 1.
template <int BM, int BN, int BK, bool TRB, bool BIAS>
__global__ void __launch_bounds__(256)
tgemm(const float* __restrict__ A, const float* __restrict__ Bm,
      const float* __restrict__ bias, float* __restrict__ C,
      int K, int lda, int ldb, int ldc, int zdiv,
      long sA1, long sA2, long sB1, long sB2, long sC1, long sC2, long sb1,
      float alpha)
{
    constexpr int WM = BM / 4;          // warp tile M (4 warps in M)
    constexpr int WN = BN / 2;          // warp tile N (2 warps in N)
    constexpr int MF = WM / 16;         // m16 frags per warp
    constexpr int NF = WN / 8;          // n8 frags per warp
    constexpr int A4 = BM * BK / (4 * 256);  // float4 loads per thread (A)
    constexpr int B4 = BK * BN / (4 * 256);  // float4 loads per thread (B)
    constexpr int KQ = BK / 4;          // float4 per k-row
    constexpr int NQ = BN / 4;          // float4 per n-row

    const int tid = threadIdx.x;
    const int z = blockIdx.z, zi = z % zdiv, zo = z / zdiv;
    A  += zi * sA1 + zo * sA2;
    Bm += zi * sB1 + zo * sB2;
    C  += zi * sC1 + zo * sC2;
    if (BIAS) bias += zi * sb1;

    const int m0 = blockIdx.y * BM;
    const int n0 = blockIdx.x * BN;
    const int w = tid >> 5, lane = tid & 31;
    const int wm = w & 3, wn = w >> 2;
    const int gid = lane >> 2, tg = lane & 3;

    // As stride 36 (mod 32 == 4): conflict-free a-frag loads.
    // Bs stride BN+8 (mod 32 == 8): conflict-free b-frag loads.
    __shared__ __align__(16) float As[BM][BK + 4];
    __shared__ __align__(16) float Bs[BK][BN + 8];

    float acc[MF][NF][4];
#pragma unroll
    for (int i = 0; i < MF; ++i)
#pragma unroll
        for (int j = 0; j < NF; ++j)
#pragma unroll
            for (int r = 0; r < 4; ++r) acc[i][j][r] = 0.f;

    float4 ra[A4], rb[B4];

    auto load_tiles = [&](int kb) {
#pragma unroll
        for (int i = 0; i < A4; ++i) {
            int q = tid + i * 256; int m = q / KQ, kq = q % KQ;
            ra[i] = *(const float4*)&A[(long)(m0 + m) * lda + kb + kq * 4];
        }
        if (TRB) {
#pragma unroll
            for (int i = 0; i < B4; ++i) {
                int q = tid + i * 256; int n = q / KQ, kq = q % KQ;
                rb[i] = *(const float4*)&Bm[(long)(n0 + n) * ldb + kb + kq * 4];
            }
        } else {
#pragma unroll
            for (int i = 0; i < B4; ++i) {
                int q = tid + i * 256; int k = q / NQ, nq = q % NQ;
                rb[i] = *(const float4*)&Bm[(long)(kb + k) * ldb + n0 + nq * 4];
            }
        }
    };

    auto sts_tiles = [&]() {
#pragma unroll
        for (int i = 0; i < A4; ++i) {
            int q = tid + i * 256; int m = q / KQ, kq = q % KQ;
            float4 t;
            t.x = tf32r(ra[i].x); t.y = tf32r(ra[i].y);
            t.z = tf32r(ra[i].z); t.w = tf32r(ra[i].w);
            *(float4*)&As[m][kq * 4] = t;
        }
        if (TRB) {
#pragma unroll
            for (int i = 0; i < B4; ++i) {
                int q = tid + i * 256; int n = q / KQ, kq = q % KQ;
                Bs[kq * 4 + 0][n] = tf32r(rb[i].x);
                Bs[kq * 4 + 1][n] = tf32r(rb[i].y);
                Bs[kq * 4 + 2][n] = tf32r(rb[i].z);
                Bs[kq * 4 + 3][n] = tf32r(rb[i].w);
            }
        } else {
#pragma unroll
            for (int i = 0; i < B4; ++i) {
                int q = tid + i * 256; int k = q / NQ, nq = q % NQ;
                float4 t;
                t.x = tf32r(rb[i].x); t.y = tf32r(rb[i].y);
                t.z = tf32r(rb[i].z); t.w = tf32r(rb[i].w);
                *(float4*)&Bs[k][nq * 4] = t;
            }
        }
    };

    // prologue: tile 0
    load_tiles(0);
    sts_tiles();
    __syncthreads();

    for (int k0 = 0; k0 < K; k0 += BK) {
        const bool more = (k0 + BK) < K;
        if (more) load_tiles(k0 + BK);

        // compute on resident tile
#pragma unroll
        for (int ks = 0; ks < BK / 8; ++ks) {
            const int kk = ks * 8;
            float af[MF][4], bf[NF][2];
#pragma unroll
            for (int mi = 0; mi < MF; ++mi) {
                int m = wm * WM + mi * 16 + gid;
                af[mi][0] = As[m][kk + tg];
                af[mi][1] = As[m + 8][kk + tg];
                af[mi][2] = As[m][kk + tg + 4];
                af[mi][3] = As[m + 8][kk + tg + 4];
            }
#pragma unroll
            for (int nj = 0; nj < NF; ++nj) {
                int n = wn * WN + nj * 8 + gid;
                bf[nj][0] = Bs[kk + tg][n];
                bf[nj][1] = Bs[kk + tg + 4][n];
            }
#pragma unroll
            for (int mi = 0; mi < MF; ++mi)
#pragma unroll
                for (int nj = 0; nj < NF; ++nj)
                    mma8(acc[mi][nj], af[mi], bf[nj]);
        }
        __syncthreads();
        if (more) {
            sts_tiles();
            __syncthreads();
        }
    }

    // epilogue
#pragma unroll
    for (int mi = 0; mi < MF; ++mi) {
        int r0 = m0 + wm * WM + mi * 16 + gid;
#pragma unroll
        for (int nj = 0; nj < NF; ++nj) {
            int n = n0 + wn * WN + nj * 8 + tg * 2;
            float b0 = 0.f, b1 = 0.f;
            if (BIAS) { b0 = bias[n]; b1 = bias[n + 1]; }
            float2 v;
            v.x = acc[mi][nj][0] * alpha + b0;
            v.y = acc[mi][nj][1] * alpha + b1;
            *(float2*)&C[(long)r0 * ldc + n] = v;
            v.x = acc[mi][nj][2] * alpha + b0;
            v.y = acc[mi][nj][3] * alpha + b1;
            *(float2*)&C[(long)(r0 + 8) * ldc + n] = v;
        }
    }
}

// ---------------- softmax + attn_mean (unchanged, proven) ---------------------
__device__ __forceinline__ float block_red_max(float v, float* red)
{
#pragma unroll
    for (int o = 16; o > 0; o >>= 1) v = fmaxf(v, __shfl_xor_sync(0xffffffffu, v, o));
    int w = threadIdx.x >> 5;
    if ((threadIdx.x & 31) == 0) red[w] = v;
    __syncthreads();
    if (threadIdx.x == 0) {
        float r = red[0];
#pragma unroll
        for (int i = 1; i < 8; ++i) r = fmaxf(r, red[i]);
        red[8] = r;
    }
    __syncthreads();
    v = red[8];
    __syncthreads();
    return v;
}

__device__ __forceinline__ float block_red_sum(float v, float* red)
{
#pragma unroll
    for (int o = 16; o > 0; o >>= 1) v += __shfl_xor_sync(0xffffffffu, v, o);
    int w = threadIdx.x >> 5;
    if ((threadIdx.x & 31) == 0) red[w] = v;
    __syncthreads();
    if (threadIdx.x == 0) {
        float r = red[0];
#pragma unroll
        for (int i = 1; i < 8; ++i) r += red[i];
        red[8] = r;
    }
    __syncthreads();
    v = red[8];
    __syncthreads();
    return v;
}

__global__ void __launch_bounds__(256)
softmax_attn(float* __restrict__ P, float* __restrict__ attn)
{
    const int q = blockIdx.x, b = blockIdx.y, tid = threadIdx.x;
    __shared__ float red[16];
    float4 a0 = make_float4(0.f, 0.f, 0.f, 0.f);
    float4 a1 = a0;

    for (int h = 0; h < NHEAD; ++h) {
        float4* row = (float4*)(P + (((long)b * NHEAD + h) * SLEN + q) * SLEN);
        float4 v0 = row[tid];
        float4 v1 = row[tid + 256];
        float m = fmaxf(fmaxf(fmaxf(v0.x, v0.y), fmaxf(v0.z, v0.w)),
                        fmaxf(fmaxf(v1.x, v1.y), fmaxf(v1.z, v1.w)));
        m = block_red_max(m, red);

        float4 e0, e1;
        e0.x = __expf(v0.x - m); e0.y = __expf(v0.y - m);
        e0.z = __expf(v0.z - m); e0.w = __expf(v0.w - m);
        e1.x = __expf(v1.x - m); e1.y = __expf(v1.y - m);
        e1.z = __expf(v1.z - m); e1.w = __expf(v1.w - m);

        float s = (e0.x + e0.y + e0.z + e0.w) + (e1.x + e1.y + e1.z + e1.w);
        s = block_red_sum(s, red);
        float inv = 1.f / s;

        e0.x *= inv; e0.y *= inv; e0.z *= inv; e0.w *= inv;
        e1.x *= inv; e1.y *= inv; e1.z *= inv; e1.w *= inv;
        row[tid]       = e0;
        row[tid + 256] = e1;

        a0.x += e0.x; a0.y += e0.y; a0.z += e0.z; a0.w += e0.w;
        a1.x += e1.x; a1.y += e1.y; a1.z += e1.z; a1.w += e1.w;
    }

    const float sc = 1.f / (float)NHEAD;
    a0.x *= sc; a0.y *= sc; a0.z *= sc; a0.w *= sc;
    a1.x *= sc; a1.y *= sc; a1.z *= sc; a1.w *= sc;
    float4* out4 = (float4*)(attn + ((long)b * SLEN + q) * SLEN);
    out4[tid]       = a0;
    out4[tid + 256] = a1;
}

// ---------------- launch ------------------------------------------------------
extern "C" void kernel_launch(void* const* d_in, const int* in_sizes, int n_in,
                              void* d_out, int out_size)
{
    const float* x  = (const float*)d_in[0];
    const float* Wq = (const float*)d_in[1];
    const float* bq = (const float*)d_in[2];
    const float* Wk = (const float*)d_in[3];
    const float* bk = (const float*)d_in[4];
    const float* Wv = (const float*)d_in[5];
    const float* bv = (const float*)d_in[6];
    const float* Wo = (const float*)d_in[7];
    const float* bo = (const float*)d_in[8];
    float* out = (float*)d_out;

    const int Bsz = in_sizes[0] / (SLEN * DDIM);   // = 2
    const long NB = (long)Bsz * SLEN * DDIM;

    float *W, *bb, *qkv, *sc, *ctx;
    cudaGetSymbolAddress((void**)&W,   g_W);
    cudaGetSymbolAddress((void**)&bb,  g_b);
    cudaGetSymbolAddress((void**)&qkv, g_qkv);
    cudaGetSymbolAddress((void**)&sc,  g_sc);
    cudaGetSymbolAddress((void**)&ctx, g_ctx);

    cudaMemcpyAsync(W + 0 * DDIM * DDIM, Wq, sizeof(float) * DDIM * DDIM, cudaMemcpyDeviceToDevice);
    cudaMemcpyAsync(W + 1 * DDIM * DDIM, Wk, sizeof(float) * DDIM * DDIM, cudaMemcpyDeviceToDevice);
    cudaMemcpyAsync(W + 2 * DDIM * DDIM, Wv, sizeof(float) * DDIM * DDIM, cudaMemcpyDeviceToDevice);
    cudaMemcpyAsync(bb + 0 * DDIM, bq, sizeof(float) * DDIM, cudaMemcpyDeviceToDevice);
    cudaMemcpyAsync(bb + 1 * DDIM, bk, sizeof(float) * DDIM, cudaMemcpyDeviceToDevice);
    cudaMemcpyAsync(bb + 2 * DDIM, bv, sizeof(float) * DDIM, cudaMemcpyDeviceToDevice);

    // 1) QKV projection
    {
        dim3 g(DDIM / 128, (Bsz * SLEN) / 128, 3);
        tgemm<128, 128, 32, false, true><<<g, 256>>>(
            x, W, bb, qkv,
            DDIM, DDIM, DDIM, DDIM,
            3, 0, 0, (long)DDIM * DDIM, 0, NB, 0, DDIM, 1.f);
    }

    // 2) scores = Q K^T / 8
    {
        dim3 g(SLEN / 128, SLEN / 128, Bsz * NHEAD);
        tgemm<128, 128, 32, true, false><<<g, 256>>>(
            qkv, qkv + NB, nullptr, sc,
            HDIM, DDIM, DDIM, SLEN,
            NHEAD, 64, (long)SLEN * DDIM, 64, (long)SLEN * DDIM,
            (long)SLEN * SLEN, (long)NHEAD * SLEN * SLEN, 0, 0.125f);
    }

    // 3) softmax + attn_mean
    {
        dim3 g(SLEN, Bsz);
        softmax_attn<<<g, 256>>>(sc, out + NB);
    }

    // 4) ctx = P V
    {
        dim3 g(1, SLEN / 128, Bsz * NHEAD);
        tgemm<128, 64, 32, false, false><<<g, 256>>>(
            sc, qkv + 2 * NB, nullptr, ctx,
            SLEN, SLEN, DDIM, DDIM,
            NHEAD, (long)SLEN * SLEN, (long)NHEAD * SLEN * SLEN,
            64, (long)SLEN * DDIM, 64, (long)SLEN * DDIM, 0, 1.f);
    }

    // 5) out = ctx Wo + bo
    {
        dim3 g(DDIM / 128, (Bsz * SLEN) / 128, 1);
        tgemm<128, 128, 32, false, true><<<g, 256>>>(
            ctx, Wo, bo, out,
            DDIM, DDIM, DDIM, DDIM,
            1, 0, 0, 0, 0, 0, 0, 0, 1.f);
    }
}

// round 3
// speedup vs baseline: 4.0778x; 1.6402x over previous
#include <cuda_runtime.h>
#include <cuda_fp16.h>
#include <cstdint>

#define SLEN  2048
#define DDIM  1024
#define NHEAD 16
#define HDIM  64
#define MAXB  2

using u32 = unsigned int;

// ---------------- scratch (device globals) ------------------------------------
__device__ __half g_wt [4L * DDIM * DDIM];                 // Wq,Wk,Wv,Wo transposed [n][k] fp16
__device__ float  g_b2 [2 * DDIM];                         // packed bq,bk
__device__ __half g_qk [2L * MAXB * SLEN * DDIM];          // Q then K, [s][1024] fp16
__device__ __half g_vt [(long)MAXB * NHEAD * HDIM * SLEN]; // V^T [b][h][d][s] fp16
__device__ __half g_E  [(long)MAXB * NHEAD * SLEN * SLEN]; // exp(scores) fp16 (268MB)
__device__ __half g_ctx[(long)MAXB * SLEN * DDIM];         // ctx fp16
__device__ float  g_rs [MAXB * NHEAD * SLEN];              // 1/rowsum

// ---------------- helpers ------------------------------------------------------
__device__ __forceinline__ u32 pkh2(float a, float b) {
    __half2 h = __floats2half2_rn(a, b);
    return *(u32*)&h;
}

__device__ __forceinline__ void hmma(float* c, const u32* a, const u32* b) {
    asm volatile(
        "mma.sync.aligned.m16n8k16.row.col.f32.f16.f16.f32 "
        "{%0,%1,%2,%3},{%4,%5,%6,%7},{%8,%9},{%0,%1,%2,%3};"
        : "+f"(c[0]), "+f"(c[1]), "+f"(c[2]), "+f"(c[3])
        : "r"(a[0]), "r"(a[1]), "r"(a[2]), "r"(a[3]),
          "r"(b[0]), "r"(b[1]));
}

// ---------------- universal fp16 NT GEMM ---------------------------------------
// C(m,n) = epi( sum_k A[m,k] * B[n,k] )
// A: fp32 (AF32) or fp16, m-major, lda. B: fp16, n-major, ldb.
// EPI: 0=fp32+bias  1=fp16+bias(QK)  2=fp16 V-transpose scatter+bias
//      3=fp16 exp(acc/8)  4=fp16 acc*invZ[row]
template <int BM, int BN, int BK, int WGM, int WGN, bool AF32, int EPI>
__global__ void __launch_bounds__(256)
hgemm(const void* __restrict__ Av, const __half* __restrict__ B,
      const float* __restrict__ bias, void* __restrict__ Cv,
      const float* __restrict__ rs,
      int K, int lda, int ldb, int ldc, int zdiv,
      long sA1, long sA2, long sB1, long sB2, long sC1, long sC2, long sb1)
{
    constexpr int WM = BM / WGM, WN = BN / WGN;
    constexpr int MF = WM / 16, NF = WN / 8;
    constexpr int KU = BK / 8;                 // uint4 units per tile row
    constexpr int AU = BM * KU / 256;
    constexpr int BU = BN * KU / 256;
    constexpr int BKP = BK + 8;

    const int tid = threadIdx.x;
    const int z = blockIdx.z, zi = z % zdiv, zo = z / zdiv;
    const float* Af = (const float*)Av;
    const __half* Ah = (const __half*)Av;
    if (AF32) Af += zi * sA1 + zo * sA2; else Ah += zi * sA1 + zo * sA2;
    B += zi * sB1 + zo * sB2;
    if (EPI == 4) rs += (long)z * SLEN;

    const int m0 = blockIdx.y * BM;
    const int n0 = blockIdx.x * BN;
    const int w = tid >> 5, lane = tid & 31;
    const int gid = lane >> 2, tg = lane & 3;
    const int wm = w % WGM, wn = w / WGM;

    __shared__ __align__(16) __half As[BM][BKP];
    __shared__ __align__(16) __half Bs[BN][BKP];

    float acc[MF][NF][4];
#pragma unroll
    for (int i = 0; i < MF; ++i)
#pragma unroll
        for (int j = 0; j < NF; ++j)
#pragma unroll
            for (int r = 0; r < 4; ++r) acc[i][j][r] = 0.f;

    uint4 rA[AU], rB[BU];
    float4 rAF[AF32 ? 2 * AU : 1];

    auto load_tiles = [&](int kb) {
#pragma unroll
        for (int i = 0; i < AU; ++i) {
            int q = tid + i * 256; int m = q / KU, ku = q % KU;
            if (AF32) {
                const float* p = Af + (long)(m0 + m) * lda + kb + ku * 8;
                rAF[2 * i]     = *(const float4*)p;
                rAF[2 * i + 1] = *(const float4*)(p + 4);
            } else {
                rA[i] = *(const uint4*)(Ah + (long)(m0 + m) * lda + kb + ku * 8);
            }
        }
#pragma unroll
        for (int i = 0; i < BU; ++i) {
            int q = tid + i * 256; int n = q / KU, ku = q % KU;
            rB[i] = *(const uint4*)(B + (long)(n0 + n) * ldb + kb + ku * 8);
        }
    };

    auto sts_tiles = [&]() {
#pragma unroll
        for (int i = 0; i < AU; ++i) {
            int q = tid + i * 256; int m = q / KU, ku = q % KU;
            uint4 u;
            if (AF32) {
                u.x = pkh2(rAF[2*i].x,   rAF[2*i].y);
                u.y = pkh2(rAF[2*i].z,   rAF[2*i].w);
                u.z = pkh2(rAF[2*i+1].x, rAF[2*i+1].y);
                u.w = pkh2(rAF[2*i+1].z, rAF[2*i+1].w);
            } else u = rA[i];
            *(uint4*)&As[m][ku * 8] = u;
        }
#pragma unroll
        for (int i = 0; i < BU; ++i) {
            int q = tid + i * 256; int n = q / KU, ku = q % KU;
            *(uint4*)&Bs[n][ku * 8] = rB[i];
        }
    };

    load_tiles(0);
    sts_tiles();
    __syncthreads();

    for (int k0 = 0; k0 < K; k0 += BK) {
        const bool more = (k0 + BK) < K;
        if (more) load_tiles(k0 + BK);

#pragma unroll
        for (int ks = 0; ks < BK / 16; ++ks) {
            const int kk = ks * 16;
            u32 a[MF][4], b[NF][2];
#pragma unroll
            for (int mi = 0; mi < MF; ++mi) {
                int m = wm * WM + mi * 16 + gid;
                a[mi][0] = *(const u32*)&As[m][kk + 2 * tg];
                a[mi][1] = *(const u32*)&As[m + 8][kk + 2 * tg];
                a[mi][2] = *(const u32*)&As[m][kk + 8 + 2 * tg];
                a[mi][3] = *(const u32*)&As[m + 8][kk + 8 + 2 * tg];
            }
#pragma unroll
            for (int nj = 0; nj < NF; ++nj) {
                int n = wn * WN + nj * 8 + gid;
                b[nj][0] = *(const u32*)&Bs[n][kk + 2 * tg];
                b[nj][1] = *(const u32*)&Bs[n][kk + 8 + 2 * tg];
            }
#pragma unroll
            for (int mi = 0; mi < MF; ++mi)
#pragma unroll
                for (int nj = 0; nj < NF; ++nj)
                    hmma(acc[mi][nj], a[mi], b[nj]);
        }
        __syncthreads();
        if (more) { sts_tiles(); __syncthreads(); }
    }

    // ---------------- epilogue --------------------------------------------------
    float* Cf = (float*)Cv;
    __half* Ch = (__half*)Cv;
    if (EPI != 2) { Cf += zi * sC1 + zo * sC2; Ch += zi * sC1 + zo * sC2; }
    if (EPI == 0 || EPI == 1 || EPI == 2) bias += zi * sb1;

#pragma unroll
    for (int mi = 0; mi < MF; ++mi) {
        int r = m0 + wm * WM + mi * 16 + gid;
        float iz0 = 0.f, iz1 = 0.f;
        if (EPI == 4) { iz0 = rs[r]; iz1 = rs[r + 8]; }
#pragma unroll
        for (int nj = 0; nj < NF; ++nj) {
            int n = n0 + wn * WN + nj * 8 + 2 * tg;
            float* c = acc[mi][nj];
            if (EPI == 0) {
                float b0 = bias[n], b1 = bias[n + 1];
                *(float2*)&Cf[(long)r * ldc + n]       = make_float2(c[0] + b0, c[1] + b1);
                *(float2*)&Cf[(long)(r + 8) * ldc + n] = make_float2(c[2] + b0, c[3] + b1);
            } else if (EPI == 1) {
                float b0 = bias[n], b1 = bias[n + 1];
                *(u32*)&Ch[(long)r * ldc + n]       = pkh2(c[0] + b0, c[1] + b1);
                *(u32*)&Ch[(long)(r + 8) * ldc + n] = pkh2(c[2] + b0, c[3] + b1);
            } else if (EPI == 2) {
                // V^T scatter: Vt[b][h][d][s], r encodes b*2048+s, n encodes h*64+d
                float b0 = bias[n], b1 = bias[n + 1];
                int bb0 = r >> 11, s0 = r & 2047;
                int bb1 = (r + 8) >> 11, s1 = (r + 8) & 2047;
                long base0 = ((long)(bb0 * NHEAD) * HDIM) * SLEN;
                long base1 = ((long)(bb1 * NHEAD) * HDIM) * SLEN;
                Ch[base0 + (long)n * SLEN + s0]       = __float2half(c[0] + b0);
                Ch[base0 + (long)(n + 1) * SLEN + s0] = __float2half(c[1] + b1);
                Ch[base1 + (long)n * SLEN + s1]       = __float2half(c[2] + b0);
                Ch[base1 + (long)(n + 1) * SLEN + s1] = __float2half(c[3] + b1);
            } else if (EPI == 3) {
                *(u32*)&Ch[(long)r * ldc + n] =
                    pkh2(__expf(c[0] * 0.125f), __expf(c[1] * 0.125f));
                *(u32*)&Ch[(long)(r + 8) * ldc + n] =
                    pkh2(__expf(c[2] * 0.125f), __expf(c[3] * 0.125f));
            } else { // EPI == 4
                *(u32*)&Ch[(long)r * ldc + n]       = pkh2(c[0] * iz0, c[1] * iz0);
                *(u32*)&Ch[(long)(r + 8) * ldc + n] = pkh2(c[2] * iz1, c[3] * iz1);
            }
        }
    }
}

// ---------------- fused rowsum + attn_mean -------------------------------------
// One block per (q, b): loads all 16 head rows of E once into registers,
// computes Z_h, writes invZ and attn_mean = (1/16) sum_h E_h * invZ_h.
__global__ void __launch_bounds__(256)
attn_kernel(const __half* __restrict__ E, float* __restrict__ invz,
            float* __restrict__ attn)
{
    const int q = blockIdx.x, b = blockIdx.y, tid = threadIdx.x;
    const int lane = tid & 31, w = tid >> 5;
    __shared__ float red[NHEAD][8];
    __shared__ float siz[NHEAD];

    uint4 ev[NHEAD];
#pragma unroll
    for (int h = 0; h < NHEAD; ++h) {
        const __half* p = E + (((long)(b * NHEAD + h) * SLEN + q) * SLEN) + tid * 8;
        ev[h] = *(const uint4*)p;
        float2 f0 = __half22float2(*(__half2*)&ev[h].x);
        float2 f1 = __half22float2(*(__half2*)&ev[h].y);
        float2 f2 = __half22float2(*(__half2*)&ev[h].z);
        float2 f3 = __half22float2(*(__half2*)&ev[h].w);
        float v = (f0.x + f0.y) + (f1.x + f1.y) + (f2.x + f2.y) + (f3.x + f3.y);
#pragma unroll
        for (int o = 16; o > 0; o >>= 1) v += __shfl_xor_sync(0xffffffffu, v, o);
        if (lane == 0) red[h][w] = v;
    }
    __syncthreads();
    if (tid < NHEAD) {
        float s = 0.f;
#pragma unroll
        for (int i = 0; i < 8; ++i) s += red[tid][i];
        float z = 1.f / s;
        siz[tid] = z;
        invz[(long)(b * NHEAD + tid) * SLEN + q] = z;
    }
    __syncthreads();

    float a[8] = {0, 0, 0, 0, 0, 0, 0, 0};
#pragma unroll
    for (int h = 0; h < NHEAD; ++h) {
        float z = siz[h];
        float2 f0 = __half22float2(*(__half2*)&ev[h].x);
        float2 f1 = __half22float2(*(__half2*)&ev[h].y);
        float2 f2 = __half22float2(*(__half2*)&ev[h].z);
        float2 f3 = __half22float2(*(__half2*)&ev[h].w);
        a[0] += f0.x * z; a[1] += f0.y * z; a[2] += f1.x * z; a[3] += f1.y * z;
        a[4] += f2.x * z; a[5] += f2.y * z; a[6] += f3.x * z; a[7] += f3.y * z;
    }
    const float sc = 1.f / (float)NHEAD;
    float* o = attn + ((long)b * SLEN + q) * SLEN + tid * 8;
    *(float4*)o       = make_float4(a[0] * sc, a[1] * sc, a[2] * sc, a[3] * sc);
    *(float4*)(o + 4) = make_float4(a[4] * sc, a[5] * sc, a[6] * sc, a[7] * sc);
}

// ---------------- weight transpose+convert --------------------------------------
__global__ void __launch_bounds__(256)
prep_w(const float* __restrict__ W0, const float* __restrict__ W1,
       const float* __restrict__ W2, const float* __restrict__ W3,
       __half* __restrict__ Wt)
{
    const int z = blockIdx.z;
    const float* W = (z == 0) ? W0 : (z == 1) ? W1 : (z == 2) ? W2 : W3;
    __half* T = Wt + (long)z * DDIM * DDIM;
    __shared__ float t[32][33];
    const int tx = threadIdx.x, ty = threadIdx.y;
    const int n0 = blockIdx.x * 32, k0 = blockIdx.y * 32;
#pragma unroll
    for (int i = 0; i < 4; ++i)
        t[tx][ty + 8 * i] = W[(long)(k0 + ty + 8 * i) * DDIM + n0 + tx];
    __syncthreads();
#pragma unroll
    for (int i = 0; i < 4; ++i)
        T[(long)(n0 + ty + 8 * i) * DDIM + k0 + tx] = __float2half(t[ty + 8 * i][tx]);
}

// ---------------- launch --------------------------------------------------------
extern "C" void kernel_launch(void* const* d_in, const int* in_sizes, int n_in,
                              void* d_out, int out_size)
{
    const float* x  = (const float*)d_in[0];
    const float* Wq = (const float*)d_in[1];
    const float* bq = (const float*)d_in[2];
    const float* Wk = (const float*)d_in[3];
    const float* bk = (const float*)d_in[4];
    const float* Wv = (const float*)d_in[5];
    const float* bv = (const float*)d_in[6];
    const float* Wo = (const float*)d_in[7];
    const float* bo = (const float*)d_in[8];
    float* out = (float*)d_out;

    const int Bsz = in_sizes[0] / (SLEN * DDIM);   // = 2
    const int BS  = Bsz * SLEN;
    const long NB = (long)BS * DDIM;               // out section size

    __half *wt, *qk, *vt, *E, *ctx;
    float *b2, *rs;
    cudaGetSymbolAddress((void**)&wt,  g_wt);
    cudaGetSymbolAddress((void**)&b2,  g_b2);
    cudaGetSymbolAddress((void**)&qk,  g_qk);
    cudaGetSymbolAddress((void**)&vt,  g_vt);
    cudaGetSymbolAddress((void**)&E,   g_E);
    cudaGetSymbolAddress((void**)&ctx, g_ctx);
    cudaGetSymbolAddress((void**)&rs,  g_rs);

    cudaMemcpyAsync(b2,        bq, sizeof(float) * DDIM, cudaMemcpyDeviceToDevice);
    cudaMemcpyAsync(b2 + DDIM, bk, sizeof(float) * DDIM, cudaMemcpyDeviceToDevice);

    // 0) transpose+convert all 4 weight matrices
    prep_w<<<dim3(32, 32, 4), dim3(32, 8)>>>(Wq, Wk, Wv, Wo, wt);

    const long QKoff = (long)BS * DDIM;

    // 1) Q,K projection (fp32 A, fp16 out)
    hgemm<128, 128, 32, 2, 4, true, 1><<<dim3(8, BS / 128, 2), 256>>>(
        x, wt, b2, qk, nullptr,
        DDIM, DDIM, DDIM, DDIM, 2,
        0, 0, (long)DDIM * DDIM, 0, QKoff, 0, DDIM);

    // 2) V projection -> V^T scatter
    hgemm<128, 128, 32, 2, 4, true, 2><<<dim3(8, BS / 128, 1), 256>>>(
        x, wt + 2L * DDIM * DDIM, bv, vt, nullptr,
        DDIM, DDIM, DDIM, 0, 1,
        0, 0, 0, 0, 0, 0, 0);

    // 3) E = exp(Q K^T / 8)  (fp16 A/B, fp16 out)
    hgemm<128, 128, 32, 2, 4, false, 3><<<dim3(16, 16, Bsz * NHEAD), 256>>>(
        qk, qk + QKoff, nullptr, E, nullptr,
        HDIM, DDIM, DDIM, SLEN, NHEAD,
        HDIM, (long)SLEN * DDIM, HDIM, (long)SLEN * DDIM,
        (long)SLEN * SLEN, (long)NHEAD * SLEN * SLEN, 0);

    // 4) rowsums (invZ) + attn_mean output
    attn_kernel<<<dim3(SLEN, Bsz), 256>>>(E, rs, out + NB);

    // 5) ctx = (E * invZ) @ V : per (b,h), N=64
    hgemm<128, 64, 32, 4, 2, false, 4><<<dim3(1, SLEN / 128, Bsz * NHEAD), 256>>>(
        E, vt, nullptr, ctx, rs,
        SLEN, SLEN, SLEN, DDIM, NHEAD,
        (long)SLEN * SLEN, (long)NHEAD * SLEN * SLEN,
        (long)HDIM * SLEN, (long)NHEAD * HDIM * SLEN,
        HDIM, (long)SLEN * DDIM, 0);

    // 6) out = ctx @ Wo + bo (fp16 A, fp32 out)
    hgemm<128, 128, 32, 2, 4, false, 0><<<dim3(8, BS / 128, 1), 256>>>(
        ctx, wt + 3L * DDIM * DDIM, bo, out, nullptr,
        DDIM, DDIM, DDIM, DDIM, 1,
        0, 0, 0, 0, 0, 0, 0);
}

// round 4
// speedup vs baseline: 5.2669x; 1.2916x over previous
#include <cuda_runtime.h>
#include <cuda_fp16.h>
#include <cstdint>

#define SLEN  2048
#define DDIM  1024
#define NHEAD 16
#define HDIM  64
#define MAXB  2

using u32 = unsigned int;

// ---------------- scratch (device globals) ------------------------------------
__device__ __half g_wt [4L * DDIM * DDIM];                 // W{q,k,v,o}^T [n][k] fp16
__device__ float  g_b2 [2 * DDIM];                         // packed bq,bk
__device__ __half g_xh [(long)MAXB * SLEN * DDIM];         // x in fp16
__device__ __half g_qk [2L * MAXB * SLEN * DDIM];          // Q then K fp16
__device__ __half g_vt [(long)MAXB * NHEAD * HDIM * SLEN]; // V^T [b][h][d][s]
__device__ __half g_E  [(long)MAXB * NHEAD * SLEN * SLEN]; // exp(scores) fp16
__device__ __half g_ctx[(long)MAXB * SLEN * DDIM];
__device__ float  g_rs [MAXB * NHEAD * SLEN];              // 1/rowsum

// ---------------- helpers ------------------------------------------------------
__device__ __forceinline__ u32 pkh2(float a, float b) {
    __half2 h = __floats2half2_rn(a, b);
    return *(u32*)&h;
}

__device__ __forceinline__ void hmma(float* c, const u32* a, const u32* b) {
    asm volatile(
        "mma.sync.aligned.m16n8k16.row.col.f32.f16.f16.f32 "
        "{%0,%1,%2,%3},{%4,%5,%6,%7},{%8,%9},{%0,%1,%2,%3};"
        : "+f"(c[0]), "+f"(c[1]), "+f"(c[2]), "+f"(c[3])
        : "r"(a[0]), "r"(a[1]), "r"(a[2]), "r"(a[3]), "r"(b[0]), "r"(b[1]));
}

__device__ __forceinline__ void ldsm4(u32& r0, u32& r1, u32& r2, u32& r3, u32 saddr) {
    asm volatile("ldmatrix.sync.aligned.m8n8.x4.shared.b16 {%0,%1,%2,%3}, [%4];"
                 : "=r"(r0), "=r"(r1), "=r"(r2), "=r"(r3) : "r"(saddr));
}

__device__ __forceinline__ void cpa16(u32 dst, const void* src) {
    asm volatile("cp.async.cg.shared.global [%0], [%1], 16;" :: "r"(dst), "l"(src));
}
__device__ __forceinline__ void cpa_commit() {
    asm volatile("cp.async.commit_group;" ::: "memory");
}
__device__ __forceinline__ void cpa_wait1() {
    asm volatile("cp.async.wait_group 1;" ::: "memory");
}

// ---------------- pipelined fp16 NT GEMM ---------------------------------------
// C(m,n) = epi( sum_k A[m,k] * B[n,k] ); A,B fp16; 3-stage cp.async; ldmatrix.
// EPI: 0=fp32+bias  1=fp16+bias  2=fp16 V^T scatter+bias  3=fp16 exp(acc/8)
//      4=fp16 acc*invZ[row]
template <int BM, int BN, int BK, int WGM, int WGN, int EPI>
__global__ void __launch_bounds__(256)
hgemm(const __half* __restrict__ A, const __half* __restrict__ B,
      const float* __restrict__ bias, void* __restrict__ Cv,
      const float* __restrict__ rs,
      int K, int lda, int ldb, int ldc, int zdiv,
      long sA1, long sA2, long sB1, long sB2, long sC1, long sC2, long sb1)
{
    constexpr int WM = BM / WGM, WN = BN / WGN;
    constexpr int MF = WM / 16, NF = WN / 8;
    constexpr int BKP = BK + 8;                 // 80-byte rows: conflict-free LDSM
    constexpr int ASTG = BM * BKP;              // halves per A stage
    constexpr int BSTG = BN * BKP;
    constexpr int AU4 = BM * (BK / 8) / 256;    // 16B chunks per thread (A)
    constexpr int BU4 = BN * (BK / 8) / 256;

    const int tid = threadIdx.x;
    const int z = blockIdx.z, zi = z % zdiv, zo = z / zdiv;
    A += zi * sA1 + zo * sA2;
    B += zi * sB1 + zo * sB2;
    if (EPI == 4) rs += (long)z * SLEN;

    const int m0 = blockIdx.y * BM;
    const int n0 = blockIdx.x * BN;
    const __half* Agp = A + (long)m0 * lda;
    const __half* Bgp = B + (long)n0 * ldb;

    const int w = tid >> 5, lane = tid & 31;
    const int gid = lane >> 2, tg = lane & 3;
    const int wm = w % WGM, wn = w / WGM;
    const int q8 = lane >> 3, r8 = lane & 7;
    const int rowA = wm * WM + (q8 & 1) * 8 + r8, colA = (q8 >> 1) * 8;
    const int rowB = wn * WN + (q8 >> 1) * 8 + r8, colB = (q8 & 1) * 8;

    extern __shared__ __align__(16) __half smem[];
    const u32 sbase = (u32)__cvta_generic_to_shared(smem);

    float acc[MF][NF][4];
#pragma unroll
    for (int i = 0; i < MF; ++i)
#pragma unroll
        for (int j = 0; j < NF; ++j)
#pragma unroll
            for (int r = 0; r < 4; ++r) acc[i][j][r] = 0.f;

    auto issue = [&](int stage, int kb) {
        const u32 ab = sbase + stage * (ASTG * 2);
#pragma unroll
        for (int i = 0; i < AU4; ++i) {
            int c = tid + i * 256; int row = c >> 2, ku = c & 3;
            cpa16(ab + (row * BKP + ku * 8) * 2, Agp + (long)row * lda + kb + ku * 8);
        }
        const u32 bb = sbase + (3 * ASTG + stage * BSTG) * 2;
#pragma unroll
        for (int i = 0; i < BU4; ++i) {
            int c = tid + i * 256; int row = c >> 2, ku = c & 3;
            cpa16(bb + (row * BKP + ku * 8) * 2, Bgp + (long)row * ldb + kb + ku * 8);
        }
        cpa_commit();
    };

    const int KT = K / BK;
    issue(0, 0);
    issue(1, BK);

    for (int kt = 0; kt < KT; ++kt) {
        cpa_wait1();
        __syncthreads();
        if (kt + 2 < KT) issue((kt + 2) % 3, (kt + 2) * BK);
        else cpa_commit();

        const int stage = kt % 3;
        const u32 ab = sbase + stage * (ASTG * 2);
        const u32 bb = sbase + (3 * ASTG + stage * BSTG) * 2;
#pragma unroll
        for (int ks = 0; ks < BK / 16; ++ks) {
            const int kk = ks * 16;
            u32 a[MF][4], b[NF][2];
#pragma unroll
            for (int mi = 0; mi < MF; ++mi)
                ldsm4(a[mi][0], a[mi][1], a[mi][2], a[mi][3],
                      ab + ((rowA + mi * 16) * BKP + kk + colA) * 2);
#pragma unroll
            for (int p = 0; p < NF / 2; ++p)
                ldsm4(b[2 * p][0], b[2 * p][1], b[2 * p + 1][0], b[2 * p + 1][1],
                      bb + ((rowB + p * 16) * BKP + kk + colB) * 2);
#pragma unroll
            for (int mi = 0; mi < MF; ++mi)
#pragma unroll
                for (int nj = 0; nj < NF; ++nj)
                    hmma(acc[mi][nj], a[mi], b[nj]);
        }
    }

    // ---------------- epilogue --------------------------------------------------
    float* Cf = (float*)Cv;
    __half* Ch = (__half*)Cv;
    if (EPI != 2) { Cf += zi * sC1 + zo * sC2; Ch += zi * sC1 + zo * sC2; }
    if (EPI == 0 || EPI == 1 || EPI == 2) bias += zi * sb1;

#pragma unroll
    for (int mi = 0; mi < MF; ++mi) {
        int r = m0 + wm * WM + mi * 16 + gid;
        float iz0 = 0.f, iz1 = 0.f;
        if (EPI == 4) { iz0 = rs[r]; iz1 = rs[r + 8]; }
#pragma unroll
        for (int nj = 0; nj < NF; ++nj) {
            int n = n0 + wn * WN + nj * 8 + 2 * tg;
            float* c = acc[mi][nj];
            if (EPI == 0) {
                float b0 = bias[n], b1 = bias[n + 1];
                *(float2*)&Cf[(long)r * ldc + n]       = make_float2(c[0] + b0, c[1] + b1);
                *(float2*)&Cf[(long)(r + 8) * ldc + n] = make_float2(c[2] + b0, c[3] + b1);
            } else if (EPI == 1) {
                float b0 = bias[n], b1 = bias[n + 1];
                *(u32*)&Ch[(long)r * ldc + n]       = pkh2(c[0] + b0, c[1] + b1);
                *(u32*)&Ch[(long)(r + 8) * ldc + n] = pkh2(c[2] + b0, c[3] + b1);
            } else if (EPI == 2) {
                float b0 = bias[n], b1 = bias[n + 1];
                int bb0 = r >> 11, s0 = r & 2047;
                int bb1 = (r + 8) >> 11, s1 = (r + 8) & 2047;
                long base0 = ((long)(bb0 * NHEAD) * HDIM) * SLEN;
                long base1 = ((long)(bb1 * NHEAD) * HDIM) * SLEN;
                Ch[base0 + (long)n * SLEN + s0]       = __float2half(c[0] + b0);
                Ch[base0 + (long)(n + 1) * SLEN + s0] = __float2half(c[1] + b1);
                Ch[base1 + (long)n * SLEN + s1]       = __float2half(c[2] + b0);
                Ch[base1 + (long)(n + 1) * SLEN + s1] = __float2half(c[3] + b1);
            } else if (EPI == 3) {
                *(u32*)&Ch[(long)r * ldc + n] =
                    pkh2(__expf(c[0] * 0.125f), __expf(c[1] * 0.125f));
                *(u32*)&Ch[(long)(r + 8) * ldc + n] =
                    pkh2(__expf(c[2] * 0.125f), __expf(c[3] * 0.125f));
            } else {
                *(u32*)&Ch[(long)r * ldc + n]       = pkh2(c[0] * iz0, c[1] * iz0);
                *(u32*)&Ch[(long)(r + 8) * ldc + n] = pkh2(c[2] * iz1, c[3] * iz1);
            }
        }
    }
}

// ---------------- fused rowsum + attn_mean -------------------------------------
__global__ void __launch_bounds__(256)
attn_kernel(const __half* __restrict__ E, float* __restrict__ invz,
            float* __restrict__ attn)
{
    const int q = blockIdx.x, b = blockIdx.y, tid = threadIdx.x;
    const int lane = tid & 31, w = tid >> 5;
    __shared__ float red[NHEAD][8];
    __shared__ float siz[NHEAD];

    uint4 ev[NHEAD];
#pragma unroll
    for (int h = 0; h < NHEAD; ++h) {
        const __half* p = E + (((long)(b * NHEAD + h) * SLEN + q) * SLEN) + tid * 8;
        ev[h] = *(const uint4*)p;
        float2 f0 = __half22float2(*(__half2*)&ev[h].x);
        float2 f1 = __half22float2(*(__half2*)&ev[h].y);
        float2 f2 = __half22float2(*(__half2*)&ev[h].z);
        float2 f3 = __half22float2(*(__half2*)&ev[h].w);
        float v = (f0.x + f0.y) + (f1.x + f1.y) + (f2.x + f2.y) + (f3.x + f3.y);
#pragma unroll
        for (int o = 16; o > 0; o >>= 1) v += __shfl_xor_sync(0xffffffffu, v, o);
        if (lane == 0) red[h][w] = v;
    }
    __syncthreads();
    if (tid < NHEAD) {
        float s = 0.f;
#pragma unroll
        for (int i = 0; i < 8; ++i) s += red[tid][i];
        float z = 1.f / s;
        siz[tid] = z;
        invz[(long)(b * NHEAD + tid) * SLEN + q] = z;
    }
    __syncthreads();

    float a[8] = {0, 0, 0, 0, 0, 0, 0, 0};
#pragma unroll
    for (int h = 0; h < NHEAD; ++h) {
        float z = siz[h];
        float2 f0 = __half22float2(*(__half2*)&ev[h].x);
        float2 f1 = __half22float2(*(__half2*)&ev[h].y);
        float2 f2 = __half22float2(*(__half2*)&ev[h].z);
        float2 f3 = __half22float2(*(__half2*)&ev[h].w);
        a[0] += f0.x * z; a[1] += f0.y * z; a[2] += f1.x * z; a[3] += f1.y * z;
        a[4] += f2.x * z; a[5] += f2.y * z; a[6] += f3.x * z; a[7] += f3.y * z;
    }
    const float sc = 1.f / (float)NHEAD;
    float* o = attn + ((long)b * SLEN + q) * SLEN + tid * 8;
    *(float4*)o       = make_float4(a[0] * sc, a[1] * sc, a[2] * sc, a[3] * sc);
    *(float4*)(o + 4) = make_float4(a[4] * sc, a[5] * sc, a[6] * sc, a[7] * sc);
}

// ---------------- prep kernels ---------------------------------------------------
__global__ void __launch_bounds__(256)
prep_w(const float* __restrict__ W0, const float* __restrict__ W1,
       const float* __restrict__ W2, const float* __restrict__ W3,
       __half* __restrict__ Wt)
{
    const int z = blockIdx.z;
    const float* W = (z == 0) ? W0 : (z == 1) ? W1 : (z == 2) ? W2 : W3;
    __half* T = Wt + (long)z * DDIM * DDIM;
    __shared__ float t[32][33];
    const int tx = threadIdx.x, ty = threadIdx.y;
    const int n0 = blockIdx.x * 32, k0 = blockIdx.y * 32;
#pragma unroll
    for (int i = 0; i < 4; ++i)
        t[tx][ty + 8 * i] = W[(long)(k0 + ty + 8 * i) * DDIM + n0 + tx];
    __syncthreads();
#pragma unroll
    for (int i = 0; i < 4; ++i)
        T[(long)(n0 + ty + 8 * i) * DDIM + k0 + tx] = __float2half(t[ty + 8 * i][tx]);
}

__global__ void __launch_bounds__(256)
prep_x(const float* __restrict__ x, __half* __restrict__ xh)
{
    long i = ((long)blockIdx.x * 256 + threadIdx.x) * 8;
    float4 f0 = *(const float4*)(x + i);
    float4 f1 = *(const float4*)(x + i + 4);
    uint4 u;
    u.x = pkh2(f0.x, f0.y); u.y = pkh2(f0.z, f0.w);
    u.z = pkh2(f1.x, f1.y); u.w = pkh2(f1.z, f1.w);
    *(uint4*)(xh + i) = u;
}

// ---------------- launch ---------------------------------------------------------
extern "C" void kernel_launch(void* const* d_in, const int* in_sizes, int n_in,
                              void* d_out, int out_size)
{
    const float* x  = (const float*)d_in[0];
    const float* Wq = (const float*)d_in[1];
    const float* bq = (const float*)d_in[2];
    const float* Wk = (const float*)d_in[3];
    const float* bk = (const float*)d_in[4];
    const float* Wv = (const float*)d_in[5];
    const float* bv = (const float*)d_in[6];
    const float* Wo = (const float*)d_in[7];
    const float* bo = (const float*)d_in[8];
    float* out = (float*)d_out;

    const int Bsz = in_sizes[0] / (SLEN * DDIM);   // = 2
    const int BS  = Bsz * SLEN;
    const long NB = (long)BS * DDIM;

    __half *wt, *xh, *qk, *vt, *E, *ctx;
    float *b2, *rs;
    cudaGetSymbolAddress((void**)&wt,  g_wt);
    cudaGetSymbolAddress((void**)&b2,  g_b2);
    cudaGetSymbolAddress((void**)&xh,  g_xh);
    cudaGetSymbolAddress((void**)&qk,  g_qk);
    cudaGetSymbolAddress((void**)&vt,  g_vt);
    cudaGetSymbolAddress((void**)&E,   g_E);
    cudaGetSymbolAddress((void**)&ctx, g_ctx);
    cudaGetSymbolAddress((void**)&rs,  g_rs);

    // raise dynamic-smem limits (idempotent)
    const int SM_A = 3 * (128 * 40 + 128 * 40) * 2;   // 61440
    const int SM_C = 3 * (128 * 40 + 64 * 40) * 2;    // 46080
    cudaFuncSetAttribute(hgemm<128,128,32,2,4,0>, cudaFuncAttributeMaxDynamicSharedMemorySize, SM_A);
    cudaFuncSetAttribute(hgemm<128,128,32,2,4,1>, cudaFuncAttributeMaxDynamicSharedMemorySize, SM_A);
    cudaFuncSetAttribute(hgemm<128,128,32,2,4,2>, cudaFuncAttributeMaxDynamicSharedMemorySize, SM_A);
    cudaFuncSetAttribute(hgemm<128,128,32,2,4,3>, cudaFuncAttributeMaxDynamicSharedMemorySize, SM_A);
    cudaFuncSetAttribute(hgemm<128,64,32,4,2,4>,  cudaFuncAttributeMaxDynamicSharedMemorySize, SM_C);

    cudaMemcpyAsync(b2,        bq, sizeof(float) * DDIM, cudaMemcpyDeviceToDevice);
    cudaMemcpyAsync(b2 + DDIM, bk, sizeof(float) * DDIM, cudaMemcpyDeviceToDevice);

    // 0) prep: x -> fp16, weights -> transposed fp16
    prep_x<<<(unsigned)(NB / (256 * 8)), 256>>>(x, xh);
    prep_w<<<dim3(32, 32, 4), dim3(32, 8)>>>(Wq, Wk, Wv, Wo, wt);

    const long QKoff = (long)BS * DDIM;

    // 1) Q,K projection
    hgemm<128,128,32,2,4,1><<<dim3(8, BS / 128, 2), 256, SM_A>>>(
        xh, wt, b2, qk, nullptr,
        DDIM, DDIM, DDIM, DDIM, 2,
        0, 0, (long)DDIM * DDIM, 0, QKoff, 0, DDIM);

    // 2) V projection -> V^T scatter
    hgemm<128,128,32,2,4,2><<<dim3(8, BS / 128, 1), 256, SM_A>>>(
        xh, wt + 2L * DDIM * DDIM, bv, vt, nullptr,
        DDIM, DDIM, DDIM, 0, 1,
        0, 0, 0, 0, 0, 0, 0);

    // 3) E = exp(Q K^T / 8)
    hgemm<128,128,32,2,4,3><<<dim3(16, 16, Bsz * NHEAD), 256, SM_A>>>(
        qk, qk + QKoff, nullptr, E, nullptr,
        HDIM, DDIM, DDIM, SLEN, NHEAD,
        HDIM, (long)SLEN * DDIM, HDIM, (long)SLEN * DDIM,
        (long)SLEN * SLEN, (long)NHEAD * SLEN * SLEN, 0);

    // 4) rowsums (invZ) + attn_mean output
    attn_kernel<<<dim3(SLEN, Bsz), 256>>>(E, rs, out + NB);

    // 5) ctx = (E * invZ) @ V
    hgemm<128,64,32,4,2,4><<<dim3(1, SLEN / 128, Bsz * NHEAD), 256, SM_C>>>(
        E, vt, nullptr, ctx, rs,
        SLEN, SLEN, SLEN, DDIM, NHEAD,
        (long)SLEN * SLEN, (long)NHEAD * SLEN * SLEN,
        (long)HDIM * SLEN, (long)NHEAD * HDIM * SLEN,
        HDIM, (long)SLEN * DDIM, 0);

    // 6) out = ctx @ Wo + bo
    hgemm<128,128,32,2,4,0><<<dim3(8, BS / 128, 1), 256, SM_A>>>(
        ctx, wt + 3L * DDIM * DDIM, bo, out, nullptr,
        DDIM, DDIM, DDIM, DDIM, 1,
        0, 0, 0, 0, 0, 0, 0);
}

// round 5
// speedup vs baseline: 6.2149x; 1.1800x over previous
#include <cuda_runtime.h>
#include <cuda_fp16.h>
#include <cstdint>

#define SLEN  2048
#define DDIM  1024
#define NHEAD 16
#define HDIM  64
#define MAXB  2

using u32 = unsigned int;

// ---------------- scratch (device globals) ------------------------------------
__device__ __half g_wt [4L * DDIM * DDIM];                 // W{q,k,v,o}^T [n][k] fp16
__device__ float  g_b2 [2 * DDIM];                         // packed bq,bk
__device__ __half g_xh [(long)MAXB * SLEN * DDIM];         // x in fp16
__device__ __half g_qk [2L * MAXB * SLEN * DDIM];          // Q then K fp16
__device__ __half g_vt [(long)MAXB * NHEAD * HDIM * SLEN]; // V^T [b][h][d][s]
__device__ __half g_E  [(long)MAXB * NHEAD * SLEN * SLEN]; // exp(scores) fp16
__device__ __half g_ctx[(long)MAXB * SLEN * DDIM];
__device__ float  g_rs [MAXB * NHEAD * SLEN];              // 1/rowsum

// ---------------- helpers ------------------------------------------------------
__device__ __forceinline__ u32 pkh2(float a, float b) {
    __half2 h = __floats2half2_rn(a, b);
    return *(u32*)&h;
}

__device__ __forceinline__ void hmma(float* c, const u32* a, const u32* b) {
    asm volatile(
        "mma.sync.aligned.m16n8k16.row.col.f32.f16.f16.f32 "
        "{%0,%1,%2,%3},{%4,%5,%6,%7},{%8,%9},{%0,%1,%2,%3};"
        : "+f"(c[0]), "+f"(c[1]), "+f"(c[2]), "+f"(c[3])
        : "r"(a[0]), "r"(a[1]), "r"(a[2]), "r"(a[3]), "r"(b[0]), "r"(b[1]));
}

__device__ __forceinline__ void ldsm4(u32& r0, u32& r1, u32& r2, u32& r3, u32 saddr) {
    asm volatile("ldmatrix.sync.aligned.m8n8.x4.shared.b16 {%0,%1,%2,%3}, [%4];"
                 : "=r"(r0), "=r"(r1), "=r"(r2), "=r"(r3) : "r"(saddr));
}

__device__ __forceinline__ void cpa16(u32 dst, const void* src) {
    asm volatile("cp.async.cg.shared.global [%0], [%1], 16;" :: "r"(dst), "l"(src));
}
__device__ __forceinline__ void cpa_commit() {
    asm volatile("cp.async.commit_group;" ::: "memory");
}
__device__ __forceinline__ void cpa_wait1() {
    asm volatile("cp.async.wait_group 1;" ::: "memory");
}

// ---------------- pipelined fp16 NT GEMM (projections) --------------------------
// EPI: 0=fp32+bias  1=fp16+bias  2=fp16 V^T scatter+bias
template <int BM, int BN, int BK, int WGM, int WGN, int EPI>
__global__ void __launch_bounds__(256)
hgemm(const __half* __restrict__ A, const __half* __restrict__ B,
      const float* __restrict__ bias, void* __restrict__ Cv,
      int K, int lda, int ldb, int ldc, int zdiv,
      long sA1, long sA2, long sB1, long sB2, long sC1, long sC2, long sb1)
{
    constexpr int WM = BM / WGM, WN = BN / WGN;
    constexpr int MF = WM / 16, NF = WN / 8;
    constexpr int BKP = BK + 8;
    constexpr int ASTG = BM * BKP;
    constexpr int BSTG = BN * BKP;
    constexpr int AU4 = BM * (BK / 8) / 256;
    constexpr int BU4 = BN * (BK / 8) / 256;

    const int tid = threadIdx.x;
    const int z = blockIdx.z, zi = z % zdiv, zo = z / zdiv;
    A += zi * sA1 + zo * sA2;
    B += zi * sB1 + zo * sB2;

    const int m0 = blockIdx.y * BM;
    const int n0 = blockIdx.x * BN;
    const __half* Agp = A + (long)m0 * lda;
    const __half* Bgp = B + (long)n0 * ldb;

    const int w = tid >> 5, lane = tid & 31;
    const int gid = lane >> 2, tg = lane & 3;
    const int wm = w % WGM, wn = w / WGM;
    const int q8 = lane >> 3, r8 = lane & 7;
    const int rowA = wm * WM + (q8 & 1) * 8 + r8, colA = (q8 >> 1) * 8;
    const int rowB = wn * WN + (q8 >> 1) * 8 + r8, colB = (q8 & 1) * 8;

    extern __shared__ __align__(16) __half smem[];
    const u32 sbase = (u32)__cvta_generic_to_shared(smem);

    float acc[MF][NF][4];
#pragma unroll
    for (int i = 0; i < MF; ++i)
#pragma unroll
        for (int j = 0; j < NF; ++j)
#pragma unroll
            for (int r = 0; r < 4; ++r) acc[i][j][r] = 0.f;

    auto issue = [&](int stage, int kb) {
        const u32 ab = sbase + stage * (ASTG * 2);
#pragma unroll
        for (int i = 0; i < AU4; ++i) {
            int c = tid + i * 256; int row = c >> 2, ku = c & 3;
            cpa16(ab + (row * BKP + ku * 8) * 2, Agp + (long)row * lda + kb + ku * 8);
        }
        const u32 bb = sbase + (3 * ASTG + stage * BSTG) * 2;
#pragma unroll
        for (int i = 0; i < BU4; ++i) {
            int c = tid + i * 256; int row = c >> 2, ku = c & 3;
            cpa16(bb + (row * BKP + ku * 8) * 2, Bgp + (long)row * ldb + kb + ku * 8);
        }
        cpa_commit();
    };

    const int KT = K / BK;
    issue(0, 0);
    issue(1, BK);

    for (int kt = 0; kt < KT; ++kt) {
        cpa_wait1();
        __syncthreads();
        if (kt + 2 < KT) issue((kt + 2) % 3, (kt + 2) * BK);
        else cpa_commit();

        const int stage = kt % 3;
        const u32 ab = sbase + stage * (ASTG * 2);
        const u32 bb = sbase + (3 * ASTG + stage * BSTG) * 2;
#pragma unroll
        for (int ks = 0; ks < BK / 16; ++ks) {
            const int kk = ks * 16;
            u32 a[MF][4], b[NF][2];
#pragma unroll
            for (int mi = 0; mi < MF; ++mi)
                ldsm4(a[mi][0], a[mi][1], a[mi][2], a[mi][3],
                      ab + ((rowA + mi * 16) * BKP + kk + colA) * 2);
#pragma unroll
            for (int p = 0; p < NF / 2; ++p)
                ldsm4(b[2 * p][0], b[2 * p][1], b[2 * p + 1][0], b[2 * p + 1][1],
                      bb + ((rowB + p * 16) * BKP + kk + colB) * 2);
#pragma unroll
            for (int mi = 0; mi < MF; ++mi)
#pragma unroll
                for (int nj = 0; nj < NF; ++nj)
                    hmma(acc[mi][nj], a[mi], b[nj]);
        }
    }

    float* Cf = (float*)Cv;
    __half* Ch = (__half*)Cv;
    if (EPI != 2) { Cf += zi * sC1 + zo * sC2; Ch += zi * sC1 + zo * sC2; }
    bias += zi * sb1;

#pragma unroll
    for (int mi = 0; mi < MF; ++mi) {
        int r = m0 + wm * WM + mi * 16 + gid;
#pragma unroll
        for (int nj = 0; nj < NF; ++nj) {
            int n = n0 + wn * WN + nj * 8 + 2 * tg;
            float* c = acc[mi][nj];
            float b0 = bias[n], b1 = bias[n + 1];
            if (EPI == 0) {
                *(float2*)&Cf[(long)r * ldc + n]       = make_float2(c[0] + b0, c[1] + b1);
                *(float2*)&Cf[(long)(r + 8) * ldc + n] = make_float2(c[2] + b0, c[3] + b1);
            } else if (EPI == 1) {
                *(u32*)&Ch[(long)r * ldc + n]       = pkh2(c[0] + b0, c[1] + b1);
                *(u32*)&Ch[(long)(r + 8) * ldc + n] = pkh2(c[2] + b0, c[3] + b1);
            } else {
                int bb0 = r >> 11, s0 = r & 2047;
                int bb1 = (r + 8) >> 11, s1 = (r + 8) & 2047;
                long base0 = ((long)(bb0 * NHEAD) * HDIM) * SLEN;
                long base1 = ((long)(bb1 * NHEAD) * HDIM) * SLEN;
                Ch[base0 + (long)n * SLEN + s0]       = __float2half(c[0] + b0);
                Ch[base0 + (long)(n + 1) * SLEN + s0] = __float2half(c[1] + b1);
                Ch[base1 + (long)n * SLEN + s1]       = __float2half(c[2] + b0);
                Ch[base1 + (long)(n + 1) * SLEN + s1] = __float2half(c[3] + b1);
            }
        }
    }
}

// ---------------- fused attention: E=exp(QK^T/8), ctx=(E/Z)V, invZ ---------------
// Block = (m-tile of 128 queries, b*NHEAD+h). 8 warps: WGM=4 (m), WGN=2 (keys).
// 16 key-chunks of 128; 3-stage cp.async on K,V; E frags reused as mma A operands.
__global__ void __launch_bounds__(256, 1)
fused_attn(const __half* __restrict__ Q, const __half* __restrict__ Kg,
           const __half* __restrict__ Vt, __half* __restrict__ E,
           __half* __restrict__ ctx, float* __restrict__ rs)
{
    constexpr int QP = 72;    // Q/K row pad (halves)
    constexpr int VP = 136;   // V row pad
    constexpr int QTILE = 128 * QP;       // halves
    constexpr int VTILE = HDIM * VP;
    constexpr int NC = SLEN / 128;        // 16 chunks

    const int tid = threadIdx.x;
    const int m0 = blockIdx.x * 128;
    const int bh = blockIdx.y;
    const int b = bh / NHEAD, h = bh % NHEAD;

    const __half* Qg = Q  + ((long)b * SLEN + m0) * DDIM + h * HDIM;
    const __half* Kb = Kg + ((long)b * SLEN) * DDIM + h * HDIM;
    const __half* Vg = Vt + (long)bh * HDIM * SLEN;
    __half* Eg = E + (long)bh * SLEN * SLEN;

    const int w = tid >> 5, lane = tid & 31;
    const int gid = lane >> 2, tg = lane & 3;
    const int wm = w & 3, wn = w >> 2;
    const int q8 = lane >> 3, r8 = lane & 7;
    const int rowA = wm * 32 + (q8 & 1) * 8 + r8, colA = (q8 >> 1) * 8;
    const int rowB = wn * 64 + (q8 >> 1) * 8 + r8, colB = (q8 & 1) * 8;
    const int rowV = (q8 >> 1) * 8 + r8,            colV = (q8 & 1) * 8;

    extern __shared__ __align__(16) __half smem[];
    const u32 sbase = (u32)__cvta_generic_to_shared(smem);
    const u32 qb = sbase;
    auto kb = [&](int s) { return sbase + (QTILE + s * QTILE) * 2; };
    auto vb = [&](int s) { return sbase + (4 * QTILE + s * VTILE) * 2; };

    __shared__ float zs[4][32][2];
    __shared__ float siz[128];

    // ---- async loaders -------------------------------------------------------
    auto load_q = [&]() {
#pragma unroll
        for (int i = 0; i < 4; ++i) {
            int c = tid + i * 256; int row = c >> 3, cq = c & 7;
            cpa16(qb + (row * QP + cq * 8) * 2, Qg + (long)row * DDIM + cq * 8);
        }
    };
    auto issue = [&](int chunk) {
        const int stage = chunk % 3;
        const __half* Kp = Kb + (long)(chunk * 128) * DDIM;
        const u32 kbs = kb(stage);
#pragma unroll
        for (int i = 0; i < 4; ++i) {
            int c = tid + i * 256; int row = c >> 3, cq = c & 7;
            cpa16(kbs + (row * QP + cq * 8) * 2, Kp + (long)row * DDIM + cq * 8);
        }
        const __half* Vp = Vg + chunk * 128;
        const u32 vbs = vb(stage);
#pragma unroll
        for (int i = 0; i < 4; ++i) {
            int c = tid + i * 256; int row = c >> 4, cv = c & 15;
            cpa16(vbs + (row * VP + cv * 8) * 2, Vp + (long)row * SLEN + cv * 8);
        }
        cpa_commit();
    };

    float cU[2][8][4];
#pragma unroll
    for (int mi = 0; mi < 2; ++mi)
#pragma unroll
        for (int dj = 0; dj < 8; ++dj)
#pragma unroll
            for (int r = 0; r < 4; ++r) cU[mi][dj][r] = 0.f;
    float zacc[2][2] = {{0.f, 0.f}, {0.f, 0.f}};

    load_q();
    issue(0);     // group 0: Q + chunk 0
    issue(1);     // group 1: chunk 1

    for (int kt = 0; kt < NC; ++kt) {
        cpa_wait1();
        __syncthreads();
        if (kt + 2 < NC) issue(kt + 2);
        else cpa_commit();

        const int stage = kt % 3;
        const u32 kbs = kb(stage), vbs = vb(stage);

        // ---- S = Q K^T (128x128, K=64) ---------------------------------------
        float cS[2][8][4];
#pragma unroll
        for (int mi = 0; mi < 2; ++mi)
#pragma unroll
            for (int nj = 0; nj < 8; ++nj)
#pragma unroll
                for (int r = 0; r < 4; ++r) cS[mi][nj][r] = 0.f;

#pragma unroll
        for (int kf = 0; kf < 4; ++kf) {
            const int kk = kf * 16;
            u32 a[2][4], bfr[8][2];
#pragma unroll
            for (int mi = 0; mi < 2; ++mi)
                ldsm4(a[mi][0], a[mi][1], a[mi][2], a[mi][3],
                      qb + ((rowA + mi * 16) * QP + kk + colA) * 2);
#pragma unroll
            for (int p = 0; p < 4; ++p)
                ldsm4(bfr[2 * p][0], bfr[2 * p][1], bfr[2 * p + 1][0], bfr[2 * p + 1][1],
                      kbs + ((rowB + p * 16) * QP + kk + colB) * 2);
#pragma unroll
            for (int mi = 0; mi < 2; ++mi)
#pragma unroll
                for (int nj = 0; nj < 8; ++nj)
                    hmma(cS[mi][nj], a[mi], bfr[nj]);
        }

        // ---- E = exp(S/8); accumulate Z --------------------------------------
        u32 eh[2][8][2];
#pragma unroll
        for (int mi = 0; mi < 2; ++mi)
#pragma unroll
            for (int nj = 0; nj < 8; ++nj) {
                float e0 = __expf(cS[mi][nj][0] * 0.125f);
                float e1 = __expf(cS[mi][nj][1] * 0.125f);
                float e2 = __expf(cS[mi][nj][2] * 0.125f);
                float e3 = __expf(cS[mi][nj][3] * 0.125f);
                zacc[mi][0] += e0 + e1;
                zacc[mi][1] += e2 + e3;
                eh[mi][nj][0] = pkh2(e0, e1);
                eh[mi][nj][1] = pkh2(e2, e3);
            }

        // ---- U += E * V  (E frags reused as A operands) -----------------------
#pragma unroll
        for (int kf = 0; kf < 4; ++kf) {
            const int kk2 = kf * 16;
            u32 a[2][4], bv[8][2];
#pragma unroll
            for (int mi = 0; mi < 2; ++mi) {
                a[mi][0] = eh[mi][2 * kf][0];
                a[mi][1] = eh[mi][2 * kf][1];
                a[mi][2] = eh[mi][2 * kf + 1][0];
                a[mi][3] = eh[mi][2 * kf + 1][1];
            }
#pragma unroll
            for (int p = 0; p < 4; ++p)
                ldsm4(bv[2 * p][0], bv[2 * p][1], bv[2 * p + 1][0], bv[2 * p + 1][1],
                      vbs + ((rowV + p * 16) * VP + wn * 64 + kk2 + colV) * 2);
#pragma unroll
            for (int mi = 0; mi < 2; ++mi)
#pragma unroll
                for (int dj = 0; dj < 8; ++dj)
                    hmma(cU[mi][dj], a[mi], bv[dj]);
        }

        // ---- stream E tile to gmem -------------------------------------------
        const long ebase = (long)(m0 + wm * 32) * SLEN + kt * 128 + wn * 64;
#pragma unroll
        for (int mi = 0; mi < 2; ++mi) {
            long r0 = ebase + (long)(mi * 16 + gid) * SLEN + 2 * tg;
#pragma unroll
            for (int nj = 0; nj < 8; ++nj) {
                *(u32*)&Eg[r0 + nj * 8]            = eh[mi][nj][0];
                *(u32*)&Eg[r0 + 8L * SLEN + nj * 8] = eh[mi][nj][1];
            }
        }
    }

    __syncthreads();

    // ---- reduce Z: over tg lanes, then across wn -------------------------------
#pragma unroll
    for (int mi = 0; mi < 2; ++mi)
#pragma unroll
        for (int r = 0; r < 2; ++r) {
            float v = zacc[mi][r];
            v += __shfl_xor_sync(0xffffffffu, v, 1);
            v += __shfl_xor_sync(0xffffffffu, v, 2);
            zacc[mi][r] = v;
        }
    if (tg == 0) {
#pragma unroll
        for (int mi = 0; mi < 2; ++mi)
#pragma unroll
            for (int r = 0; r < 2; ++r)
                zs[wm][mi * 16 + r * 8 + gid][wn] = zacc[mi][r];
    }
    __syncthreads();
    if (tid < 128) {
        float inv = 1.f / (zs[tid >> 5][tid & 31][0] + zs[tid >> 5][tid & 31][1]);
        siz[tid] = inv;
        rs[(long)bh * SLEN + m0 + tid] = inv;
    }
    __syncthreads();

    // ---- cross-warp U reduce (2-way over wn) through smem ----------------------
    float* Ured = (float*)smem;   // 128 x 68 fp32, reuses dead tile space
    if (wn == 1) {
#pragma unroll
        for (int mi = 0; mi < 2; ++mi) {
            int r = wm * 32 + mi * 16 + gid;
#pragma unroll
            for (int dj = 0; dj < 8; ++dj) {
                int n = dj * 8 + 2 * tg;
                *(float2*)&Ured[r * 68 + n]       = make_float2(cU[mi][dj][0], cU[mi][dj][1]);
                *(float2*)&Ured[(r + 8) * 68 + n] = make_float2(cU[mi][dj][2], cU[mi][dj][3]);
            }
        }
    }
    __syncthreads();
    if (wn == 0) {
#pragma unroll
        for (int mi = 0; mi < 2; ++mi) {
            int r = wm * 32 + mi * 16 + gid;
            float iz0 = siz[r], iz1 = siz[r + 8];
            __half* C0 = ctx + ((long)b * SLEN + m0 + r) * DDIM + h * HDIM;
#pragma unroll
            for (int dj = 0; dj < 8; ++dj) {
                int n = dj * 8 + 2 * tg;
                float2 u0 = *(const float2*)&Ured[r * 68 + n];
                float2 u1 = *(const float2*)&Ured[(r + 8) * 68 + n];
                *(u32*)&C0[n] = pkh2((cU[mi][dj][0] + u0.x) * iz0,
                                     (cU[mi][dj][1] + u0.y) * iz0);
                *(u32*)&C0[8L * DDIM + n] = pkh2((cU[mi][dj][2] + u1.x) * iz1,
                                                 (cU[mi][dj][3] + u1.y) * iz1);
            }
        }
    }
}

// ---------------- attn_mean (reads precomputed invZ) ----------------------------
__global__ void __launch_bounds__(256)
attn_kernel(const __half* __restrict__ E, const float* __restrict__ rs,
            float* __restrict__ attn)
{
    const int q = blockIdx.x, b = blockIdx.y, tid = threadIdx.x;
    __shared__ float siz[NHEAD];
    if (tid < NHEAD) siz[tid] = rs[(long)(b * NHEAD + tid) * SLEN + q];
    __syncthreads();

    float a[8] = {0, 0, 0, 0, 0, 0, 0, 0};
#pragma unroll
    for (int h = 0; h < NHEAD; ++h) {
        const __half* p = E + (((long)(b * NHEAD + h) * SLEN + q) * SLEN) + tid * 8;
        uint4 ev = *(const uint4*)p;
        float z = siz[h];
        float2 f0 = __half22float2(*(__half2*)&ev.x);
        float2 f1 = __half22float2(*(__half2*)&ev.y);
        float2 f2 = __half22float2(*(__half2*)&ev.z);
        float2 f3 = __half22float2(*(__half2*)&ev.w);
        a[0] += f0.x * z; a[1] += f0.y * z; a[2] += f1.x * z; a[3] += f1.y * z;
        a[4] += f2.x * z; a[5] += f2.y * z; a[6] += f3.x * z; a[7] += f3.y * z;
    }
    const float sc = 1.f / (float)NHEAD;
    float* o = attn + ((long)b * SLEN + q) * SLEN + tid * 8;
    *(float4*)o       = make_float4(a[0] * sc, a[1] * sc, a[2] * sc, a[3] * sc);
    *(float4*)(o + 4) = make_float4(a[4] * sc, a[5] * sc, a[6] * sc, a[7] * sc);
}

// ---------------- prep kernels ---------------------------------------------------
__global__ void __launch_bounds__(256)
prep_w(const float* __restrict__ W0, const float* __restrict__ W1,
       const float* __restrict__ W2, const float* __restrict__ W3,
       __half* __restrict__ Wt)
{
    const int z = blockIdx.z;
    const float* W = (z == 0) ? W0 : (z == 1) ? W1 : (z == 2) ? W2 : W3;
    __half* T = Wt + (long)z * DDIM * DDIM;
    __shared__ float t[32][33];
    const int tx = threadIdx.x, ty = threadIdx.y;
    const int n0 = blockIdx.x * 32, k0 = blockIdx.y * 32;
#pragma unroll
    for (int i = 0; i < 4; ++i)
        t[tx][ty + 8 * i] = W[(long)(k0 + ty + 8 * i) * DDIM + n0 + tx];
    __syncthreads();
#pragma unroll
    for (int i = 0; i < 4; ++i)
        T[(long)(n0 + ty + 8 * i) * DDIM + k0 + tx] = __float2half(t[ty + 8 * i][tx]);
}

__global__ void __launch_bounds__(256)
prep_x(const float* __restrict__ x, __half* __restrict__ xh)
{
    long i = ((long)blockIdx.x * 256 + threadIdx.x) * 8;
    float4 f0 = *(const float4*)(x + i);
    float4 f1 = *(const float4*)(x + i + 4);
    uint4 u;
    u.x = pkh2(f0.x, f0.y); u.y = pkh2(f0.z, f0.w);
    u.z = pkh2(f1.x, f1.y); u.w = pkh2(f1.z, f1.w);
    *(uint4*)(xh + i) = u;
}

// ---------------- launch ---------------------------------------------------------
extern "C" void kernel_launch(void* const* d_in, const int* in_sizes, int n_in,
                              void* d_out, int out_size)
{
    const float* x  = (const float*)d_in[0];
    const float* Wq = (const float*)d_in[1];
    const float* bq = (const float*)d_in[2];
    const float* Wk = (const float*)d_in[3];
    const float* bk = (const float*)d_in[4];
    const float* Wv = (const float*)d_in[5];
    const float* bv = (const float*)d_in[6];
    const float* Wo = (const float*)d_in[7];
    const float* bo = (const float*)d_in[8];
    float* out = (float*)d_out;

    const int Bsz = in_sizes[0] / (SLEN * DDIM);   // = 2
    const int BS  = Bsz * SLEN;
    const long NB = (long)BS * DDIM;

    __half *wt, *xh, *qk, *vt, *E, *ctx;
    float *b2, *rs;
    cudaGetSymbolAddress((void**)&wt,  g_wt);
    cudaGetSymbolAddress((void**)&b2,  g_b2);
    cudaGetSymbolAddress((void**)&xh,  g_xh);
    cudaGetSymbolAddress((void**)&qk,  g_qk);
    cudaGetSymbolAddress((void**)&vt,  g_vt);
    cudaGetSymbolAddress((void**)&E,   g_E);
    cudaGetSymbolAddress((void**)&ctx, g_ctx);
    cudaGetSymbolAddress((void**)&rs,  g_rs);

    const int SM_A = 3 * (128 * 40 + 128 * 40) * 2;            // 61440 (projections)
    const int SM_F = (4 * 128 * 72 + 3 * 64 * 136) * 2;        // 125952 (fused attn)
    cudaFuncSetAttribute(hgemm<128,128,32,2,4,0>, cudaFuncAttributeMaxDynamicSharedMemorySize, SM_A);
    cudaFuncSetAttribute(hgemm<128,128,32,2,4,1>, cudaFuncAttributeMaxDynamicSharedMemorySize, SM_A);
    cudaFuncSetAttribute(hgemm<128,128,32,2,4,2>, cudaFuncAttributeMaxDynamicSharedMemorySize, SM_A);
    cudaFuncSetAttribute(fused_attn, cudaFuncAttributeMaxDynamicSharedMemorySize, SM_F);

    cudaMemcpyAsync(b2,        bq, sizeof(float) * DDIM, cudaMemcpyDeviceToDevice);
    cudaMemcpyAsync(b2 + DDIM, bk, sizeof(float) * DDIM, cudaMemcpyDeviceToDevice);

    // 0) prep: x -> fp16, weights -> transposed fp16
    prep_x<<<(unsigned)(NB / (256 * 8)), 256>>>(x, xh);
    prep_w<<<dim3(32, 32, 4), dim3(32, 8)>>>(Wq, Wk, Wv, Wo, wt);

    const long QKoff = (long)BS * DDIM;

    // 1) Q,K projection
    hgemm<128,128,32,2,4,1><<<dim3(8, BS / 128, 2), 256, SM_A>>>(
        xh, wt, b2, qk,
        DDIM, DDIM, DDIM, DDIM, 2,
        0, 0, (long)DDIM * DDIM, 0, QKoff, 0, DDIM);

    // 2) V projection -> V^T scatter
    hgemm<128,128,32,2,4,2><<<dim3(8, BS / 128, 1), 256, SM_A>>>(
        xh, wt + 2L * DDIM * DDIM, bv, vt,
        DDIM, DDIM, DDIM, 0, 1,
        0, 0, 0, 0, 0, 0, 0);

    // 3) fused: E, invZ, ctx
    fused_attn<<<dim3(SLEN / 128, Bsz * NHEAD), 256, SM_F>>>(
        qk, qk + QKoff, vt, E, ctx, rs);

    // 4) attn_mean output
    attn_kernel<<<dim3(SLEN, Bsz), 256>>>(E, rs, out + NB);

    // 5) out = ctx @ Wo + bo
    hgemm<128,128,32,2,4,0><<<dim3(8, BS / 128, 1), 256, SM_A>>>(
        ctx, wt + 3L * DDIM * DDIM, bo, out,
        DDIM, DDIM, DDIM, DDIM, 1,
        0, 0, 0, 0, 0, 0, 0);
}

// round 7
// speedup vs baseline: 6.3369x; 1.0196x over previous
#include <cuda_runtime.h>
#include <cuda_fp16.h>
#include <cstdint>

#define SLEN  2048
#define DDIM  1024
#define NHEAD 16
#define HDIM  64
#define MAXB  2

using u32 = unsigned int;

// ---------------- scratch (device globals) ------------------------------------
__device__ __half g_wt [4L * DDIM * DDIM];                 // W{q,k,v,o}^T [n][k] fp16
__device__ float  g_b3 [3 * DDIM];                         // packed bq,bk,bv
__device__ __half g_xh [(long)MAXB * SLEN * DDIM];         // x in fp16
__device__ __half g_qk [2L * MAXB * SLEN * DDIM];          // Q then K fp16
__device__ __half g_vt [(long)MAXB * NHEAD * HDIM * SLEN]; // V^T [b][h][d][s]
__device__ __half g_E  [(long)MAXB * NHEAD * SLEN * SLEN]; // exp(scores) fp16
__device__ __half g_ctx[(long)MAXB * SLEN * DDIM];
__device__ float  g_rs [MAXB * NHEAD * SLEN];              // 1/rowsum

// ---------------- helpers ------------------------------------------------------
__device__ __forceinline__ u32 pkh2(float a, float b) {
    __half2 h = __floats2half2_rn(a, b);
    return *(u32*)&h;
}

__device__ __forceinline__ void hmma(float* c, const u32* a, const u32* b) {
    asm volatile(
        "mma.sync.aligned.m16n8k16.row.col.f32.f16.f16.f32 "
        "{%0,%1,%2,%3},{%4,%5,%6,%7},{%8,%9},{%0,%1,%2,%3};"
        : "+f"(c[0]), "+f"(c[1]), "+f"(c[2]), "+f"(c[3])
        : "r"(a[0]), "r"(a[1]), "r"(a[2]), "r"(a[3]), "r"(b[0]), "r"(b[1]));
}

__device__ __forceinline__ void ldsm4(u32& r0, u32& r1, u32& r2, u32& r3, u32 saddr) {
    asm volatile("ldmatrix.sync.aligned.m8n8.x4.shared.b16 {%0,%1,%2,%3}, [%4];"
                 : "=r"(r0), "=r"(r1), "=r"(r2), "=r"(r3) : "r"(saddr));
}

__device__ __forceinline__ void cpa16(u32 dst, const void* src) {
    asm volatile("cp.async.cg.shared.global [%0], [%1], 16;" :: "r"(dst), "l"(src));
}
__device__ __forceinline__ void cpa_commit() {
    asm volatile("cp.async.commit_group;" ::: "memory");
}
__device__ __forceinline__ void cpa_wait1() {
    asm volatile("cp.async.wait_group 1;" ::: "memory");
}

// ---------------- GEMM core: BM=128,BN=128,BK=64, 8 warps (WGM=2,WGN=4) ---------
// acc[mi*4+nj][4], MF=4, NF=4. A,B fp16 K-major, 3-stage cp.async + ldmatrix.
__device__ __forceinline__ void gemm_core_128(
    const __half* __restrict__ Agp, const __half* __restrict__ Bgp,
    int K, int lda, int ldb, u32 sbase, float (*acc)[4])
{
    constexpr int BK = 64, BKP = 72;              // 144B rows, conflict-free
    constexpr u32 TSTG = 128 * BKP * 2;           // bytes per tile per stage
    constexpr u32 STG = 2 * TSTG;                 // A+B stage

    const int tid = threadIdx.x;
    const int w = tid >> 5, lane = tid & 31;
    const int wm = w & 1, wn = w >> 1;            // WGM=2, WGN=4
    const int q8 = lane >> 3, r8 = lane & 7;
    const int rowA = wm * 64 + (q8 & 1) * 8 + r8, colA = (q8 >> 1) * 8;
    const int rowB = wn * 32 + (q8 >> 1) * 8 + r8, colB = (q8 & 1) * 8;

#pragma unroll
    for (int i = 0; i < 16; ++i)
#pragma unroll
        for (int r = 0; r < 4; ++r) acc[i][r] = 0.f;

    auto issue = [&](int stage, int kb) {
        const u32 ab = sbase + stage * STG;
#pragma unroll
        for (int i = 0; i < 4; ++i) {
            int c = tid + i * 256; int row = c >> 3, ku = c & 7;
            cpa16(ab + (u32)(row * BKP + ku * 8) * 2, Agp + (long)row * lda + kb + ku * 8);
        }
        const u32 bb = sbase + stage * STG + TSTG;
#pragma unroll
        for (int i = 0; i < 4; ++i) {
            int c = tid + i * 256; int row = c >> 3, ku = c & 7;
            cpa16(bb + (u32)(row * BKP + ku * 8) * 2, Bgp + (long)row * ldb + kb + ku * 8);
        }
        cpa_commit();
    };

    const int KT = K / BK;
    issue(0, 0);
    issue(1, BK);

    for (int kt = 0; kt < KT; ++kt) {
        cpa_wait1();
        __syncthreads();
        if (kt + 2 < KT) issue((kt + 2) % 3, (kt + 2) * BK);
        else cpa_commit();

        const int stage = kt % 3;
        const u32 ab = sbase + stage * STG;
        const u32 bb = ab + TSTG;
#pragma unroll
        for (int ks = 0; ks < 4; ++ks) {
            const int kk = ks * 16;
            u32 a[4][4], b[4][2];
#pragma unroll
            for (int mi = 0; mi < 4; ++mi)
                ldsm4(a[mi][0], a[mi][1], a[mi][2], a[mi][3],
                      ab + (u32)((rowA + mi * 16) * BKP + kk + colA) * 2);
#pragma unroll
            for (int p = 0; p < 2; ++p)
                ldsm4(b[2 * p][0], b[2 * p][1], b[2 * p + 1][0], b[2 * p + 1][1],
                      bb + (u32)((rowB + p * 16) * BKP + kk + colB) * 2);
#pragma unroll
            for (int mi = 0; mi < 4; ++mi)
#pragma unroll
                for (int nj = 0; nj < 4; ++nj)
                    hmma(acc[mi * 4 + nj], a[mi], b[nj]);
        }
    }
}

// ---------------- QKV projection (one launch, z selects Q/K/V epilogue) ---------
__global__ void __launch_bounds__(256)
qkv_proj(const __half* __restrict__ xh, const __half* __restrict__ wt,
         const float* __restrict__ b3, __half* __restrict__ qk,
         __half* __restrict__ vt, long QKoff)
{
    extern __shared__ __align__(16) __half smem[];
    const u32 sbase = (u32)__cvta_generic_to_shared(smem);
    const int z = blockIdx.z;
    const int m0 = blockIdx.y * 128, n0 = blockIdx.x * 128;

    const __half* Agp = xh + (long)m0 * DDIM;
    const __half* Bgp = wt + (long)z * DDIM * DDIM + (long)n0 * DDIM;
    const float* bias = b3 + z * DDIM;

    float acc[16][4];
    gemm_core_128(Agp, Bgp, DDIM, DDIM, DDIM, sbase, acc);

    const int tid = threadIdx.x;
    const int w = tid >> 5, lane = tid & 31;
    const int wm = w & 1, wn = w >> 1;
    const int gid = lane >> 2, tg = lane & 3;

    if (z < 2) {
        __half* Ch = qk + z * QKoff;
#pragma unroll
        for (int mi = 0; mi < 4; ++mi) {
            int r = m0 + wm * 64 + mi * 16 + gid;
#pragma unroll
            for (int nj = 0; nj < 4; ++nj) {
                int n = n0 + wn * 32 + nj * 8 + 2 * tg;
                float b0 = bias[n], b1 = bias[n + 1];
                float* c = acc[mi * 4 + nj];
                *(u32*)&Ch[(long)r * DDIM + n]       = pkh2(c[0] + b0, c[1] + b1);
                *(u32*)&Ch[(long)(r + 8) * DDIM + n] = pkh2(c[2] + b0, c[3] + b1);
            }
        }
    } else {
#pragma unroll
        for (int mi = 0; mi < 4; ++mi) {
            int r = m0 + wm * 64 + mi * 16 + gid;
#pragma unroll
            for (int nj = 0; nj < 4; ++nj) {
                int n = n0 + wn * 32 + nj * 8 + 2 * tg;
                float b0 = bias[n], b1 = bias[n + 1];
                float* c = acc[mi * 4 + nj];
                int bb0 = r >> 11, s0 = r & 2047;
                int bb1 = (r + 8) >> 11, s1 = (r + 8) & 2047;
                long base0 = ((long)(bb0 * NHEAD) * HDIM) * SLEN;
                long base1 = ((long)(bb1 * NHEAD) * HDIM) * SLEN;
                vt[base0 + (long)n * SLEN + s0]       = __float2half(c[0] + b0);
                vt[base0 + (long)(n + 1) * SLEN + s0] = __float2half(c[1] + b1);
                vt[base1 + (long)n * SLEN + s1]       = __float2half(c[2] + b0);
                vt[base1 + (long)(n + 1) * SLEN + s1] = __float2half(c[3] + b1);
            }
        }
    }
}

// ---------------- merged out-projection + attn_mean ------------------------------
// blocks [0,256): out = ctx @ Wo + bo (fp32). blocks [256, 256+B*SLEN): attn_mean.
__global__ void __launch_bounds__(256)
outmerge(const __half* __restrict__ ctx, const __half* __restrict__ wo,
         const float* __restrict__ bo, float* __restrict__ out,
         const __half* __restrict__ E, const float* __restrict__ rs,
         float* __restrict__ attn)
{
    const int bid = blockIdx.x;
    const int tid = threadIdx.x;

    if (bid < 256) {
        // ---- out-projection GEMM tile ----
        extern __shared__ __align__(16) __half smem[];
        const u32 sbase = (u32)__cvta_generic_to_shared(smem);
        const int m0 = (bid >> 3) * 128, n0 = (bid & 7) * 128;
        const __half* Agp = ctx + (long)m0 * DDIM;
        const __half* Bgp = wo + (long)n0 * DDIM;

        float acc[16][4];
        gemm_core_128(Agp, Bgp, DDIM, DDIM, DDIM, sbase, acc);

        const int w = tid >> 5, lane = tid & 31;
        const int wm = w & 1, wn = w >> 1;
        const int gid = lane >> 2, tg = lane & 3;
#pragma unroll
        for (int mi = 0; mi < 4; ++mi) {
            int r = m0 + wm * 64 + mi * 16 + gid;
#pragma unroll
            for (int nj = 0; nj < 4; ++nj) {
                int n = n0 + wn * 32 + nj * 8 + 2 * tg;
                float b0 = bo[n], b1 = bo[n + 1];
                float* c = acc[mi * 4 + nj];
                *(float2*)&out[(long)r * DDIM + n]       = make_float2(c[0] + b0, c[1] + b1);
                *(float2*)&out[(long)(r + 8) * DDIM + n] = make_float2(c[2] + b0, c[3] + b1);
            }
        }
    } else {
        // ---- attn_mean row ----
        const int id = bid - 256;
        const int q = id & (SLEN - 1), b = id >> 11;
        __shared__ float siz[NHEAD];
        if (tid < NHEAD) siz[tid] = rs[(long)(b * NHEAD + tid) * SLEN + q];
        __syncthreads();

        float a[8] = {0, 0, 0, 0, 0, 0, 0, 0};
#pragma unroll
        for (int h = 0; h < NHEAD; ++h) {
            const __half* p = E + (((long)(b * NHEAD + h) * SLEN + q) * SLEN) + tid * 8;
            uint4 ev = *(const uint4*)p;
            float z = siz[h];
            float2 f0 = __half22float2(*(__half2*)&ev.x);
            float2 f1 = __half22float2(*(__half2*)&ev.y);
            float2 f2 = __half22float2(*(__half2*)&ev.z);
            float2 f3 = __half22float2(*(__half2*)&ev.w);
            a[0] += f0.x * z; a[1] += f0.y * z; a[2] += f1.x * z; a[3] += f1.y * z;
            a[4] += f2.x * z; a[5] += f2.y * z; a[6] += f3.x * z; a[7] += f3.y * z;
        }
        const float sc = 1.f / (float)NHEAD;
        float* o = attn + ((long)b * SLEN + q) * SLEN + tid * 8;
        *(float4*)o       = make_float4(a[0] * sc, a[1] * sc, a[2] * sc, a[3] * sc);
        *(float4*)(o + 4) = make_float4(a[4] * sc, a[5] * sc, a[6] * sc, a[7] * sc);
    }
}

// ---------------- fused attention (verbatim from R5, passing) --------------------
__global__ void __launch_bounds__(256, 1)
fused_attn(const __half* __restrict__ Q, const __half* __restrict__ Kg,
           const __half* __restrict__ Vt, __half* __restrict__ E,
           __half* __restrict__ ctx, float* __restrict__ rs)
{
    constexpr int QP = 72;
    constexpr int VP = 136;
    constexpr int QTILE = 128 * QP;
    constexpr int VTILE = HDIM * VP;
    constexpr int NC = SLEN / 128;

    const int tid = threadIdx.x;
    const int m0 = blockIdx.x * 128;
    const int bh = blockIdx.y;
    const int b = bh / NHEAD, h = bh % NHEAD;

    const __half* Qg = Q  + ((long)b * SLEN + m0) * DDIM + h * HDIM;
    const __half* Kb = Kg + ((long)b * SLEN) * DDIM + h * HDIM;
    const __half* Vg = Vt + (long)bh * HDIM * SLEN;
    __half* Eg = E + (long)bh * SLEN * SLEN;

    const int w = tid >> 5, lane = tid & 31;
    const int gid = lane >> 2, tg = lane & 3;
    const int wm = w & 3, wn = w >> 2;
    const int q8 = lane >> 3, r8 = lane & 7;
    const int rowA = wm * 32 + (q8 & 1) * 8 + r8, colA = (q8 >> 1) * 8;
    const int rowB = wn * 64 + (q8 >> 1) * 8 + r8, colB = (q8 & 1) * 8;
    const int rowV = (q8 >> 1) * 8 + r8,            colV = (q8 & 1) * 8;

    extern __shared__ __align__(16) __half smem[];
    const u32 sbase = (u32)__cvta_generic_to_shared(smem);
    const u32 qb = sbase;
    auto kb = [&](int s) { return sbase + (QTILE + s * QTILE) * 2; };
    auto vb = [&](int s) { return sbase + (4 * QTILE + s * VTILE) * 2; };

    __shared__ float zs[4][32][2];
    __shared__ float siz[128];

    auto load_q = [&]() {
#pragma unroll
        for (int i = 0; i < 4; ++i) {
            int c = tid + i * 256; int row = c >> 3, cq = c & 7;
            cpa16(qb + (row * QP + cq * 8) * 2, Qg + (long)row * DDIM + cq * 8);
        }
    };
    auto issue = [&](int chunk) {
        const int stage = chunk % 3;
        const __half* Kp = Kb + (long)(chunk * 128) * DDIM;
        const u32 kbs = kb(stage);
#pragma unroll
        for (int i = 0; i < 4; ++i) {
            int c = tid + i * 256; int row = c >> 3, cq = c & 7;
            cpa16(kbs + (row * QP + cq * 8) * 2, Kp + (long)row * DDIM + cq * 8);
        }
        const __half* Vp = Vg + chunk * 128;
        const u32 vbs = vb(stage);
#pragma unroll
        for (int i = 0; i < 4; ++i) {
            int c = tid + i * 256; int row = c >> 4, cv = c & 15;
            cpa16(vbs + (row * VP + cv * 8) * 2, Vp + (long)row * SLEN + cv * 8);
        }
        cpa_commit();
    };

    float cU[2][8][4];
#pragma unroll
    for (int mi = 0; mi < 2; ++mi)
#pragma unroll
        for (int dj = 0; dj < 8; ++dj)
#pragma unroll
            for (int r = 0; r < 4; ++r) cU[mi][dj][r] = 0.f;
    float zacc[2][2] = {{0.f, 0.f}, {0.f, 0.f}};

    load_q();
    issue(0);
    issue(1);

    for (int kt = 0; kt < NC; ++kt) {
        cpa_wait1();
        __syncthreads();
        if (kt + 2 < NC) issue(kt + 2);
        else cpa_commit();

        const int stage = kt % 3;
        const u32 kbs = kb(stage), vbs = vb(stage);

        float cS[2][8][4];
#pragma unroll
        for (int mi = 0; mi < 2; ++mi)
#pragma unroll
            for (int nj = 0; nj < 8; ++nj)
#pragma unroll
                for (int r = 0; r < 4; ++r) cS[mi][nj][r] = 0.f;

#pragma unroll
        for (int kf = 0; kf < 4; ++kf) {
            const int kk = kf * 16;
            u32 a[2][4], bfr[8][2];
#pragma unroll
            for (int mi = 0; mi < 2; ++mi)
                ldsm4(a[mi][0], a[mi][1], a[mi][2], a[mi][3],
                      qb + ((rowA + mi * 16) * QP + kk + colA) * 2);
#pragma unroll
            for (int p = 0; p < 4; ++p)
                ldsm4(bfr[2 * p][0], bfr[2 * p][1], bfr[2 * p + 1][0], bfr[2 * p + 1][1],
                      kbs + ((rowB + p * 16) * QP + kk + colB) * 2);
#pragma unroll
            for (int mi = 0; mi < 2; ++mi)
#pragma unroll
                for (int nj = 0; nj < 8; ++nj)
                    hmma(cS[mi][nj], a[mi], bfr[nj]);
        }

        u32 eh[2][8][2];
#pragma unroll
        for (int mi = 0; mi < 2; ++mi)
#pragma unroll
            for (int nj = 0; nj < 8; ++nj) {
                float e0 = __expf(cS[mi][nj][0] * 0.125f);
                float e1 = __expf(cS[mi][nj][1] * 0.125f);
                float e2 = __expf(cS[mi][nj][2] * 0.125f);
                float e3 = __expf(cS[mi][nj][3] * 0.125f);
                zacc[mi][0] += e0 + e1;
                zacc[mi][1] += e2 + e3;
                eh[mi][nj][0] = pkh2(e0, e1);
                eh[mi][nj][1] = pkh2(e2, e3);
            }

#pragma unroll
        for (int kf = 0; kf < 4; ++kf) {
            const int kk2 = kf * 16;
            u32 a[2][4], bv[8][2];
#pragma unroll
            for (int mi = 0; mi < 2; ++mi) {
                a[mi][0] = eh[mi][2 * kf][0];
                a[mi][1] = eh[mi][2 * kf][1];
                a[mi][2] = eh[mi][2 * kf + 1][0];
                a[mi][3] = eh[mi][2 * kf + 1][1];
            }
#pragma unroll
            for (int p = 0; p < 4; ++p)
                ldsm4(bv[2 * p][0], bv[2 * p][1], bv[2 * p + 1][0], bv[2 * p + 1][1],
                      vbs + ((rowV + p * 16) * VP + wn * 64 + kk2 + colV) * 2);
#pragma unroll
            for (int mi = 0; mi < 2; ++mi)
#pragma unroll
                for (int dj = 0; dj < 8; ++dj)
                    hmma(cU[mi][dj], a[mi], bv[dj]);
        }

        const long ebase = (long)(m0 + wm * 32) * SLEN + kt * 128 + wn * 64;
#pragma unroll
        for (int mi = 0; mi < 2; ++mi) {
            long r0 = ebase + (long)(mi * 16 + gid) * SLEN + 2 * tg;
#pragma unroll
            for (int nj = 0; nj < 8; ++nj) {
                *(u32*)&Eg[r0 + nj * 8]             = eh[mi][nj][0];
                *(u32*)&Eg[r0 + 8L * SLEN + nj * 8] = eh[mi][nj][1];
            }
        }
    }

    __syncthreads();

#pragma unroll
    for (int mi = 0; mi < 2; ++mi)
#pragma unroll
        for (int r = 0; r < 2; ++r) {
            float v = zacc[mi][r];
            v += __shfl_xor_sync(0xffffffffu, v, 1);
            v += __shfl_xor_sync(0xffffffffu, v, 2);
            zacc[mi][r] = v;
        }
    if (tg == 0) {
#pragma unroll
        for (int mi = 0; mi < 2; ++mi)
#pragma unroll
            for (int r = 0; r < 2; ++r)
                zs[wm][mi * 16 + r * 8 + gid][wn] = zacc[mi][r];
    }
    __syncthreads();
    if (tid < 128) {
        float inv = 1.f / (zs[tid >> 5][tid & 31][0] + zs[tid >> 5][tid & 31][1]);
        siz[tid] = inv;
        rs[(long)bh * SLEN + m0 + tid] = inv;
    }
    __syncthreads();

    float* Ured = (float*)smem;
    if (wn == 1) {
#pragma unroll
        for (int mi = 0; mi < 2; ++mi) {
            int r = wm * 32 + mi * 16 + gid;
#pragma unroll
            for (int dj = 0; dj < 8; ++dj) {
                int n = dj * 8 + 2 * tg;
                *(float2*)&Ured[r * 68 + n]       = make_float2(cU[mi][dj][0], cU[mi][dj][1]);
                *(float2*)&Ured[(r + 8) * 68 + n] = make_float2(cU[mi][dj][2], cU[mi][dj][3]);
            }
        }
    }
    __syncthreads();
    if (wn == 0) {
#pragma unroll
        for (int mi = 0; mi < 2; ++mi) {
            int r = wm * 32 + mi * 16 + gid;
            float iz0 = siz[r], iz1 = siz[r + 8];
            __half* C0 = ctx + ((long)b * SLEN + m0 + r) * DDIM + h * HDIM;
#pragma unroll
            for (int dj = 0; dj < 8; ++dj) {
                int n = dj * 8 + 2 * tg;
                float2 u0 = *(const float2*)&Ured[r * 68 + n];
                float2 u1 = *(const float2*)&Ured[(r + 8) * 68 + n];
                *(u32*)&C0[n] = pkh2((cU[mi][dj][0] + u0.x) * iz0,
                                     (cU[mi][dj][1] + u0.y) * iz0);
                *(u32*)&C0[8L * DDIM + n] = pkh2((cU[mi][dj][2] + u1.x) * iz1,
                                                 (cU[mi][dj][3] + u1.y) * iz1);
            }
        }
    }
}

// ---------------- prep kernels ----------------------------------------------------
__global__ void __launch_bounds__(256)
prep_w(const float* __restrict__ W0, const float* __restrict__ W1,
       const float* __restrict__ W2, const float* __restrict__ W3,
       __half* __restrict__ Wt)
{
    const int z = blockIdx.z;
    const float* W = (z == 0) ? W0 : (z == 1) ? W1 : (z == 2) ? W2 : W3;
    __half* T = Wt + (long)z * DDIM * DDIM;
    __shared__ float t[32][33];
    const int tx = threadIdx.x, ty = threadIdx.y;
    const int n0 = blockIdx.x * 32, k0 = blockIdx.y * 32;
#pragma unroll
    for (int i = 0; i < 4; ++i)
        t[tx][ty + 8 * i] = W[(long)(k0 + ty + 8 * i) * DDIM + n0 + tx];
    __syncthreads();
#pragma unroll
    for (int i = 0; i < 4; ++i)
        T[(long)(n0 + ty + 8 * i) * DDIM + k0 + tx] = __float2half(t[ty + 8 * i][tx]);
}

__global__ void __launch_bounds__(256)
prep_x(const float* __restrict__ x, __half* __restrict__ xh)
{
    long i = ((long)blockIdx.x * 256 + threadIdx.x) * 8;
    float4 f0 = *(const float4*)(x + i);
    float4 f1 = *(const float4*)(x + i + 4);
    uint4 u;
    u.x = pkh2(f0.x, f0.y); u.y = pkh2(f0.z, f0.w);
    u.z = pkh2(f1.x, f1.y); u.w = pkh2(f1.z, f1.w);
    *(uint4*)(xh + i) = u;
}

// ---------------- launch -----------------------------------------------------------
extern "C" void kernel_launch(void* const* d_in, const int* in_sizes, int n_in,
                              void* d_out, int out_size)
{
    const float* x  = (const float*)d_in[0];
    const float* Wq = (const float*)d_in[1];
    const float* bq = (const float*)d_in[2];
    const float* Wk = (const float*)d_in[3];
    const float* bk = (const float*)d_in[4];
    const float* Wv = (const float*)d_in[5];
    const float* bv = (const float*)d_in[6];
    const float* Wo = (const float*)d_in[7];
    const float* bo = (const float*)d_in[8];
    float* out = (float*)d_out;

    const int Bsz = in_sizes[0] / (SLEN * DDIM);   // = 2
    const int BS  = Bsz * SLEN;
    const long NB = (long)BS * DDIM;

    __half *wt, *xh, *qk, *vt, *E, *ctx;
    float *b3, *rs;
    cudaGetSymbolAddress((void**)&wt,  g_wt);
    cudaGetSymbolAddress((void**)&b3,  g_b3);
    cudaGetSymbolAddress((void**)&xh,  g_xh);
    cudaGetSymbolAddress((void**)&qk,  g_qk);
    cudaGetSymbolAddress((void**)&vt,  g_vt);
    cudaGetSymbolAddress((void**)&E,   g_E);
    cudaGetSymbolAddress((void**)&ctx, g_ctx);
    cudaGetSymbolAddress((void**)&rs,  g_rs);

    const int SM_P = 3 * 2 * 128 * 72 * 2;                     // 110592 (BK=64 gemm)
    const int SM_F = (4 * 128 * 72 + 3 * 64 * 136) * 2;        // 125952 (fused attn)
    cudaFuncSetAttribute(qkv_proj,   cudaFuncAttributeMaxDynamicSharedMemorySize, SM_P);
    cudaFuncSetAttribute(outmerge,   cudaFuncAttributeMaxDynamicSharedMemorySize, SM_P);
    cudaFuncSetAttribute(fused_attn, cudaFuncAttributeMaxDynamicSharedMemorySize, SM_F);

    cudaMemcpyAsync(b3,            bq, sizeof(float) * DDIM, cudaMemcpyDeviceToDevice);
    cudaMemcpyAsync(b3 + DDIM,     bk, sizeof(float) * DDIM, cudaMemcpyDeviceToDevice);
    cudaMemcpyAsync(b3 + 2 * DDIM, bv, sizeof(float) * DDIM, cudaMemcpyDeviceToDevice);

    // 0) prep: x -> fp16, weights -> transposed fp16
    prep_x<<<(unsigned)(NB / (256 * 8)), 256>>>(x, xh);
    prep_w<<<dim3(32, 32, 4), dim3(32, 8)>>>(Wq, Wk, Wv, Wo, wt);

    const long QKoff = (long)BS * DDIM;

    // 1) QKV projection (single launch, z = Q/K/V)
    qkv_proj<<<dim3(8, BS / 128, 3), 256, SM_P>>>(xh, wt, b3, qk, vt, QKoff);

    // 2) fused: E, invZ, ctx
    fused_attn<<<dim3(SLEN / 128, Bsz * NHEAD), 256, SM_F>>>(
        qk, qk + QKoff, vt, E, ctx, rs);

    // 3) merged: out-projection + attn_mean (independent, overlapped)
    outmerge<<<256 + BS, 256, SM_P>>>(
        ctx, wt + 3L * DDIM * DDIM, bo, out, E, rs, out + NB);
}

// round 8
// speedup vs baseline: 6.4455x; 1.0171x over previous
#include <cuda_runtime.h>
#include <cuda_fp16.h>
#include <cstdint>

#define SLEN  2048
#define DDIM  1024
#define NHEAD 16
#define HDIM  64
#define MAXB  2

using u32 = unsigned int;

// ---------------- scratch (device globals) ------------------------------------
__device__ __half g_wt [4L * DDIM * DDIM];                 // W{q,k,v,o}^T [n][k] fp16
__device__ float  g_b3 [3 * DDIM];                         // packed bq,bk,bv
__device__ __half g_xh [(long)MAXB * SLEN * DDIM];         // x in fp16
__device__ __half g_qk [2L * MAXB * SLEN * DDIM];          // Q (pre-scaled) then K
__device__ __half g_vt [(long)MAXB * NHEAD * HDIM * SLEN]; // V^T [b][h][d][s]
__device__ __half g_E  [(long)MAXB * NHEAD * SLEN * SLEN]; // exp(scores) fp16
__device__ __half g_ctx[(long)MAXB * SLEN * DDIM];
__device__ float  g_rs [MAXB * NHEAD * SLEN];              // 1/rowsum

#define QSCALE 0.1803368801111204f   // log2(e) / 8

// ---------------- helpers ------------------------------------------------------
__device__ __forceinline__ u32 pkh2(float a, float b) {
    __half2 h = __floats2half2_rn(a, b);
    return *(u32*)&h;
}

__device__ __forceinline__ u32 ex2h2(u32 x) {
    u32 r;
    asm("ex2.approx.f16x2 %0, %1;" : "=r"(r) : "r"(x));
    return r;
}

__device__ __forceinline__ void hmma(float* c, const u32* a, const u32* b) {
    asm volatile(
        "mma.sync.aligned.m16n8k16.row.col.f32.f16.f16.f32 "
        "{%0,%1,%2,%3},{%4,%5,%6,%7},{%8,%9},{%0,%1,%2,%3};"
        : "+f"(c[0]), "+f"(c[1]), "+f"(c[2]), "+f"(c[3])
        : "r"(a[0]), "r"(a[1]), "r"(a[2]), "r"(a[3]), "r"(b[0]), "r"(b[1]));
}

__device__ __forceinline__ void ldsm4(u32& r0, u32& r1, u32& r2, u32& r3, u32 saddr) {
    asm volatile("ldmatrix.sync.aligned.m8n8.x4.shared.b16 {%0,%1,%2,%3}, [%4];"
                 : "=r"(r0), "=r"(r1), "=r"(r2), "=r"(r3) : "r"(saddr));
}

__device__ __forceinline__ void ldsm2(u32& r0, u32& r1, u32 saddr) {
    asm volatile("ldmatrix.sync.aligned.m8n8.x2.shared.b16 {%0,%1}, [%2];"
                 : "=r"(r0), "=r"(r1) : "r"(saddr));
}

__device__ __forceinline__ void cpa16(u32 dst, const void* src) {
    asm volatile("cp.async.cg.shared.global [%0], [%1], 16;" :: "r"(dst), "l"(src));
}
__device__ __forceinline__ void cpa_commit() {
    asm volatile("cp.async.commit_group;" ::: "memory");
}
__device__ __forceinline__ void cpa_wait1() {
    asm volatile("cp.async.wait_group 1;" ::: "memory");
}

// ---------------- GEMM core: BM=128,BN=128,BK=64, 8 warps (WGM=2,WGN=4) ---------
__device__ __forceinline__ void gemm_core_128(
    const __half* __restrict__ Agp, const __half* __restrict__ Bgp,
    int K, int lda, int ldb, u32 sbase, float (*acc)[4])
{
    constexpr int BK = 64, BKP = 72;
    constexpr u32 TSTG = 128 * BKP * 2;
    constexpr u32 STG = 2 * TSTG;

    const int tid = threadIdx.x;
    const int w = tid >> 5, lane = tid & 31;
    const int wm = w & 1, wn = w >> 1;
    const int q8 = lane >> 3, r8 = lane & 7;
    const int rowA = wm * 64 + (q8 & 1) * 8 + r8, colA = (q8 >> 1) * 8;
    const int rowB = wn * 32 + (q8 >> 1) * 8 + r8, colB = (q8 & 1) * 8;

#pragma unroll
    for (int i = 0; i < 16; ++i)
#pragma unroll
        for (int r = 0; r < 4; ++r) acc[i][r] = 0.f;

    auto issue = [&](int stage, int kb) {
        const u32 ab = sbase + stage * STG;
#pragma unroll
        for (int i = 0; i < 4; ++i) {
            int c = tid + i * 256; int row = c >> 3, ku = c & 7;
            cpa16(ab + (u32)(row * BKP + ku * 8) * 2, Agp + (long)row * lda + kb + ku * 8);
        }
        const u32 bb = sbase + stage * STG + TSTG;
#pragma unroll
        for (int i = 0; i < 4; ++i) {
            int c = tid + i * 256; int row = c >> 3, ku = c & 7;
            cpa16(bb + (u32)(row * BKP + ku * 8) * 2, Bgp + (long)row * ldb + kb + ku * 8);
        }
        cpa_commit();
    };

    const int KT = K / BK;
    issue(0, 0);
    issue(1, BK);

    for (int kt = 0; kt < KT; ++kt) {
        cpa_wait1();
        __syncthreads();
        if (kt + 2 < KT) issue((kt + 2) % 3, (kt + 2) * BK);
        else cpa_commit();

        const int stage = kt % 3;
        const u32 ab = sbase + stage * STG;
        const u32 bb = ab + TSTG;
#pragma unroll
        for (int ks = 0; ks < 4; ++ks) {
            const int kk = ks * 16;
            u32 a[4][4], b[4][2];
#pragma unroll
            for (int mi = 0; mi < 4; ++mi)
                ldsm4(a[mi][0], a[mi][1], a[mi][2], a[mi][3],
                      ab + (u32)((rowA + mi * 16) * BKP + kk + colA) * 2);
#pragma unroll
            for (int p = 0; p < 2; ++p)
                ldsm4(b[2 * p][0], b[2 * p][1], b[2 * p + 1][0], b[2 * p + 1][1],
                      bb + (u32)((rowB + p * 16) * BKP + kk + colB) * 2);
#pragma unroll
            for (int mi = 0; mi < 4; ++mi)
#pragma unroll
                for (int nj = 0; nj < 4; ++nj)
                    hmma(acc[mi * 4 + nj], a[mi], b[nj]);
        }
    }
}

// ---------------- QKV projection (z selects Q/K/V; Q pre-scaled by QSCALE) ------
__global__ void __launch_bounds__(256)
qkv_proj(const __half* __restrict__ xh, const __half* __restrict__ wt,
         const float* __restrict__ b3, __half* __restrict__ qk,
         __half* __restrict__ vt, long QKoff)
{
    extern __shared__ __align__(16) __half smem[];
    const u32 sbase = (u32)__cvta_generic_to_shared(smem);
    const int z = blockIdx.z;
    const int m0 = blockIdx.y * 128, n0 = blockIdx.x * 128;

    const __half* Agp = xh + (long)m0 * DDIM;
    const __half* Bgp = wt + (long)z * DDIM * DDIM + (long)n0 * DDIM;
    const float* bias = b3 + z * DDIM;

    float acc[16][4];
    gemm_core_128(Agp, Bgp, DDIM, DDIM, DDIM, sbase, acc);

    const int tid = threadIdx.x;
    const int w = tid >> 5, lane = tid & 31;
    const int wm = w & 1, wn = w >> 1;
    const int gid = lane >> 2, tg = lane & 3;

    if (z < 2) {
        const float sc = (z == 0) ? QSCALE : 1.f;
        __half* Ch = qk + z * QKoff;
#pragma unroll
        for (int mi = 0; mi < 4; ++mi) {
            int r = m0 + wm * 64 + mi * 16 + gid;
#pragma unroll
            for (int nj = 0; nj < 4; ++nj) {
                int n = n0 + wn * 32 + nj * 8 + 2 * tg;
                float b0 = bias[n], b1 = bias[n + 1];
                float* c = acc[mi * 4 + nj];
                *(u32*)&Ch[(long)r * DDIM + n]       = pkh2((c[0] + b0) * sc, (c[1] + b1) * sc);
                *(u32*)&Ch[(long)(r + 8) * DDIM + n] = pkh2((c[2] + b0) * sc, (c[3] + b1) * sc);
            }
        }
    } else {
#pragma unroll
        for (int mi = 0; mi < 4; ++mi) {
            int r = m0 + wm * 64 + mi * 16 + gid;
#pragma unroll
            for (int nj = 0; nj < 4; ++nj) {
                int n = n0 + wn * 32 + nj * 8 + 2 * tg;
                float b0 = bias[n], b1 = bias[n + 1];
                float* c = acc[mi * 4 + nj];
                int bb0 = r >> 11, s0 = r & 2047;
                int bb1 = (r + 8) >> 11, s1 = (r + 8) & 2047;
                long base0 = ((long)(bb0 * NHEAD) * HDIM) * SLEN;
                long base1 = ((long)(bb1 * NHEAD) * HDIM) * SLEN;
                vt[base0 + (long)n * SLEN + s0]       = __float2half(c[0] + b0);
                vt[base0 + (long)(n + 1) * SLEN + s0] = __float2half(c[1] + b1);
                vt[base1 + (long)n * SLEN + s1]       = __float2half(c[2] + b0);
                vt[base1 + (long)(n + 1) * SLEN + s1] = __float2half(c[3] + b1);
            }
        }
    }
}

// ---------------- merged out-projection + attn_mean ------------------------------
__global__ void __launch_bounds__(256)
outmerge(const __half* __restrict__ ctx, const __half* __restrict__ wo,
         const float* __restrict__ bo, float* __restrict__ out,
         const __half* __restrict__ E, const float* __restrict__ rs,
         float* __restrict__ attn)
{
    const int bid = blockIdx.x;
    const int tid = threadIdx.x;

    if (bid < 256) {
        extern __shared__ __align__(16) __half smem[];
        const u32 sbase = (u32)__cvta_generic_to_shared(smem);
        const int m0 = (bid >> 3) * 128, n0 = (bid & 7) * 128;
        const __half* Agp = ctx + (long)m0 * DDIM;
        const __half* Bgp = wo + (long)n0 * DDIM;

        float acc[16][4];
        gemm_core_128(Agp, Bgp, DDIM, DDIM, DDIM, sbase, acc);

        const int w = tid >> 5, lane = tid & 31;
        const int wm = w & 1, wn = w >> 1;
        const int gid = lane >> 2, tg = lane & 3;
#pragma unroll
        for (int mi = 0; mi < 4; ++mi) {
            int r = m0 + wm * 64 + mi * 16 + gid;
#pragma unroll
            for (int nj = 0; nj < 4; ++nj) {
                int n = n0 + wn * 32 + nj * 8 + 2 * tg;
                float b0 = bo[n], b1 = bo[n + 1];
                float* c = acc[mi * 4 + nj];
                *(float2*)&out[(long)r * DDIM + n]       = make_float2(c[0] + b0, c[1] + b1);
                *(float2*)&out[(long)(r + 8) * DDIM + n] = make_float2(c[2] + b0, c[3] + b1);
            }
        }
    } else {
        const int id = bid - 256;
        const int q = id & (SLEN - 1), b = id >> 11;
        __shared__ float siz[NHEAD];
        if (tid < NHEAD) siz[tid] = rs[(long)(b * NHEAD + tid) * SLEN + q];
        __syncthreads();

        float a[8] = {0, 0, 0, 0, 0, 0, 0, 0};
#pragma unroll
        for (int h = 0; h < NHEAD; ++h) {
            const __half* p = E + (((long)(b * NHEAD + h) * SLEN + q) * SLEN) + tid * 8;
            uint4 ev = *(const uint4*)p;
            float z = siz[h];
            float2 f0 = __half22float2(*(__half2*)&ev.x);
            float2 f1 = __half22float2(*(__half2*)&ev.y);
            float2 f2 = __half22float2(*(__half2*)&ev.z);
            float2 f3 = __half22float2(*(__half2*)&ev.w);
            a[0] += f0.x * z; a[1] += f0.y * z; a[2] += f1.x * z; a[3] += f1.y * z;
            a[4] += f2.x * z; a[5] += f2.y * z; a[6] += f3.x * z; a[7] += f3.y * z;
        }
        const float sc = 1.f / (float)NHEAD;
        float* o = attn + ((long)b * SLEN + q) * SLEN + tid * 8;
        *(float4*)o       = make_float4(a[0] * sc, a[1] * sc, a[2] * sc, a[3] * sc);
        *(float4*)(o + 4) = make_float4(a[4] * sc, a[5] * sc, a[6] * sc, a[7] * sc);
    }
}

// ---------------- fused attention: E=2^S', U+=(E|Z)·[V;1], ctx --------------------
// Q pre-scaled so S' = log2 of exp argument. V smem tile has 72 d-rows:
// row 64 = ones (tensor-core row-sum), rows 65-71 = 0.
__global__ void __launch_bounds__(256, 1)
fused_attn(const __half* __restrict__ Q, const __half* __restrict__ Kg,
           const __half* __restrict__ Vt, __half* __restrict__ E,
           __half* __restrict__ ctx, float* __restrict__ rs)
{
    constexpr int QP = 72;
    constexpr int VP = 136;
    constexpr int QTILE = 128 * QP;         // halves
    constexpr int VTILE = 72 * VP;          // halves (64 data rows + 8 ones/zero rows)
    constexpr int NC = SLEN / 128;

    const int tid = threadIdx.x;
    const int m0 = blockIdx.x * 128;
    const int bh = blockIdx.y;
    const int b = bh / NHEAD, h = bh % NHEAD;

    const __half* Qg = Q  + ((long)b * SLEN + m0) * DDIM + h * HDIM;
    const __half* Kb = Kg + ((long)b * SLEN) * DDIM + h * HDIM;
    const __half* Vg = Vt + (long)bh * HDIM * SLEN;
    __half* Eg = E + (long)bh * SLEN * SLEN;

    const int w = tid >> 5, lane = tid & 31;
    const int gid = lane >> 2, tg = lane & 3;
    const int wm = w & 3, wn = w >> 2;
    const int q8 = lane >> 3, r8 = lane & 7;
    const int rowA = wm * 32 + (q8 & 1) * 8 + r8, colA = (q8 >> 1) * 8;
    const int rowB = wn * 64 + (q8 >> 1) * 8 + r8, colB = (q8 & 1) * 8;
    const int rowV = (q8 >> 1) * 8 + r8,            colV = (q8 & 1) * 8;

    extern __shared__ __align__(16) __half smem[];
    const u32 sbase = (u32)__cvta_generic_to_shared(smem);
    const u32 qb = sbase;
    auto kb = [&](int s) { return sbase + (QTILE + s * QTILE) * 2; };
    auto vb = [&](int s) { return sbase + (4 * QTILE + s * VTILE) * 2; };

    __shared__ float zs[4][32][2];
    __shared__ float siz[128];

    // ---- ones/zero rows of all 3 V stages (cp.async only writes rows 0..63) ----
#pragma unroll
    for (int s = 0; s < 3; ++s) {
        __half* vbase = smem + 4 * QTILE + s * VTILE;
        for (int i = tid; i < 8 * VP; i += 256) {
            int row = 64 + i / VP, col = i % VP;
            vase: ;
            vbase2: ;
            vbase3: ;
            vbase4: ;
            vbase5: ;
            vbase6: ;
            vbase7: ;
            vbase8: ;
            vbase9: ;
            vbase10: ;
            vbase11: ;
            vbase12: ;
            vbase13: ;
            vbase14: ;
            vbase15: ;
            vbase16: ;
            vbase17: ;
            vbase18: ;
            vbase19: ;
            vbase20: ;
            vbase21: ;
            vbase22: ;
            vbase23: ;
            vbase24: ;
            vbase25: ;
            vbase26: ;
            vbase27: ;
            vbase28: ;
            vbase29: ;
            vbase30: ;
            vbase31: ;
            vbase32: ;
            vbase33: ;
            vbase34: ;
            vbase35: ;
            vbase36: ;
            vbase37: ;
            vbase38: ;
            vbase39: ;
            vbase40: ;
            vbase41: ;
            vbase42: ;
            vbase43: ;
            vbase44: ;
            vbase45: ;
            vbase46: ;
            vbase47: ;
            vbase48: ;
            vbase49: ;
            vbase50: ;
            vbase51: ;
            vbase52: ;
            vbase53: ;
            vbase54: ;
            vbase55: ;
            vbase56: ;
            vbase57: ;
            vbase58: ;
            vbase59: ;
            vbase60: ;
            vbase61: ;
            vbase62: ;
            vbase63: ;
            vbase[row * VP + col] = (row == 64) ? __float2half(1.f) : __float2half(0.f);
        }
    }

    auto load_q = [&]() {
#pragma unroll
        for (int i = 0; i < 4; ++i) {
            int c = tid + i * 256; int row = c >> 3, cq = c & 7;
            cpa16(qb + (row * QP + cq * 8) * 2, Qg + (long)row * DDIM + cq * 8);
        }
    };
    auto issue = [&](int chunk) {
        const int stage = chunk % 3;
        const __half* Kp = Kb + (long)(chunk * 128) * DDIM;
        const u32 kbs = kb(stage);
#pragma unroll
        for (int i = 0; i < 4; ++i) {
            int c = tid + i * 256; int row = c >> 3, cq = c & 7;
            cpa16(kbs + (row * QP + cq * 8) * 2, Kp + (long)row * DDIM + cq * 8);
        }
        const __half* Vp = Vg + chunk * 128;
        const u32 vbs = vb(stage);
#pragma unroll
        for (int i = 0; i < 4; ++i) {
            int c = tid + i * 256; int row = c >> 4, cv = c & 15;
            cpa16(vbs + (row * VP + cv * 8) * 2, Vp + (long)row * SLEN + cv * 8);
        }
        cpa_commit();
    };

    float cU[2][8][4];
#pragma unroll
    for (int mi = 0; mi < 2; ++mi)
#pragma unroll
        for (int dj = 0; dj < 8; ++dj)
#pragma unroll
            for (int r = 0; r < 4; ++r) cU[mi][dj][r] = 0.f;
    float cUz[2][4];
#pragma unroll
    for (int mi = 0; mi < 2; ++mi)
#pragma unroll
        for (int r = 0; r < 4; ++r) cUz[mi][r] = 0.f;

    load_q();
    issue(0);
    issue(1);

    for (int kt = 0; kt < NC; ++kt) {
        cpa_wait1();
        __syncthreads();
        if (kt + 2 < NC) issue(kt + 2);
        else cpa_commit();

        const int stage = kt % 3;
        const u32 kbs = kb(stage), vbs = vb(stage);

        // ---- S' = Q' K^T --------------------------------------------------------
        float cS[2][8][4];
#pragma unroll
        for (int mi = 0; mi < 2; ++mi)
#pragma unroll
            for (int nj = 0; nj < 8; ++nj)
#pragma unroll
                for (int r = 0; r < 4; ++r) cS[mi][nj][r] = 0.f;

#pragma unroll
        for (int kf = 0; kf < 4; ++kf) {
            const int kk = kf * 16;
            u32 a[2][4], bfr[8][2];
#pragma unroll
            for (int mi = 0; mi < 2; ++mi)
                ldsm4(a[mi][0], a[mi][1], a[mi][2], a[mi][3],
                      qb + ((rowA + mi * 16) * QP + kk + colA) * 2);
#pragma unroll
            for (int p = 0; p < 4; ++p)
                ldsm4(bfr[2 * p][0], bfr[2 * p][1], bfr[2 * p + 1][0], bfr[2 * p + 1][1],
                      kbs + ((rowB + p * 16) * QP + kk + colB) * 2);
#pragma unroll
            for (int mi = 0; mi < 2; ++mi)
#pragma unroll
                for (int nj = 0; nj < 8; ++nj)
                    hmma(cS[mi][nj], a[mi], bfr[nj]);
        }

        // ---- E = 2^S' in fp16 (cvt + ex2.f16x2; no scale, no f32 rowsum) --------
        u32 eh[2][8][2];
#pragma unroll
        for (int mi = 0; mi < 2; ++mi)
#pragma unroll
            for (int nj = 0; nj < 8; ++nj) {
                eh[mi][nj][0] = ex2h2(pkh2(cS[mi][nj][0], cS[mi][nj][1]));
                eh[mi][nj][1] = ex2h2(pkh2(cS[mi][nj][2], cS[mi][nj][3]));
            }

        // ---- U += E * [V ; ones-row] -------------------------------------------
#pragma unroll
        for (int kf = 0; kf < 4; ++kf) {
            const int kk2 = kf * 16;
            u32 a[2][4], bv[8][2], bz[2];
#pragma unroll
            for (int mi = 0; mi < 2; ++mi) {
                a[mi][0] = eh[mi][2 * kf][0];
                a[mi][1] = eh[mi][2 * kf][1];
                a[mi][2] = eh[mi][2 * kf + 1][0];
                a[mi][3] = eh[mi][2 * kf + 1][1];
            }
#pragma unroll
            for (int p = 0; p < 4; ++p)
                ldsm4(bv[2 * p][0], bv[2 * p][1], bv[2 * p + 1][0], bv[2 * p + 1][1],
                      vbs + ((rowV + p * 16) * VP + wn * 64 + kk2 + colV) * 2);
            ldsm2(bz[0], bz[1],
                  vbs + ((64 + r8) * VP + wn * 64 + kk2 + (q8 & 1) * 8) * 2);
#pragma unroll
            for (int mi = 0; mi < 2; ++mi) {
#pragma unroll
                for (int dj = 0; dj < 8; ++dj)
                    hmma(cU[mi][dj], a[mi], bv[dj]);
                hmma(cUz[mi], a[mi], bz);
            }
        }

        // ---- stream E tile to gmem ----------------------------------------------
        const long ebase = (long)(m0 + wm * 32) * SLEN + kt * 128 + wn * 64;
#pragma unroll
        for (int mi = 0; mi < 2; ++mi) {
            long r0 = ebase + (long)(mi * 16 + gid) * SLEN + 2 * tg;
#pragma unroll
            for (int nj = 0; nj < 8; ++nj) {
                *(u32*)&Eg[r0 + nj * 8]             = eh[mi][nj][0];
                *(u32*)&Eg[r0 + 8L * SLEN + nj * 8] = eh[mi][nj][1];
            }
        }
    }

    __syncthreads();

    // ---- Z came out of the tensor core: cUz col 64 (tg==0) ----------------------
    if (tg == 0) {
#pragma unroll
        for (int mi = 0; mi < 2; ++mi) {
            zs[wm][mi * 16 + gid][wn]     = cUz[mi][0];
            zs[wm][mi * 16 + 8 + gid][wn] = cUz[mi][2];
        }
    }
    __syncthreads();
    if (tid < 128) {
        float inv = 1.f / (zs[tid >> 5][tid & 31][0] + zs[tid >> 5][tid & 31][1]);
        siz[tid] = inv;
        rs[(long)bh * SLEN + m0 + tid] = inv;
    }
    __syncthreads();

    // ---- cross-warp U reduce (2-way over wn) through smem -----------------------
    float* Ured = (float*)smem;
    if (wn == 1) {
#pragma unroll
        for (int mi = 0; mi < 2; ++mi) {
            int r = wm * 32 + mi * 16 + gid;
#pragma unroll
            for (int dj = 0; dj < 8; ++dj) {
                int n = dj * 8 + 2 * tg;
                *(float2*)&Ured[r * 68 + n]       = make_float2(cU[mi][dj][0], cU[mi][dj][1]);
                *(float2*)&Ured[(r + 8) * 68 + n] = make_float2(cU[mi][dj][2], cU[mi][dj][3]);
            }
        }
    }
    __syncthreads();
    if (wn == 0) {
#pragma unroll
        for (int mi = 0; mi < 2; ++mi) {
            int r = wm * 32 + mi * 16 + gid;
            float iz0 = siz[r], iz1 = siz[r + 8];
            __half* C0 = ctx + ((long)b * SLEN + m0 + r) * DDIM + h * HDIM;
#pragma unroll
            for (int dj = 0; dj < 8; ++dj) {
                int n = dj * 8 + 2 * tg;
                float2 u0 = *(const float2*)&Ured[r * 68 + n];
                float2 u1 = *(const float2*)&Ured[(r + 8) * 68 + n];
                *(u32*)&C0[n] = pkh2((cU[mi][dj][0] + u0.x) * iz0,
                                     (cU[mi][dj][1] + u0.y) * iz0);
                *(u32*)&C0[8L * DDIM + n] = pkh2((cU[mi][dj][2] + u1.x) * iz1,
                                                 (cU[mi][dj][3] + u1.y) * iz1);
            }
        }
    }
}

// ---------------- prep kernels ----------------------------------------------------
__global__ void __launch_bounds__(256)
prep_w(const float* __restrict__ W0, const float* __restrict__ W1,
       const float* __restrict__ W2, const float* __restrict__ W3,
       __half* __restrict__ Wt)
{
    const int z = blockIdx.z;
    const float* W = (z == 0) ? W0 : (z == 1) ? W1 : (z == 2) ? W2 : W3;
    __half* T = Wt + (long)z * DDIM * DDIM;
    __shared__ float t[32][33];
    const int tx = threadIdx.x, ty = threadIdx.y;
    const int n0 = blockIdx.x * 32, k0 = blockIdx.y * 32;
#pragma unroll
    for (int i = 0; i < 4; ++i)
        t[tx][ty + 8 * i] = W[(long)(k0 + ty + 8 * i) * DDIM + n0 + tx];
    __syncthreads();
#pragma unroll
    for (int i = 0; i < 4; ++i)
        T[(long)(n0 + ty + 8 * i) * DDIM + k0 + tx] = __float2half(t[ty + 8 * i][tx]);
}

__global__ void __launch_bounds__(256)
prep_x(const float* __restrict__ x, __half* __restrict__ xh)
{
    long i = ((long)blockIdx.x * 256 + threadIdx.x) * 8;
    float4 f0 = *(const float4*)(x + i);
    float4 f1 = *(const float4*)(x + i + 4);
    uint4 u;
    u.x = pkh2(f0.x, f0.y); u.y = pkh2(f0.z, f0.w);
    u.z = pkh2(f1.x, f1.y); u.w = pkh2(f1.z, f1.w);
    *(uint4*)(xh + i) = u;
}

// ---------------- launch -----------------------------------------------------------
extern "C" void kernel_launch(void* const* d_in, const int* in_sizes, int n_in,
                              void* d_out, int out_size)
{
    const float* x  = (const float*)d_in[0];
    const float* Wq = (const float*)d_in[1];
    const float* bq = (const float*)d_in[2];
    const float* Wk = (const float*)d_in[3];
    const float* bk = (const float*)d_in[4];
    const float* Wv = (const float*)d_in[5];
    const float* bv = (const float*)d_in[6];
    const float* Wo = (const float*)d_in[7];
    const float* bo = (const float*)d_in[8];
    float* out = (float*)d_out;

    const int Bsz = in_sizes[0] / (SLEN * DDIM);   // = 2
    const int BS  = Bsz * SLEN;
    const long NB = (long)BS * DDIM;

    __half *wt, *xh, *qk, *vt, *E, *ctx;
    float *b3, *rs;
    cudaGetSymbolAddress((void**)&wt,  g_wt);
    cudaGetSymbolAddress((void**)&b3,  g_b3);
    cudaGetSymbolAddress((void**)&xh,  g_xh);
    cudaGetSymbolAddress((void**)&qk,  g_qk);
    cudaGetSymbolAddress((void**)&vt,  g_vt);
    cudaGetSymbolAddress((void**)&E,   g_E);
    cudaGetSymbolAddress((void**)&ctx, g_ctx);
    cudaGetSymbolAddress((void**)&rs,  g_rs);

    const int SM_P = 3 * 2 * 128 * 72 * 2;                     // 110592 (gemm core)
    const int SM_F = (4 * 128 * 72 + 3 * 72 * 136) * 2;        // 132480 (fused attn)
    cudaFuncSetAttribute(qkv_proj,   cudaFuncAttributeMaxDynamicSharedMemorySize, SM_P);
    cudaFuncSetAttribute(outmerge,   cudaFuncAttributeMaxDynamicSharedMemorySize, SM_P);
    cudaFuncSetAttribute(fused_attn, cudaFuncAttributeMaxDynamicSharedMemorySize, SM_F);

    cudaMemcpyAsync(b3,            bq, sizeof(float) * DDIM, cudaMemcpyDeviceToDevice);
    cudaMemcpyAsync(b3 + DDIM,     bk, sizeof(float) * DDIM, cudaMemcpyDeviceToDevice);
    cudaMemcpyAsync(b3 + 2 * DDIM, bv, sizeof(float) * DDIM, cudaMemcpyDeviceToDevice);

    prep_x<<<(unsigned)(NB / (256 * 8)), 256>>>(x, xh);
    prep_w<<<dim3(32, 32, 4), dim3(32, 8)>>>(Wq, Wk, Wv, Wo, wt);

    const long QKoff = (long)BS * DDIM;

    qkv_proj<<<dim3(8, BS / 128, 3), 256, SM_P>>>(xh, wt, b3, qk, vt, QKoff);

    fused_attn<<<dim3(SLEN / 128, Bsz * NHEAD), 256, SM_F>>>(
        qk, qk + QKoff, vt, E, ctx, rs);

    outmerge<<<256 + BS, 256, SM_P>>>(
        ctx, wt + 3L * DDIM * DDIM, bo, out, E, rs, out + NB);
}

// round 9
// speedup vs baseline: 6.7869x; 1.0530x over previous
#include <cuda_runtime.h>
#include <cuda_fp16.h>
#include <cstdint>

#define SLEN  2048
#define DDIM  1024
#define NHEAD 16
#define HDIM  64
#define MAXB  2

using u32 = unsigned int;

// ---------------- scratch (device globals) ------------------------------------
__device__ __half g_wt [4L * DDIM * DDIM];                 // W{q,k,v,o}^T [n][k] fp16
__device__ float  g_b3 [3 * DDIM];                         // packed bq,bk,bv
__device__ __half g_xh [(long)MAXB * SLEN * DDIM];         // x in fp16
__device__ __half g_qk [2L * MAXB * SLEN * DDIM];          // Q (pre-scaled) then K
__device__ __half g_vt [(long)MAXB * NHEAD * HDIM * SLEN]; // V^T [b][h][d][s]
__device__ __half g_E  [(long)MAXB * NHEAD * SLEN * SLEN]; // exp(scores) fp16
__device__ __half g_ctx[(long)MAXB * SLEN * DDIM];
__device__ float  g_rs [MAXB * NHEAD * SLEN];              // 1/rowsum

#define QSCALE 0.1803368801111204f   // log2(e) / 8

// ---------------- helpers ------------------------------------------------------
__device__ __forceinline__ u32 pkh2(float a, float b) {
    __half2 h = __floats2half2_rn(a, b);
    return *(u32*)&h;
}

__device__ __forceinline__ u32 ex2h2(u32 x) {
    u32 r;
    asm("ex2.approx.f16x2 %0, %1;" : "=r"(r) : "r"(x));
    return r;
}

__device__ __forceinline__ void hmma(float* c, const u32* a, const u32* b) {
    asm volatile(
        "mma.sync.aligned.m16n8k16.row.col.f32.f16.f16.f32 "
        "{%0,%1,%2,%3},{%4,%5,%6,%7},{%8,%9},{%0,%1,%2,%3};"
        : "+f"(c[0]), "+f"(c[1]), "+f"(c[2]), "+f"(c[3])
        : "r"(a[0]), "r"(a[1]), "r"(a[2]), "r"(a[3]), "r"(b[0]), "r"(b[1]));
}

__device__ __forceinline__ void ldsm4(u32& r0, u32& r1, u32& r2, u32& r3, u32 saddr) {
    asm volatile("ldmatrix.sync.aligned.m8n8.x4.shared.b16 {%0,%1,%2,%3}, [%4];"
                 : "=r"(r0), "=r"(r1), "=r"(r2), "=r"(r3) : "r"(saddr));
}

__device__ __forceinline__ void ldsm2(u32& r0, u32& r1, u32 saddr) {
    asm volatile("ldmatrix.sync.aligned.m8n8.x2.shared.b16 {%0,%1}, [%2];"
                 : "=r"(r0), "=r"(r1) : "r"(saddr));
}

__device__ __forceinline__ void cpa16(u32 dst, const void* src) {
    asm volatile("cp.async.cg.shared.global [%0], [%1], 16;" :: "r"(dst), "l"(src));
}
__device__ __forceinline__ void cpa_commit() {
    asm volatile("cp.async.commit_group;" ::: "memory");
}
__device__ __forceinline__ void cpa_wait1() {
    asm volatile("cp.async.wait_group 1;" ::: "memory");
}

// ---------------- GEMM core: BM=128,BN=128,BK=64, 8 warps (WGM=2,WGN=4) ---------
__device__ __forceinline__ void gemm_core_128(
    const __half* __restrict__ Agp, const __half* __restrict__ Bgp,
    int K, int lda, int ldb, u32 sbase, float (*acc)[4])
{
    constexpr int BK = 64, BKP = 72;
    constexpr u32 TSTG = 128 * BKP * 2;
    constexpr u32 STG = 2 * TSTG;

    const int tid = threadIdx.x;
    const int w = tid >> 5, lane = tid & 31;
    const int wm = w & 1, wn = w >> 1;
    const int q8 = lane >> 3, r8 = lane & 7;
    const int rowA = wm * 64 + (q8 & 1) * 8 + r8, colA = (q8 >> 1) * 8;
    const int rowB = wn * 32 + (q8 >> 1) * 8 + r8, colB = (q8 & 1) * 8;

#pragma unroll
    for (int i = 0; i < 16; ++i)
#pragma unroll
        for (int r = 0; r < 4; ++r) acc[i][r] = 0.f;

    auto issue = [&](int stage, int kb) {
        const u32 ab = sbase + stage * STG;
#pragma unroll
        for (int i = 0; i < 4; ++i) {
            int c = tid + i * 256; int row = c >> 3, ku = c & 7;
            cpa16(ab + (u32)(row * BKP + ku * 8) * 2, Agp + (long)row * lda + kb + ku * 8);
        }
        const u32 bb = sbase + stage * STG + TSTG;
#pragma unroll
        for (int i = 0; i < 4; ++i) {
            int c = tid + i * 256; int row = c >> 3, ku = c & 7;
            cpa16(bb + (u32)(row * BKP + ku * 8) * 2, Bgp + (long)row * ldb + kb + ku * 8);
        }
        cpa_commit();
    };

    const int KT = K / BK;
    issue(0, 0);
    issue(1, BK);

    for (int kt = 0; kt < KT; ++kt) {
        cpa_wait1();
        __syncthreads();
        if (kt + 2 < KT) issue((kt + 2) % 3, (kt + 2) * BK);
        else cpa_commit();

        const int stage = kt % 3;
        const u32 ab = sbase + stage * STG;
        const u32 bb = ab + TSTG;
#pragma unroll
        for (int ks = 0; ks < 4; ++ks) {
            const int kk = ks * 16;
            u32 a[4][4], b[4][2];
#pragma unroll
            for (int mi = 0; mi < 4; ++mi)
                ldsm4(a[mi][0], a[mi][1], a[mi][2], a[mi][3],
                      ab + (u32)((rowA + mi * 16) * BKP + kk + colA) * 2);
#pragma unroll
            for (int p = 0; p < 2; ++p)
                ldsm4(b[2 * p][0], b[2 * p][1], b[2 * p + 1][0], b[2 * p + 1][1],
                      bb + (u32)((rowB + p * 16) * BKP + kk + colB) * 2);
#pragma unroll
            for (int mi = 0; mi < 4; ++mi)
#pragma unroll
                for (int nj = 0; nj < 4; ++nj)
                    hmma(acc[mi * 4 + nj], a[mi], b[nj]);
        }
    }
}

// ---------------- QKV projection (z selects Q/K/V; Q pre-scaled by QSCALE) ------
__global__ void __launch_bounds__(256)
qkv_proj(const __half* __restrict__ xh, const __half* __restrict__ wt,
         const float* __restrict__ b3, __half* __restrict__ qk,
         __half* __restrict__ vt, long QKoff)
{
    extern __shared__ __align__(16) __half smem[];
    const u32 sbase = (u32)__cvta_generic_to_shared(smem);
    const int z = blockIdx.z;
    const int m0 = blockIdx.y * 128, n0 = blockIdx.x * 128;

    const __half* Agp = xh + (long)m0 * DDIM;
    const __half* Bgp = wt + (long)z * DDIM * DDIM + (long)n0 * DDIM;
    const float* bias = b3 + z * DDIM;

    float acc[16][4];
    gemm_core_128(Agp, Bgp, DDIM, DDIM, DDIM, sbase, acc);

    const int tid = threadIdx.x;
    const int w = tid >> 5, lane = tid & 31;
    const int wm = w & 1, wn = w >> 1;
    const int gid = lane >> 2, tg = lane & 3;

    if (z < 2) {
        const float sc = (z == 0) ? QSCALE : 1.f;
        __half* Ch = qk + z * QKoff;
#pragma unroll
        for (int mi = 0; mi < 4; ++mi) {
            int r = m0 + wm * 64 + mi * 16 + gid;
#pragma unroll
            for (int nj = 0; nj < 4; ++nj) {
                int n = n0 + wn * 32 + nj * 8 + 2 * tg;
                float b0 = bias[n], b1 = bias[n + 1];
                float* c = acc[mi * 4 + nj];
                *(u32*)&Ch[(long)r * DDIM + n]       = pkh2((c[0] + b0) * sc, (c[1] + b1) * sc);
                *(u32*)&Ch[(long)(r + 8) * DDIM + n] = pkh2((c[2] + b0) * sc, (c[3] + b1) * sc);
            }
        }
    } else {
#pragma unroll
        for (int mi = 0; mi < 4; ++mi) {
            int r = m0 + wm * 64 + mi * 16 + gid;
#pragma unroll
            for (int nj = 0; nj < 4; ++nj) {
                int n = n0 + wn * 32 + nj * 8 + 2 * tg;
                float b0 = bias[n], b1 = bias[n + 1];
                float* c = acc[mi * 4 + nj];
                int bb0 = r >> 11, s0 = r & 2047;
                int bb1 = (r + 8) >> 11, s1 = (r + 8) & 2047;
                long base0 = ((long)(bb0 * NHEAD) * HDIM) * SLEN;
                long base1 = ((long)(bb1 * NHEAD) * HDIM) * SLEN;
                vt[base0 + (long)n * SLEN + s0]       = __float2half(c[0] + b0);
                vt[base0 + (long)(n + 1) * SLEN + s0] = __float2half(c[1] + b1);
                vt[base1 + (long)n * SLEN + s1]       = __float2half(c[2] + b0);
                vt[base1 + (long)(n + 1) * SLEN + s1] = __float2half(c[3] + b1);
            }
        }
    }
}

// ---------------- merged out-projection + attn_mean ------------------------------
__global__ void __launch_bounds__(256)
outmerge(const __half* __restrict__ ctx, const __half* __restrict__ wo,
         const float* __restrict__ bo, float* __restrict__ out,
         const __half* __restrict__ E, const float* __restrict__ rs,
         float* __restrict__ attn)
{
    const int bid = blockIdx.x;
    const int tid = threadIdx.x;

    if (bid < 256) {
        extern __shared__ __align__(16) __half smem[];
        const u32 sbase = (u32)__cvta_generic_to_shared(smem);
        const int m0 = (bid >> 3) * 128, n0 = (bid & 7) * 128;
        const __half* Agp = ctx + (long)m0 * DDIM;
        const __half* Bgp = wo + (long)n0 * DDIM;

        float acc[16][4];
        gemm_core_128(Agp, Bgp, DDIM, DDIM, DDIM, sbase, acc);

        const int w = tid >> 5, lane = tid & 31;
        const int wm = w & 1, wn = w >> 1;
        const int gid = lane >> 2, tg = lane & 3;
#pragma unroll
        for (int mi = 0; mi < 4; ++mi) {
            int r = m0 + wm * 64 + mi * 16 + gid;
#pragma unroll
            for (int nj = 0; nj < 4; ++nj) {
                int n = n0 + wn * 32 + nj * 8 + 2 * tg;
                float b0 = bo[n], b1 = bo[n + 1];
                float* c = acc[mi * 4 + nj];
                *(float2*)&out[(long)r * DDIM + n]       = make_float2(c[0] + b0, c[1] + b1);
                *(float2*)&out[(long)(r + 8) * DDIM + n] = make_float2(c[2] + b0, c[3] + b1);
            }
        }
    } else {
        const int id = bid - 256;
        const int q = id & (SLEN - 1), b = id >> 11;
        __shared__ float siz[NHEAD];
        if (tid < NHEAD) siz[tid] = rs[(long)(b * NHEAD + tid) * SLEN + q];
        __syncthreads();

        float a[8] = {0, 0, 0, 0, 0, 0, 0, 0};
#pragma unroll
        for (int h = 0; h < NHEAD; ++h) {
            const __half* p = E + (((long)(b * NHEAD + h) * SLEN + q) * SLEN) + tid * 8;
            uint4 ev = *(const uint4*)p;
            float z = siz[h];
            float2 f0 = __half22float2(*(__half2*)&ev.x);
            float2 f1 = __half22float2(*(__half2*)&ev.y);
            float2 f2 = __half22float2(*(__half2*)&ev.z);
            float2 f3 = __half22float2(*(__half2*)&ev.w);
            a[0] += f0.x * z; a[1] += f0.y * z; a[2] += f1.x * z; a[3] += f1.y * z;
            a[4] += f2.x * z; a[5] += f2.y * z; a[6] += f3.x * z; a[7] += f3.y * z;
        }
        const float sc = 1.f / (float)NHEAD;
        float* o = attn + ((long)b * SLEN + q) * SLEN + tid * 8;
        *(float4*)o       = make_float4(a[0] * sc, a[1] * sc, a[2] * sc, a[3] * sc);
        *(float4*)(o + 4) = make_float4(a[4] * sc, a[5] * sc, a[6] * sc, a[7] * sc);
    }
}

// ---------------- fused attention v2: BM=64, 128 threads, 2 CTAs/SM --------------
// 4 warps: wm = w&1 (two 32-row subtiles), wn = w>>1 (two 64-key halves).
// 2-stage K/V cp.async pipeline; Q resident; V tile rows 64..71 = ones/zero rows
// so Z = row-sum comes out of the tensor core (column 64).
__global__ void __launch_bounds__(128, 2)
fused_attn(const __half* __restrict__ Q, const __half* __restrict__ Kg,
           const __half* __restrict__ Vt, __half* __restrict__ E,
           __half* __restrict__ ctx, float* __restrict__ rs)
{
    constexpr int QP = 72;
    constexpr int VP = 136;
    constexpr int QTILE = 64 * QP;          // halves
    constexpr int KTILE = 128 * QP;
    constexpr int VTILE = 72 * VP;
    constexpr int NC = SLEN / 128;

    const int tid = threadIdx.x;
    const int m0 = blockIdx.x * 64;
    const int bh = blockIdx.y;
    const int b = bh / NHEAD, h = bh % NHEAD;

    const __half* Qg = Q  + ((long)b * SLEN + m0) * DDIM + h * HDIM;
    const __half* Kb = Kg + ((long)b * SLEN) * DDIM + h * HDIM;
    const __half* Vg = Vt + (long)bh * HDIM * SLEN;
    __half* Eg = E + (long)bh * SLEN * SLEN;

    const int w = tid >> 5, lane = tid & 31;
    const int gid = lane >> 2, tg = lane & 3;
    const int wm = w & 1, wn = w >> 1;
    const int q8 = lane >> 3, r8 = lane & 7;
    const int rowA = wm * 32 + (q8 & 1) * 8 + r8, colA = (q8 >> 1) * 8;
    const int rowB = wn * 64 + (q8 >> 1) * 8 + r8, colB = (q8 & 1) * 8;
    const int rowV = (q8 >> 1) * 8 + r8,            colV = (q8 & 1) * 8;

    extern __shared__ __align__(16) __half smem[];
    const u32 sbase = (u32)__cvta_generic_to_shared(smem);
    const u32 qb = sbase;
    auto kb = [&](int s) { return sbase + (QTILE + s * KTILE) * 2; };
    auto vb = [&](int s) { return sbase + (QTILE + 2 * KTILE + s * VTILE) * 2; };

    __shared__ float zs[2][32][2];
    __shared__ float siz[64];

    // ---- ones/zero rows of both V stages (cp.async writes only rows 0..63) -----
#pragma unroll
    for (int s = 0; s < 2; ++s) {
        __half* vbase = smem + QTILE + 2 * KTILE + s * VTILE;
        for (int i = tid; i < 8 * VP; i += 128) {
            int row = 64 + i / VP, col = i % VP;
            vbase[row * VP + col] = (row == 64) ? __float2half(1.f) : __float2half(0.f);
        }
    }
    __syncthreads();

    auto load_q = [&]() {
#pragma unroll
        for (int i = 0; i < 4; ++i) {
            int c = tid + i * 128; int row = c >> 3, cq = c & 7;
            cpa16(qb + (row * QP + cq * 8) * 2, Qg + (long)row * DDIM + cq * 8);
        }
    };
    auto issue = [&](int chunk) {
        const int stage = chunk & 1;
        const __half* Kp = Kb + (long)(chunk * 128) * DDIM;
        const u32 kbs = kb(stage);
#pragma unroll
        for (int i = 0; i < 8; ++i) {
            int c = tid + i * 128; int row = c >> 3, cq = c & 7;
            cpa16(kbs + (row * QP + cq * 8) * 2, Kp + (long)row * DDIM + cq * 8);
        }
        const __half* Vp = Vg + chunk * 128;
        const u32 vbs = vb(stage);
#pragma unroll
        for (int i = 0; i < 8; ++i) {
            int c = tid + i * 128; int row = c >> 4, cv = c & 15;
            cpa16(vbs + (row * VP + cv * 8) * 2, Vp + (long)row * SLEN + cv * 8);
        }
        cpa_commit();
    };

    float cU[2][8][4];
#pragma unroll
    for (int mi = 0; mi < 2; ++mi)
#pragma unroll
        for (int dj = 0; dj < 8; ++dj)
#pragma unroll
            for (int r = 0; r < 4; ++r) cU[mi][dj][r] = 0.f;
    float cUz[2][4];
#pragma unroll
    for (int mi = 0; mi < 2; ++mi)
#pragma unroll
        for (int r = 0; r < 4; ++r) cUz[mi][r] = 0.f;

    load_q();
    issue(0);     // group 0: Q + chunk 0
    issue(1);     // group 1: chunk 1

    for (int kt = 0; kt < NC; ++kt) {
        cpa_wait1();
        __syncthreads();

        const int stage = kt & 1;
        const u32 kbs = kb(stage), vbs = vb(stage);

        // ---- S' = Q' K^T --------------------------------------------------------
        float cS[2][8][4];
#pragma unroll
        for (int mi = 0; mi < 2; ++mi)
#pragma unroll
            for (int nj = 0; nj < 8; ++nj)
#pragma unroll
                for (int r = 0; r < 4; ++r) cS[mi][nj][r] = 0.f;

#pragma unroll
        for (int kf = 0; kf < 4; ++kf) {
            const int kk = kf * 16;
            u32 a[2][4], bfr[8][2];
#pragma unroll
            for (int mi = 0; mi < 2; ++mi)
                ldsm4(a[mi][0], a[mi][1], a[mi][2], a[mi][3],
                      qb + ((rowA + mi * 16) * QP + kk + colA) * 2);
#pragma unroll
            for (int p = 0; p < 4; ++p)
                ldsm4(bfr[2 * p][0], bfr[2 * p][1], bfr[2 * p + 1][0], bfr[2 * p + 1][1],
                      kbs + ((rowB + p * 16) * QP + kk + colB) * 2);
#pragma unroll
            for (int mi = 0; mi < 2; ++mi)
#pragma unroll
                for (int nj = 0; nj < 8; ++nj)
                    hmma(cS[mi][nj], a[mi], bfr[nj]);
        }

        // ---- E = 2^S' in fp16 ----------------------------------------------------
        u32 eh[2][8][2];
#pragma unroll
        for (int mi = 0; mi < 2; ++mi)
#pragma unroll
            for (int nj = 0; nj < 8; ++nj) {
                eh[mi][nj][0] = ex2h2(pkh2(cS[mi][nj][0], cS[mi][nj][1]));
                eh[mi][nj][1] = ex2h2(pkh2(cS[mi][nj][2], cS[mi][nj][3]));
            }

        // ---- U += E * [V ; ones-row] ----------------------------------------------
#pragma unroll
        for (int kf = 0; kf < 4; ++kf) {
            const int kk2 = kf * 16;
            u32 a[2][4], bv[8][2], bz[2];
#pragma unroll
            for (int mi = 0; mi < 2; ++mi) {
                a[mi][0] = eh[mi][2 * kf][0];
                a[mi][1] = eh[mi][2 * kf][1];
                a[mi][2] = eh[mi][2 * kf + 1][0];
                a[mi][3] = eh[mi][2 * kf + 1][1];
            }
#pragma unroll
            for (int p = 0; p < 4; ++p)
                ldsm4(bv[2 * p][0], bv[2 * p][1], bv[2 * p + 1][0], bv[2 * p + 1][1],
                      vbs + ((rowV + p * 16) * VP + wn * 64 + kk2 + colV) * 2);
            ldsm2(bz[0], bz[1],
                  vbs + ((64 + r8) * VP + wn * 64 + kk2 + (q8 & 1) * 8) * 2);
#pragma unroll
            for (int mi = 0; mi < 2; ++mi) {
#pragma unroll
                for (int dj = 0; dj < 8; ++dj)
                    hmma(cU[mi][dj], a[mi], bv[dj]);
                hmma(cUz[mi], a[mi], bz);
            }
        }

        // ---- stream E tile to gmem -------------------------------------------------
        const long ebase = (long)(m0 + wm * 32) * SLEN + kt * 128 + wn * 64;
#pragma unroll
        for (int mi = 0; mi < 2; ++mi) {
            long r0 = ebase + (long)(mi * 16 + gid) * SLEN + 2 * tg;
#pragma unroll
            for (int nj = 0; nj < 8; ++nj) {
                *(u32*)&Eg[r0 + nj * 8]             = eh[mi][nj][0];
                *(u32*)&Eg[r0 + 8L * SLEN + nj * 8] = eh[mi][nj][1];
            }
        }

        __syncthreads();                      // stage consumed by all warps
        if (kt + 2 < NC) issue(kt + 2);       // refill this stage
        else cpa_commit();                    // keep group-count invariant
    }

    // ---- Z from tensor core: cUz col 64 (tg==0) -----------------------------------
    if (tg == 0) {
#pragma unroll
        for (int mi = 0; mi < 2; ++mi) {
            zs[wm][mi * 16 + gid][wn]     = cUz[mi][0];
            zs[wm][mi * 16 + 8 + gid][wn] = cUz[mi][2];
        }
    }
    __syncthreads();
    if (tid < 64) {
        float inv = 1.f / (zs[tid >> 5][tid & 31][0] + zs[tid >> 5][tid & 31][1]);
        siz[tid] = inv;
        rs[(long)bh * SLEN + m0 + tid] = inv;
    }
    __syncthreads();

    // ---- cross-warp U reduce (2-way over wn) through smem ---------------------------
    float* Ured = (float*)smem;   // 64 x 68 fp32, reuses dead tile space
    if (wn == 1) {
#pragma unroll
        for (int mi = 0; mi < 2; ++mi) {
            int r = wm * 32 + mi * 16 + gid;
#pragma unroll
            for (int dj = 0; dj < 8; ++dj) {
                int n = dj * 8 + 2 * tg;
                *(float2*)&Ured[r * 68 + n]       = make_float2(cU[mi][dj][0], cU[mi][dj][1]);
                *(float2*)&Ured[(r + 8) * 68 + n] = make_float2(cU[mi][dj][2], cU[mi][dj][3]);
            }
        }
    }
    __syncthreads();
    if (wn == 0) {
#pragma unroll
        for (int mi = 0; mi < 2; ++mi) {
            int r = wm * 32 + mi * 16 + gid;
            float iz0 = siz[r], iz1 = siz[r + 8];
            __half* C0 = ctx + ((long)b * SLEN + m0 + r) * DDIM + h * HDIM;
#pragma unroll
            for (int dj = 0; dj < 8; ++dj) {
                int n = dj * 8 + 2 * tg;
                float2 u0 = *(const float2*)&Ured[r * 68 + n];
                float2 u1 = *(const float2*)&Ured[(r + 8) * 68 + n];
                *(u32*)&C0[n] = pkh2((cU[mi][dj][0] + u0.x) * iz0,
                                     (cU[mi][dj][1] + u0.y) * iz0);
                *(u32*)&C0[8L * DDIM + n] = pkh2((cU[mi][dj][2] + u1.x) * iz1,
                                                 (cU[mi][dj][3] + u1.y) * iz1);
            }
        }
    }
}

// ---------------- prep kernels ----------------------------------------------------
__global__ void __launch_bounds__(256)
prep_w(const float* __restrict__ W0, const float* __restrict__ W1,
       const float* __restrict__ W2, const float* __restrict__ W3,
       __half* __restrict__ Wt)
{
    const int z = blockIdx.z;
    const float* W = (z == 0) ? W0 : (z == 1) ? W1 : (z == 2) ? W2 : W3;
    __half* T = Wt + (long)z * DDIM * DDIM;
    __shared__ float t[32][33];
    const int tx = threadIdx.x, ty = threadIdx.y;
    const int n0 = blockIdx.x * 32, k0 = blockIdx.y * 32;
#pragma unroll
    for (int i = 0; i < 4; ++i)
        t[tx][ty + 8 * i] = W[(long)(k0 + ty + 8 * i) * DDIM + n0 + tx];
    __syncthreads();
#pragma unroll
    for (int i = 0; i < 4; ++i)
        T[(long)(n0 + ty + 8 * i) * DDIM + k0 + tx] = __float2half(t[ty + 8 * i][tx]);
}

__global__ void __launch_bounds__(256)
prep_x(const float* __restrict__ x, __half* __restrict__ xh)
{
    long i = ((long)blockIdx.x * 256 + threadIdx.x) * 8;
    float4 f0 = *(const float4*)(x + i);
    float4 f1 = *(const float4*)(x + i + 4);
    uint4 u;
    u.x = pkh2(f0.x, f0.y); u.y = pkh2(f0.z, f0.w);
    u.z = pkh2(f1.x, f1.y); u.w = pkh2(f1.z, f1.w);
    *(uint4*)(xh + i) = u;
}

// ---------------- launch -----------------------------------------------------------
extern "C" void kernel_launch(void* const* d_in, const int* in_sizes, int n_in,
                              void* d_out, int out_size)
{
    const float* x  = (const float*)d_in[0];
    const float* Wq = (const float*)d_in[1];
    const float* bq = (const float*)d_in[2];
    const float* Wk = (const float*)d_in[3];
    const float* bk = (const float*)d_in[4];
    const float* Wv = (const float*)d_in[5];
    const float* bv = (const float*)d_in[6];
    const float* Wo = (const float*)d_in[7];
    const float* bo = (const float*)d_in[8];
    float* out = (float*)d_out;

    const int Bsz = in_sizes[0] / (SLEN * DDIM);   // = 2
    const int BS  = Bsz * SLEN;
    const long NB = (long)BS * DDIM;

    __half *wt, *xh, *qk, *vt, *E, *ctx;
    float *b3, *rs;
    cudaGetSymbolAddress((void**)&wt,  g_wt);
    cudaGetSymbolAddress((void**)&b3,  g_b3);
    cudaGetSymbolAddress((void**)&xh,  g_xh);
    cudaGetSymbolAddress((void**)&qk,  g_qk);
    cudaGetSymbolAddress((void**)&vt,  g_vt);
    cudaGetSymbolAddress((void**)&E,   g_E);
    cudaGetSymbolAddress((void**)&ctx, g_ctx);
    cudaGetSymbolAddress((void**)&rs,  g_rs);

    const int SM_P = 3 * 2 * 128 * 72 * 2;                      // 110592 (gemm core)
    const int SM_F = (64 * 72 + 2 * 128 * 72 + 2 * 72 * 136) * 2; // 85248 (fused v2)
    cudaFuncSetAttribute(qkv_proj,   cudaFuncAttributeMaxDynamicSharedMemorySize, SM_P);
    cudaFuncSetAttribute(outmerge,   cudaFuncAttributeMaxDynamicSharedMemorySize, SM_P);
    cudaFuncSetAttribute(fused_attn, cudaFuncAttributeMaxDynamicSharedMemorySize, SM_F);

    cudaMemcpyAsync(b3,            bq, sizeof(float) * DDIM, cudaMemcpyDeviceToDevice);
    cudaMemcpyAsync(b3 + DDIM,     bk, sizeof(float) * DDIM, cudaMemcpyDeviceToDevice);
    cudaMemcpyAsync(b3 + 2 * DDIM, bv, sizeof(float) * DDIM, cudaMemcpyDeviceToDevice);

    prep_x<<<(unsigned)(NB / (256 * 8)), 256>>>(x, xh);
    prep_w<<<dim3(32, 32, 4), dim3(32, 8)>>>(Wq, Wk, Wv, Wo, wt);

    const long QKoff = (long)BS * DDIM;

    qkv_proj<<<dim3(8, BS / 128, 3), 256, SM_P>>>(xh, wt, b3, qk, vt, QKoff);

    fused_attn<<<dim3(SLEN / 64, Bsz * NHEAD), 128, SM_F>>>(
        qk, qk + QKoff, vt, E, ctx, rs);

    outmerge<<<256 + BS, 256, SM_P>>>(
        ctx, wt + 3L * DDIM * DDIM, bo, out, E, rs, out + NB);
}

// round 10
// speedup vs baseline: 7.1328x; 1.0510x over previous
#include <cuda_runtime.h>
#include <cuda_fp16.h>
#include <cstdint>

#define SLEN  2048
#define DDIM  1024
#define NHEAD 16
#define HDIM  64
#define MAXB  2

using u32 = unsigned int;

// ---------------- scratch (device globals) ------------------------------------
__device__ __half g_wt [4L * DDIM * DDIM];                 // W{q,k,v,o}^T [n][k] fp16
__device__ float  g_b3 [3 * DDIM];                         // packed bq,bk,bv
__device__ __half g_xh [(long)MAXB * SLEN * DDIM];         // x in fp16
__device__ __half g_qk [2L * MAXB * SLEN * DDIM];          // Q (pre-scaled) then K
__device__ __half g_vt [(long)MAXB * NHEAD * HDIM * SLEN]; // V^T [b][h][d][s]
__device__ __half g_E  [(long)MAXB * NHEAD * SLEN * SLEN]; // exp(scores) fp16
__device__ __half g_ctx[(long)MAXB * SLEN * DDIM];
__device__ float  g_rs [MAXB * NHEAD * SLEN];              // 1/rowsum

#define QSCALE 0.1803368801111204f   // log2(e) / 8

// ---------------- helpers ------------------------------------------------------
__device__ __forceinline__ u32 pkh2(float a, float b) {
    __half2 h = __floats2half2_rn(a, b);
    return *(u32*)&h;
}

__device__ __forceinline__ u32 ex2h2(u32 x) {
    u32 r;
    asm("ex2.approx.f16x2 %0, %1;" : "=r"(r) : "r"(x));
    return r;
}

__device__ __forceinline__ void hmma(float* c, const u32* a, const u32* b) {
    asm volatile(
        "mma.sync.aligned.m16n8k16.row.col.f32.f16.f16.f32 "
        "{%0,%1,%2,%3},{%4,%5,%6,%7},{%8,%9},{%0,%1,%2,%3};"
        : "+f"(c[0]), "+f"(c[1]), "+f"(c[2]), "+f"(c[3])
        : "r"(a[0]), "r"(a[1]), "r"(a[2]), "r"(a[3]), "r"(b[0]), "r"(b[1]));
}

__device__ __forceinline__ void ldsm4(u32& r0, u32& r1, u32& r2, u32& r3, u32 saddr) {
    asm volatile("ldmatrix.sync.aligned.m8n8.x4.shared.b16 {%0,%1,%2,%3}, [%4];"
                 : "=r"(r0), "=r"(r1), "=r"(r2), "=r"(r3) : "r"(saddr));
}

__device__ __forceinline__ void cpa16(u32 dst, const void* src) {
    asm volatile("cp.async.cg.shared.global [%0], [%1], 16;" :: "r"(dst), "l"(src));
}
__device__ __forceinline__ void cpa_commit() {
    asm volatile("cp.async.commit_group;" ::: "memory");
}
__device__ __forceinline__ void cpa_wait1() {
    asm volatile("cp.async.wait_group 1;" ::: "memory");
}

// ---------------- GEMM core: BM=128,BN=128,BK=64, 8 warps (WGM=2,WGN=4) ---------
__device__ __forceinline__ void gemm_core_128(
    const __half* __restrict__ Agp, const __half* __restrict__ Bgp,
    int K, int lda, int ldb, u32 sbase, float (*acc)[4])
{
    constexpr int BK = 64, BKP = 72;
    constexpr u32 TSTG = 128 * BKP * 2;
    constexpr u32 STG = 2 * TSTG;

    const int tid = threadIdx.x;
    const int w = tid >> 5, lane = tid & 31;
    const int wm = w & 1, wn = w >> 1;
    const int q8 = lane >> 3, r8 = lane & 7;
    const int rowA = wm * 64 + (q8 & 1) * 8 + r8, colA = (q8 >> 1) * 8;
    const int rowB = wn * 32 + (q8 >> 1) * 8 + r8, colB = (q8 & 1) * 8;

#pragma unroll
    for (int i = 0; i < 16; ++i)
#pragma unroll
        for (int r = 0; r < 4; ++r) acc[i][r] = 0.f;

    auto issue = [&](int stage, int kb) {
        const u32 ab = sbase + stage * STG;
#pragma unroll
        for (int i = 0; i < 4; ++i) {
            int c = tid + i * 256; int row = c >> 3, ku = c & 7;
            cpa16(ab + (u32)(row * BKP + ku * 8) * 2, Agp + (long)row * lda + kb + ku * 8);
        }
        const u32 bb = sbase + stage * STG + TSTG;
#pragma unroll
        for (int i = 0; i < 4; ++i) {
            int c = tid + i * 256; int row = c >> 3, ku = c & 7;
            cpa16(bb + (u32)(row * BKP + ku * 8) * 2, Bgp + (long)row * ldb + kb + ku * 8);
        }
        cpa_commit();
    };

    const int KT = K / BK;
    issue(0, 0);
    issue(1, BK);

    for (int kt = 0; kt < KT; ++kt) {
        cpa_wait1();
        __syncthreads();
        if (kt + 2 < KT) issue((kt + 2) % 3, (kt + 2) * BK);
        else cpa_commit();

        const int stage = kt % 3;
        const u32 ab = sbase + stage * STG;
        const u32 bb = ab + TSTG;
#pragma unroll
        for (int ks = 0; ks < 4; ++ks) {
            const int kk = ks * 16;
            u32 a[4][4], b[4][2];
#pragma unroll
            for (int mi = 0; mi < 4; ++mi)
                ldsm4(a[mi][0], a[mi][1], a[mi][2], a[mi][3],
                      ab + (u32)((rowA + mi * 16) * BKP + kk + colA) * 2);
#pragma unroll
            for (int p = 0; p < 2; ++p)
                ldsm4(b[2 * p][0], b[2 * p][1], b[2 * p + 1][0], b[2 * p + 1][1],
                      bb + (u32)((rowB + p * 16) * BKP + kk + colB) * 2);
#pragma unroll
            for (int mi = 0; mi < 4; ++mi)
#pragma unroll
                for (int nj = 0; nj < 4; ++nj)
                    hmma(acc[mi * 4 + nj], a[mi], b[nj]);
        }
    }
}

// ---------------- QKV projection (z selects Q/K/V; Q pre-scaled by QSCALE) ------
__global__ void __launch_bounds__(256, 2)
qkv_proj(const __half* __restrict__ xh, const __half* __restrict__ wt,
         const float* __restrict__ b3, __half* __restrict__ qk,
         __half* __restrict__ vt, long QKoff)
{
    extern __shared__ __align__(16) __half smem[];
    const u32 sbase = (u32)__cvta_generic_to_shared(smem);
    const int z = blockIdx.z;
    const int m0 = blockIdx.y * 128, n0 = blockIdx.x * 128;

    const __half* Agp = xh + (long)m0 * DDIM;
    const __half* Bgp = wt + (long)z * DDIM * DDIM + (long)n0 * DDIM;
    const float* bias = b3 + z * DDIM;

    float acc[16][4];
    gemm_core_128(Agp, Bgp, DDIM, DDIM, DDIM, sbase, acc);

    const int tid = threadIdx.x;
    const int w = tid >> 5, lane = tid & 31;
    const int wm = w & 1, wn = w >> 1;
    const int gid = lane >> 2, tg = lane & 3;

    if (z < 2) {
        const float sc = (z == 0) ? QSCALE : 1.f;
        __half* Ch = qk + z * QKoff;
#pragma unroll
        for (int mi = 0; mi < 4; ++mi) {
            int r = m0 + wm * 64 + mi * 16 + gid;
#pragma unroll
            for (int nj = 0; nj < 4; ++nj) {
                int n = n0 + wn * 32 + nj * 8 + 2 * tg;
                float b0 = bias[n], b1 = bias[n + 1];
                float* c = acc[mi * 4 + nj];
                *(u32*)&Ch[(long)r * DDIM + n]       = pkh2((c[0] + b0) * sc, (c[1] + b1) * sc);
                *(u32*)&Ch[(long)(r + 8) * DDIM + n] = pkh2((c[2] + b0) * sc, (c[3] + b1) * sc);
            }
        }
    } else {
#pragma unroll
        for (int mi = 0; mi < 4; ++mi) {
            int r = m0 + wm * 64 + mi * 16 + gid;
#pragma unroll
            for (int nj = 0; nj < 4; ++nj) {
                int n = n0 + wn * 32 + nj * 8 + 2 * tg;
                float b0 = bias[n], b1 = bias[n + 1];
                float* c = acc[mi * 4 + nj];
                int bb0 = r >> 11, s0 = r & 2047;
                int bb1 = (r + 8) >> 11, s1 = (r + 8) & 2047;
                long base0 = ((long)(bb0 * NHEAD) * HDIM) * SLEN;
                long base1 = ((long)(bb1 * NHEAD) * HDIM) * SLEN;
                vt[base0 + (long)n * SLEN + s0]       = __float2half(c[0] + b0);
                vt[base0 + (long)(n + 1) * SLEN + s0] = __float2half(c[1] + b1);
                vt[base1 + (long)n * SLEN + s1]       = __float2half(c[2] + b0);
                vt[base1 + (long)(n + 1) * SLEN + s1] = __float2half(c[3] + b1);
            }
        }
    }
}

// ---------------- merged out-projection + attn_mean ------------------------------
__global__ void __launch_bounds__(256, 2)
outmerge(const __half* __restrict__ ctx, const __half* __restrict__ wo,
         const float* __restrict__ bo, float* __restrict__ out,
         const __half* __restrict__ E, const float* __restrict__ rs,
         float* __restrict__ attn)
{
    const int bid = blockIdx.x;
    const int tid = threadIdx.x;

    if (bid < 256) {
        extern __shared__ __align__(16) __half smem[];
        const u32 sbase = (u32)__cvta_generic_to_shared(smem);
        const int m0 = (bid >> 3) * 128, n0 = (bid & 7) * 128;
        const __half* Agp = ctx + (long)m0 * DDIM;
        const __half* Bgp = wo + (long)n0 * DDIM;

        float acc[16][4];
        gemm_core_128(Agp, Bgp, DDIM, DDIM, DDIM, sbase, acc);

        const int w = tid >> 5, lane = tid & 31;
        const int wm = w & 1, wn = w >> 1;
        const int gid = lane >> 2, tg = lane & 3;
#pragma unroll
        for (int mi = 0; mi < 4; ++mi) {
            int r = m0 + wm * 64 + mi * 16 + gid;
#pragma unroll
            for (int nj = 0; nj < 4; ++nj) {
                int n = n0 + wn * 32 + nj * 8 + 2 * tg;
                float b0 = bo[n], b1 = bo[n + 1];
                float* c = acc[mi * 4 + nj];
                *(float2*)&out[(long)r * DDIM + n]       = make_float2(c[0] + b0, c[1] + b1);
                *(float2*)&out[(long)(r + 8) * DDIM + n] = make_float2(c[2] + b0, c[3] + b1);
            }
        }
    } else {
        const int id = bid - 256;
        const int q = id & (SLEN - 1), b = id >> 11;
        __shared__ float siz[NHEAD];
        if (tid < NHEAD) siz[tid] = rs[(long)(b * NHEAD + tid) * SLEN + q];
        __syncthreads();

        float a[8] = {0, 0, 0, 0, 0, 0, 0, 0};
#pragma unroll
        for (int h = 0; h < NHEAD; ++h) {
            const __half* p = E + (((long)(b * NHEAD + h) * SLEN + q) * SLEN) + tid * 8;
            uint4 ev = *(const uint4*)p;
            float z = siz[h];
            float2 f0 = __half22float2(*(__half2*)&ev.x);
            float2 f1 = __half22float2(*(__half2*)&ev.y);
            float2 f2 = __half22float2(*(__half2*)&ev.z);
            float2 f3 = __half22float2(*(__half2*)&ev.w);
            a[0] += f0.x * z; a[1] += f0.y * z; a[2] += f1.x * z; a[3] += f1.y * z;
            a[4] += f2.x * z; a[5] += f2.y * z; a[6] += f3.x * z; a[7] += f3.y * z;
        }
        const float sc = 1.f / (float)NHEAD;
        float* o = attn + ((long)b * SLEN + q) * SLEN + tid * 8;
        *(float4*)o       = make_float4(a[0] * sc, a[1] * sc, a[2] * sc, a[3] * sc);
        *(float4*)(o + 4) = make_float4(a[4] * sc, a[5] * sc, a[6] * sc, a[7] * sc);
    }
}

// ---------------- fused attention v3: BM=64, 128 threads, 2 CTAs/SM --------------
// Z row-sum via tensor core with an ANALYTIC ones B-fragment (no smem ones rows).
__global__ void __launch_bounds__(128, 2)
fused_attn(const __half* __restrict__ Q, const __half* __restrict__ Kg,
           const __half* __restrict__ Vt, __half* __restrict__ E,
           __half* __restrict__ ctx, float* __restrict__ rs)
{
    constexpr int QP = 72;
    constexpr int VP = 136;
    constexpr int QTILE = 64 * QP;          // halves
    constexpr int KTILE = 128 * QP;
    constexpr int VTILE = 64 * VP;          // 64 data rows only
    constexpr int NC = SLEN / 128;

    const int tid = threadIdx.x;
    const int m0 = blockIdx.x * 64;
    const int bh = blockIdx.y;
    const int b = bh / NHEAD, h = bh % NHEAD;

    const __half* Qg = Q  + ((long)b * SLEN + m0) * DDIM + h * HDIM;
    const __half* Kb = Kg + ((long)b * SLEN) * DDIM + h * HDIM;
    const __half* Vg = Vt + (long)bh * HDIM * SLEN;
    __half* Eg = E + (long)bh * SLEN * SLEN;

    const int w = tid >> 5, lane = tid & 31;
    const int gid = lane >> 2, tg = lane & 3;
    const int wm = w & 1, wn = w >> 1;
    const int q8 = lane >> 3, r8 = lane & 7;
    const int rowA = wm * 32 + (q8 & 1) * 8 + r8, colA = (q8 >> 1) * 8;
    const int rowB = wn * 64 + (q8 >> 1) * 8 + r8, colB = (q8 & 1) * 8;
    const int rowV = (q8 >> 1) * 8 + r8,            colV = (q8 & 1) * 8;

    // analytic ones-column B fragment: output col 64 <- sum_k E, cols 65..71 <- 0
    const u32 bzc = (gid == 0) ? 0x3C003C00u : 0u;
    const u32 bz[2] = { bzc, bzc };

    extern __shared__ __align__(16) __half smem[];
    const u32 sbase = (u32)__cvta_generic_to_shared(smem);
    const u32 qb = sbase;
    auto kb = [&](int s) { return sbase + (QTILE + s * KTILE) * 2; };
    auto vb = [&](int s) { return sbase + (QTILE + 2 * KTILE + s * VTILE) * 2; };

    __shared__ float zs[2][32][2];
    __shared__ float siz[64];

    auto load_q = [&]() {
#pragma unroll
        for (int i = 0; i < 4; ++i) {
            int c = tid + i * 128; int row = c >> 3, cq = c & 7;
            cpa16(qb + (row * QP + cq * 8) * 2, Qg + (long)row * DDIM + cq * 8);
        }
    };
    auto issue = [&](int chunk) {
        const int stage = chunk & 1;
        const __half* Kp = Kb + (long)(chunk * 128) * DDIM;
        const u32 kbs = kb(stage);
#pragma unroll
        for (int i = 0; i < 8; ++i) {
            int c = tid + i * 128; int row = c >> 3, cq = c & 7;
            cpa16(kbs + (row * QP + cq * 8) * 2, Kp + (long)row * DDIM + cq * 8);
        }
        const __half* Vp = Vg + chunk * 128;
        const u32 vbs = vb(stage);
#pragma unroll
        for (int i = 0; i < 8; ++i) {
            int c = tid + i * 128; int row = c >> 4, cv = c & 15;
            cpa16(vbs + (row * VP + cv * 8) * 2, Vp + (long)row * SLEN + cv * 8);
        }
        cpa_commit();
    };

    float cU[2][8][4];
#pragma unroll
    for (int mi = 0; mi < 2; ++mi)
#pragma unroll
        for (int dj = 0; dj < 8; ++dj)
#pragma unroll
            for (int r = 0; r < 4; ++r) cU[mi][dj][r] = 0.f;
    float cUz[2][4];
#pragma unroll
    for (int mi = 0; mi < 2; ++mi)
#pragma unroll
        for (int r = 0; r < 4; ++r) cUz[mi][r] = 0.f;

    load_q();
    issue(0);
    issue(1);

    for (int kt = 0; kt < NC; ++kt) {
        cpa_wait1();
        __syncthreads();

        const int stage = kt & 1;
        const u32 kbs = kb(stage), vbs = vb(stage);

        // ---- S' = Q' K^T --------------------------------------------------------
        float cS[2][8][4];
#pragma unroll
        for (int mi = 0; mi < 2; ++mi)
#pragma unroll
            for (int nj = 0; nj < 8; ++nj)
#pragma unroll
                for (int r = 0; r < 4; ++r) cS[mi][nj][r] = 0.f;

#pragma unroll
        for (int kf = 0; kf < 4; ++kf) {
            const int kk = kf * 16;
            u32 a[2][4], bfr[8][2];
#pragma unroll
            for (int mi = 0; mi < 2; ++mi)
                ldsm4(a[mi][0], a[mi][1], a[mi][2], a[mi][3],
                      qb + ((rowA + mi * 16) * QP + kk + colA) * 2);
#pragma unroll
            for (int p = 0; p < 4; ++p)
                ldsm4(bfr[2 * p][0], bfr[2 * p][1], bfr[2 * p + 1][0], bfr[2 * p + 1][1],
                      kbs + ((rowB + p * 16) * QP + kk + colB) * 2);
#pragma unroll
            for (int mi = 0; mi < 2; ++mi)
#pragma unroll
                for (int nj = 0; nj < 8; ++nj)
                    hmma(cS[mi][nj], a[mi], bfr[nj]);
        }

        // ---- E = 2^S' in fp16 ----------------------------------------------------
        u32 eh[2][8][2];
#pragma unroll
        for (int mi = 0; mi < 2; ++mi)
#pragma unroll
            for (int nj = 0; nj < 8; ++nj) {
                eh[mi][nj][0] = ex2h2(pkh2(cS[mi][nj][0], cS[mi][nj][1]));
                eh[mi][nj][1] = ex2h2(pkh2(cS[mi][nj][2], cS[mi][nj][3]));
            }

        // ---- U += E * V ; Z += E * ones (constant frag) ---------------------------
#pragma unroll
        for (int kf = 0; kf < 4; ++kf) {
            const int kk2 = kf * 16;
            u32 a[2][4], bv[8][2];
#pragma unroll
            for (int mi = 0; mi < 2; ++mi) {
                a[mi][0] = eh[mi][2 * kf][0];
                a[mi][1] = eh[mi][2 * kf][1];
                a[mi][2] = eh[mi][2 * kf + 1][0];
                a[mi][3] = eh[mi][2 * kf + 1][1];
            }
#pragma unroll
            for (int p = 0; p < 4; ++p)
                ldsm4(bv[2 * p][0], bv[2 * p][1], bv[2 * p + 1][0], bv[2 * p + 1][1],
                      vbs + ((rowV + p * 16) * VP + wn * 64 + kk2 + colV) * 2);
#pragma unroll
            for (int mi = 0; mi < 2; ++mi) {
#pragma unroll
                for (int dj = 0; dj < 8; ++dj)
                    hmma(cU[mi][dj], a[mi], bv[dj]);
                hmma(cUz[mi], a[mi], bz);
            }
        }

        // ---- stream E tile to gmem -------------------------------------------------
        const long ebase = (long)(m0 + wm * 32) * SLEN + kt * 128 + wn * 64;
#pragma unroll
        for (int mi = 0; mi < 2; ++mi) {
            long r0 = ebase + (long)(mi * 16 + gid) * SLEN + 2 * tg;
#pragma unroll
            for (int nj = 0; nj < 8; ++nj) {
                *(u32*)&Eg[r0 + nj * 8]             = eh[mi][nj][0];
                *(u32*)&Eg[r0 + 8L * SLEN + nj * 8] = eh[mi][nj][1];
            }
        }

        __syncthreads();                      // stage consumed by all warps
        if (kt + 2 < NC) issue(kt + 2);       // refill this stage
        else cpa_commit();                    // keep group-count invariant
    }

    // ---- Z from tensor core: cUz col 64 (tg==0) -----------------------------------
    if (tg == 0) {
#pragma unroll
        for (int mi = 0; mi < 2; ++mi) {
            zs[wm][mi * 16 + gid][wn]     = cUz[mi][0];
            zs[wm][mi * 16 + 8 + gid][wn] = cUz[mi][2];
        }
    }
    __syncthreads();
    if (tid < 64) {
        float inv = 1.f / (zs[tid >> 5][tid & 31][0] + zs[tid >> 5][tid & 31][1]);
        siz[tid] = inv;
        rs[(long)bh * SLEN + m0 + tid] = inv;
    }
    __syncthreads();

    // ---- cross-warp U reduce (2-way over wn) through smem ---------------------------
    float* Ured = (float*)smem;
    if (wn == 1) {
#pragma unroll
        for (int mi = 0; mi < 2; ++mi) {
            int r = wm * 32 + mi * 16 + gid;
#pragma unroll
            for (int dj = 0; dj < 8; ++dj) {
                int n = dj * 8 + 2 * tg;
                *(float2*)&Ured[r * 68 + n]       = make_float2(cU[mi][dj][0], cU[mi][dj][1]);
                *(float2*)&Ured[(r + 8) * 68 + n] = make_float2(cU[mi][dj][2], cU[mi][dj][3]);
            }
        }
    }
    __syncthreads();
    if (wn == 0) {
#pragma unroll
        for (int mi = 0; mi < 2; ++mi) {
            int r = wm * 32 + mi * 16 + gid;
            float iz0 = siz[r], iz1 = siz[r + 8];
            __half* C0 = ctx + ((long)b * SLEN + m0 + r) * DDIM + h * HDIM;
#pragma unroll
            for (int dj = 0; dj < 8; ++dj) {
                int n = dj * 8 + 2 * tg;
                float2 u0 = *(const float2*)&Ured[r * 68 + n];
                float2 u1 = *(const float2*)&Ured[(r + 8) * 68 + n];
                *(u32*)&C0[n] = pkh2((cU[mi][dj][0] + u0.x) * iz0,
                                     (cU[mi][dj][1] + u0.y) * iz0);
                *(u32*)&C0[8L * DDIM + n] = pkh2((cU[mi][dj][2] + u1.x) * iz1,
                                                 (cU[mi][dj][3] + u1.y) * iz1);
            }
        }
    }
}

// ---------------- prep kernels ----------------------------------------------------
__global__ void __launch_bounds__(256)
prep_w(const float* __restrict__ W0, const float* __restrict__ W1,
       const float* __restrict__ W2, const float* __restrict__ W3,
       __half* __restrict__ Wt)
{
    const int z = blockIdx.z;
    const float* W = (z == 0) ? W0 : (z == 1) ? W1 : (z == 2) ? W2 : W3;
    __half* T = Wt + (long)z * DDIM * DDIM;
    __shared__ float t[32][33];
    const int tx = threadIdx.x, ty = threadIdx.y;
    const int n0 = blockIdx.x * 32, k0 = blockIdx.y * 32;
#pragma unroll
    for (int i = 0; i < 4; ++i)
        t[tx][ty + 8 * i] = W[(long)(k0 + ty + 8 * i) * DDIM + n0 + tx];
    __syncthreads();
#pragma unroll
    for (int i = 0; i < 4; ++i)
        T[(long)(n0 + ty + 8 * i) * DDIM + k0 + tx] = __float2half(t[ty + 8 * i][tx]);
}

__global__ void __launch_bounds__(256)
prep_x(const float* __restrict__ x, __half* __restrict__ xh)
{
    long i = ((long)blockIdx.x * 256 + threadIdx.x) * 8;
    float4 f0 = *(const float4*)(x + i);
    float4 f1 = *(const float4*)(x + i + 4);
    uint4 u;
    u.x = pkh2(f0.x, f0.y); u.y = pkh2(f0.z, f0.w);
    u.z = pkh2(f1.x, f1.y); u.w = pkh2(f1.z, f1.w);
    *(uint4*)(xh + i) = u;
}

// ---------------- launch -----------------------------------------------------------
extern "C" void kernel_launch(void* const* d_in, const int* in_sizes, int n_in,
                              void* d_out, int out_size)
{
    const float* x  = (const float*)d_in[0];
    const float* Wq = (const float*)d_in[1];
    const float* bq = (const float*)d_in[2];
    const float* Wk = (const float*)d_in[3];
    const float* bk = (const float*)d_in[4];
    const float* Wv = (const float*)d_in[5];
    const float* bv = (const float*)d_in[6];
    const float* Wo = (const float*)d_in[7];
    const float* bo = (const float*)d_in[8];
    float* out = (float*)d_out;

    const int Bsz = in_sizes[0] / (SLEN * DDIM);   // = 2
    const int BS  = Bsz * SLEN;
    const long NB = (long)BS * DDIM;

    __half *wt, *xh, *qk, *vt, *E, *ctx;
    float *b3, *rs;
    cudaGetSymbolAddress((void**)&wt,  g_wt);
    cudaGetSymbolAddress((void**)&b3,  g_b3);
    cudaGetSymbolAddress((void**)&xh,  g_xh);
    cudaGetSymbolAddress((void**)&qk,  g_qk);
    cudaGetSymbolAddress((void**)&vt,  g_vt);
    cudaGetSymbolAddress((void**)&E,   g_E);
    cudaGetSymbolAddress((void**)&ctx, g_ctx);
    cudaGetSymbolAddress((void**)&rs,  g_rs);

    const int SM_P = 3 * 2 * 128 * 72 * 2;                        // 110592 (gemm core)
    const int SM_F = (64 * 72 + 2 * 128 * 72 + 2 * 64 * 136) * 2; // 80896 (fused v3)
    cudaFuncSetAttribute(qkv_proj,   cudaFuncAttributeMaxDynamicSharedMemorySize, SM_P);
    cudaFuncSetAttribute(outmerge,   cudaFuncAttributeMaxDynamicSharedMemorySize, SM_P);
    cudaFuncSetAttribute(fused_attn, cudaFuncAttributeMaxDynamicSharedMemorySize, SM_F);

    cudaMemcpyAsync(b3,            bq, sizeof(float) * DDIM, cudaMemcpyDeviceToDevice);
    cudaMemcpyAsync(b3 + DDIM,     bk, sizeof(float) * DDIM, cudaMemcpyDeviceToDevice);
    cudaMemcpyAsync(b3 + 2 * DDIM, bv, sizeof(float) * DDIM, cudaMemcpyDeviceToDevice);

    prep_x<<<(unsigned)(NB / (256 * 8)), 256>>>(x, xh);
    prep_w<<<dim3(32, 32, 4), dim3(32, 8)>>>(Wq, Wk, Wv, Wo, wt);

    const long QKoff = (long)BS * DDIM;

    qkv_proj<<<dim3(8, BS / 128, 3), 256, SM_P>>>(xh, wt, b3, qk, vt, QKoff);

    fused_attn<<<dim3(SLEN / 64, Bsz * NHEAD), 128, SM_F>>>(
        qk, qk + QKoff, vt, E, ctx, rs);

    outmerge<<<256 + BS, 256, SM_P>>>(
        ctx, wt + 3L * DDIM * DDIM, bo, out, E, rs, out + NB);
}

// round 11
// speedup vs baseline: 7.2124x; 1.0112x over previous
#include <cuda_runtime.h>
#include <cuda_fp16.h>
#include <cstdint>

#define SLEN  2048
#define DDIM  1024
#define NHEAD 16
#define HDIM  64
#define MAXB  2

using u32 = unsigned int;

// ---------------- scratch (device globals) ------------------------------------
__device__ __half g_wt [4L * DDIM * DDIM];                 // W{q,k,v,o}^T [n][k] fp16
__device__ float  g_b3 [3 * DDIM];                         // packed bq,bk,bv
__device__ __half g_xh [(long)MAXB * SLEN * DDIM];         // x in fp16
__device__ __half g_qk [2L * MAXB * SLEN * DDIM];          // Q (pre-scaled) then K
__device__ __half g_vt [(long)MAXB * NHEAD * HDIM * SLEN]; // V^T [b][h][d][s]
__device__ __half g_E  [(long)MAXB * NHEAD * SLEN * SLEN]; // exp(scores) fp16
__device__ __half g_ctx[(long)MAXB * SLEN * DDIM];
__device__ float  g_rs [MAXB * NHEAD * SLEN];              // 1/rowsum

#define QSCALE 0.1803368801111204f   // log2(e) / 8

// ---------------- helpers ------------------------------------------------------
__device__ __forceinline__ u32 pkh2(float a, float b) {
    __half2 h = __floats2half2_rn(a, b);
    return *(u32*)&h;
}

__device__ __forceinline__ u32 ex2h2(u32 x) {
    u32 r;
    asm("ex2.approx.f16x2 %0, %1;" : "=r"(r) : "r"(x));
    return r;
}

__device__ __forceinline__ void hmma(float* c, const u32* a, const u32* b) {
    asm volatile(
        "mma.sync.aligned.m16n8k16.row.col.f32.f16.f16.f32 "
        "{%0,%1,%2,%3},{%4,%5,%6,%7},{%8,%9},{%0,%1,%2,%3};"
        : "+f"(c[0]), "+f"(c[1]), "+f"(c[2]), "+f"(c[3])
        : "r"(a[0]), "r"(a[1]), "r"(a[2]), "r"(a[3]), "r"(b[0]), "r"(b[1]));
}

__device__ __forceinline__ void ldsm4(u32& r0, u32& r1, u32& r2, u32& r3, u32 saddr) {
    asm volatile("ldmatrix.sync.aligned.m8n8.x4.shared.b16 {%0,%1,%2,%3}, [%4];"
                 : "=r"(r0), "=r"(r1), "=r"(r2), "=r"(r3) : "r"(saddr));
}

__device__ __forceinline__ void cpa16(u32 dst, const void* src) {
    asm volatile("cp.async.cg.shared.global [%0], [%1], 16;" :: "r"(dst), "l"(src));
}
__device__ __forceinline__ void cpa_commit() {
    asm volatile("cp.async.commit_group;" ::: "memory");
}
__device__ __forceinline__ void cpa_wait1() {
    asm volatile("cp.async.wait_group 1;" ::: "memory");
}

// ---------------- GEMM core: BM=128,BN=128,BK=64, 8 warps (WGM=2,WGN=4) ---------
__device__ __forceinline__ void gemm_core_128(
    const __half* __restrict__ Agp, const __half* __restrict__ Bgp,
    int K, int lda, int ldb, u32 sbase, float (*acc)[4])
{
    constexpr int BK = 64, BKP = 72;
    constexpr u32 TSTG = 128 * BKP * 2;
    constexpr u32 STG = 2 * TSTG;

    const int tid = threadIdx.x;
    const int w = tid >> 5, lane = tid & 31;
    const int wm = w & 1, wn = w >> 1;
    const int q8 = lane >> 3, r8 = lane & 7;
    const int rowA = wm * 64 + (q8 & 1) * 8 + r8, colA = (q8 >> 1) * 8;
    const int rowB = wn * 32 + (q8 >> 1) * 8 + r8, colB = (q8 & 1) * 8;

#pragma unroll
    for (int i = 0; i < 16; ++i)
#pragma unroll
        for (int r = 0; r < 4; ++r) acc[i][r] = 0.f;

    auto issue = [&](int stage, int kb) {
        const u32 ab = sbase + stage * STG;
#pragma unroll
        for (int i = 0; i < 4; ++i) {
            int c = tid + i * 256; int row = c >> 3, ku = c & 7;
            cpa16(ab + (u32)(row * BKP + ku * 8) * 2, Agp + (long)row * lda + kb + ku * 8);
        }
        const u32 bb = sbase + stage * STG + TSTG;
#pragma unroll
        for (int i = 0; i < 4; ++i) {
            int c = tid + i * 256; int row = c >> 3, ku = c & 7;
            cpa16(bb + (u32)(row * BKP + ku * 8) * 2, Bgp + (long)row * ldb + kb + ku * 8);
        }
        cpa_commit();
    };

    const int KT = K / BK;
    issue(0, 0);
    issue(1, BK);

    for (int kt = 0; kt < KT; ++kt) {
        cpa_wait1();
        __syncthreads();
        if (kt + 2 < KT) issue((kt + 2) % 3, (kt + 2) * BK);
        else cpa_commit();

        const int stage = kt % 3;
        const u32 ab = sbase + stage * STG;
        const u32 bb = ab + TSTG;
#pragma unroll
        for (int ks = 0; ks < 4; ++ks) {
            const int kk = ks * 16;
            u32 a[4][4], b[4][2];
#pragma unroll
            for (int mi = 0; mi < 4; ++mi)
                ldsm4(a[mi][0], a[mi][1], a[mi][2], a[mi][3],
                      ab + (u32)((rowA + mi * 16) * BKP + kk + colA) * 2);
#pragma unroll
            for (int p = 0; p < 2; ++p)
                ldsm4(b[2 * p][0], b[2 * p][1], b[2 * p + 1][0], b[2 * p + 1][1],
                      bb + (u32)((rowB + p * 16) * BKP + kk + colB) * 2);
#pragma unroll
            for (int mi = 0; mi < 4; ++mi)
#pragma unroll
                for (int nj = 0; nj < 4; ++nj)
                    hmma(acc[mi * 4 + nj], a[mi], b[nj]);
        }
    }
}

// ---------------- QKV projection (z selects Q/K/V; Q pre-scaled by QSCALE) ------
__global__ void __launch_bounds__(256, 2)
qkv_proj(const __half* __restrict__ xh, const __half* __restrict__ wt,
         const float* __restrict__ b3, __half* __restrict__ qk,
         __half* __restrict__ vt, long QKoff)
{
    extern __shared__ __align__(16) __half smem[];
    const u32 sbase = (u32)__cvta_generic_to_shared(smem);
    const int z = blockIdx.z;
    const int m0 = blockIdx.y * 128, n0 = blockIdx.x * 128;

    const __half* Agp = xh + (long)m0 * DDIM;
    const __half* Bgp = wt + (long)z * DDIM * DDIM + (long)n0 * DDIM;
    const float* bias = b3 + z * DDIM;

    float acc[16][4];
    gemm_core_128(Agp, Bgp, DDIM, DDIM, DDIM, sbase, acc);

    const int tid = threadIdx.x;
    const int w = tid >> 5, lane = tid & 31;
    const int wm = w & 1, wn = w >> 1;
    const int gid = lane >> 2, tg = lane & 3;

    if (z < 2) {
        const float sc = (z == 0) ? QSCALE : 1.f;
        __half* Ch = qk + z * QKoff;
#pragma unroll
        for (int mi = 0; mi < 4; ++mi) {
            int r = m0 + wm * 64 + mi * 16 + gid;
#pragma unroll
            for (int nj = 0; nj < 4; ++nj) {
                int n = n0 + wn * 32 + nj * 8 + 2 * tg;
                float b0 = bias[n], b1 = bias[n + 1];
                float* c = acc[mi * 4 + nj];
                *(u32*)&Ch[(long)r * DDIM + n]       = pkh2((c[0] + b0) * sc, (c[1] + b1) * sc);
                *(u32*)&Ch[(long)(r + 8) * DDIM + n] = pkh2((c[2] + b0) * sc, (c[3] + b1) * sc);
            }
        }
    } else {
#pragma unroll
        for (int mi = 0; mi < 4; ++mi) {
            int r = m0 + wm * 64 + mi * 16 + gid;
#pragma unroll
            for (int nj = 0; nj < 4; ++nj) {
                int n = n0 + wn * 32 + nj * 8 + 2 * tg;
                float b0 = bias[n], b1 = bias[n + 1];
                float* c = acc[mi * 4 + nj];
                int bb0 = r >> 11, s0 = r & 2047;
                int bb1 = (r + 8) >> 11, s1 = (r + 8) & 2047;
                long base0 = ((long)(bb0 * NHEAD) * HDIM) * SLEN;
                long base1 = ((long)(bb1 * NHEAD) * HDIM) * SLEN;
                vt[base0 + (long)n * SLEN + s0]       = __float2half(c[0] + b0);
                vt[base0 + (long)(n + 1) * SLEN + s0] = __float2half(c[1] + b1);
                vt[base1 + (long)n * SLEN + s1]       = __float2half(c[2] + b0);
                vt[base1 + (long)(n + 1) * SLEN + s1] = __float2half(c[3] + b1);
            }
        }
    }
}

// ---------------- merged out-projection + attn_mean ------------------------------
__global__ void __launch_bounds__(256, 2)
outmerge(const __half* __restrict__ ctx, const __half* __restrict__ wo,
         const float* __restrict__ bo, float* __restrict__ out,
         const __half* __restrict__ E, const float* __restrict__ rs,
         float* __restrict__ attn)
{
    const int bid = blockIdx.x;
    const int tid = threadIdx.x;

    if (bid < 256) {
        extern __shared__ __align__(16) __half smem[];
        const u32 sbase = (u32)__cvta_generic_to_shared(smem);
        const int m0 = (bid >> 3) * 128, n0 = (bid & 7) * 128;
        const __half* Agp = ctx + (long)m0 * DDIM;
        const __half* Bgp = wo + (long)n0 * DDIM;

        float acc[16][4];
        gemm_core_128(Agp, Bgp, DDIM, DDIM, DDIM, sbase, acc);

        const int w = tid >> 5, lane = tid & 31;
        const int wm = w & 1, wn = w >> 1;
        const int gid = lane >> 2, tg = lane & 3;
#pragma unroll
        for (int mi = 0; mi < 4; ++mi) {
            int r = m0 + wm * 64 + mi * 16 + gid;
#pragma unroll
            for (int nj = 0; nj < 4; ++nj) {
                int n = n0 + wn * 32 + nj * 8 + 2 * tg;
                float b0 = bo[n], b1 = bo[n + 1];
                float* c = acc[mi * 4 + nj];
                *(float2*)&out[(long)r * DDIM + n]       = make_float2(c[0] + b0, c[1] + b1);
                *(float2*)&out[(long)(r + 8) * DDIM + n] = make_float2(c[2] + b0, c[3] + b1);
            }
        }
    } else {
        const int id = bid - 256;
        const int q = id & (SLEN - 1), b = id >> 11;
        __shared__ float siz[NHEAD];
        if (tid < NHEAD) siz[tid] = rs[(long)(b * NHEAD + tid) * SLEN + q];
        __syncthreads();

        float a[8] = {0, 0, 0, 0, 0, 0, 0, 0};
#pragma unroll
        for (int h = 0; h < NHEAD; ++h) {
            const __half* p = E + (((long)(b * NHEAD + h) * SLEN + q) * SLEN) + tid * 8;
            uint4 ev = *(const uint4*)p;
            float z = siz[h];
            float2 f0 = __half22float2(*(__half2*)&ev.x);
            float2 f1 = __half22float2(*(__half2*)&ev.y);
            float2 f2 = __half22float2(*(__half2*)&ev.z);
            float2 f3 = __half22float2(*(__half2*)&ev.w);
            a[0] += f0.x * z; a[1] += f0.y * z; a[2] += f1.x * z; a[3] += f1.y * z;
            a[4] += f2.x * z; a[5] += f2.y * z; a[6] += f3.x * z; a[7] += f3.y * z;
        }
        const float sc = 1.f / (float)NHEAD;
        float* o = attn + ((long)b * SLEN + q) * SLEN + tid * 8;
        *(float4*)o       = make_float4(a[0] * sc, a[1] * sc, a[2] * sc, a[3] * sc);
        *(float4*)(o + 4) = make_float4(a[4] * sc, a[5] * sc, a[6] * sc, a[7] * sc);
    }
}

// ---------------- fused attention v4: hoisted Q frags + split-half softmax -------
// BM=64, 128 threads, 2 CTAs/SM. Q fragments loaded once (loop-invariant).
// Per chunk: two independent 32-key halves (cS/eh live-range halved).
__global__ void __launch_bounds__(128, 2)
fused_attn(const __half* __restrict__ Q, const __half* __restrict__ Kg,
           const __half* __restrict__ Vt, __half* __restrict__ E,
           __half* __restrict__ ctx, float* __restrict__ rs)
{
    constexpr int QP = 72;
    constexpr int VP = 136;
    constexpr int QTILE = 64 * QP;          // halves
    constexpr int KTILE = 128 * QP;
    constexpr int VTILE = 64 * VP;
    constexpr int NC = SLEN / 128;

    const int tid = threadIdx.x;
    const int m0 = blockIdx.x * 64;
    const int bh = blockIdx.y;
    const int b = bh / NHEAD, h = bh % NHEAD;

    const __half* Qg = Q  + ((long)b * SLEN + m0) * DDIM + h * HDIM;
    const __half* Kb = Kg + ((long)b * SLEN) * DDIM + h * HDIM;
    const __half* Vg = Vt + (long)bh * HDIM * SLEN;
    __half* Eg = E + (long)bh * SLEN * SLEN;

    const int w = tid >> 5, lane = tid & 31;
    const int gid = lane >> 2, tg = lane & 3;
    const int wm = w & 1, wn = w >> 1;
    const int q8 = lane >> 3, r8 = lane & 7;
    const int rowA = wm * 32 + (q8 & 1) * 8 + r8, colA = (q8 >> 1) * 8;
    const int rowB = wn * 64 + (q8 >> 1) * 8 + r8, colB = (q8 & 1) * 8;
    const int rowV = (q8 >> 1) * 8 + r8,            colV = (q8 & 1) * 8;

    // analytic ones-column B fragment (row-sum via tensor core)
    const u32 bzc = (gid == 0) ? 0x3C003C00u : 0u;
    const u32 bz[2] = { bzc, bzc };

    extern __shared__ __align__(16) __half smem[];
    const u32 sbase = (u32)__cvta_generic_to_shared(smem);
    const u32 qb = sbase;
    auto kb = [&](int s) { return sbase + (QTILE + s * KTILE) * 2; };
    auto vb = [&](int s) { return sbase + (QTILE + 2 * KTILE + s * VTILE) * 2; };

    __shared__ float zs[2][32][2];
    __shared__ float siz[64];

    auto load_q = [&]() {
#pragma unroll
        for (int i = 0; i < 4; ++i) {
            int c = tid + i * 128; int row = c >> 3, cq = c & 7;
            cpa16(qb + (row * QP + cq * 8) * 2, Qg + (long)row * DDIM + cq * 8);
        }
    };
    auto issue = [&](int chunk) {
        const int stage = chunk & 1;
        const __half* Kp = Kb + (long)(chunk * 128) * DDIM;
        const u32 kbs = kb(stage);
#pragma unroll
        for (int i = 0; i < 8; ++i) {
            int c = tid + i * 128; int row = c >> 3, cq = c & 7;
            cpa16(kbs + (row * QP + cq * 8) * 2, Kp + (long)row * DDIM + cq * 8);
        }
        const __half* Vp = Vg + chunk * 128;
        const u32 vbs = vb(stage);
#pragma unroll
        for (int i = 0; i < 8; ++i) {
            int c = tid + i * 128; int row = c >> 4, cv = c & 15;
            cpa16(vbs + (row * VP + cv * 8) * 2, Vp + (long)row * SLEN + cv * 8);
        }
        cpa_commit();
    };

    float cU[2][8][4];
#pragma unroll
    for (int mi = 0; mi < 2; ++mi)
#pragma unroll
        for (int dj = 0; dj < 8; ++dj)
#pragma unroll
            for (int r = 0; r < 4; ++r) cU[mi][dj][r] = 0.f;
    float cUz[2][4];
#pragma unroll
    for (int mi = 0; mi < 2; ++mi)
#pragma unroll
        for (int r = 0; r < 4; ++r) cUz[mi][r] = 0.f;

    u32 qf[2][4][4];   // hoisted Q fragments: [mi][kf][reg]

    load_q();
    issue(0);
    issue(1);

    for (int kt = 0; kt < NC; ++kt) {
        cpa_wait1();
        __syncthreads();

        if (kt == 0) {   // Q resident after first wait: load fragments ONCE
#pragma unroll
            for (int mi = 0; mi < 2; ++mi)
#pragma unroll
                for (int kf = 0; kf < 4; ++kf)
                    ldsm4(qf[mi][kf][0], qf[mi][kf][1], qf[mi][kf][2], qf[mi][kf][3],
                          qb + ((rowA + mi * 16) * QP + kf * 16 + colA) * 2);
        }

        const int stage = kt & 1;
        const u32 kbs = kb(stage), vbs = vb(stage);
        const long ebase = (long)(m0 + wm * 32) * SLEN + kt * 128 + wn * 64;

        // ---- two independent 32-key halves -----------------------------------
#pragma unroll
        for (int hh = 0; hh < 2; ++hh) {
            // S' = Q' K^T for keys [32hh, 32hh+32)
            float cS[2][4][4];
#pragma unroll
            for (int mi = 0; mi < 2; ++mi)
#pragma unroll
                for (int nj = 0; nj < 4; ++nj)
#pragma unroll
                    for (int r = 0; r < 4; ++r) cS[mi][nj][r] = 0.f;

#pragma unroll
            for (int kf = 0; kf < 4; ++kf) {
                const int kk = kf * 16;
                u32 bfr[4][2];
#pragma unroll
                for (int p = 0; p < 2; ++p) {
                    const int pg = 2 * hh + p;
                    ldsm4(bfr[2 * p][0], bfr[2 * p][1], bfr[2 * p + 1][0], bfr[2 * p + 1][1],
                          kbs + ((rowB + pg * 16) * QP + kk + colB) * 2);
                }
#pragma unroll
                for (int mi = 0; mi < 2; ++mi)
#pragma unroll
                    for (int nj = 0; nj < 4; ++nj)
                        hmma(cS[mi][nj], qf[mi][kf], bfr[nj]);
            }

            // E = 2^S' in fp16
            u32 eh[2][4][2];
#pragma unroll
            for (int mi = 0; mi < 2; ++mi)
#pragma unroll
                for (int nj = 0; nj < 4; ++nj) {
                    eh[mi][nj][0] = ex2h2(pkh2(cS[mi][nj][0], cS[mi][nj][1]));
                    eh[mi][nj][1] = ex2h2(pkh2(cS[mi][nj][2], cS[mi][nj][3]));
                }

            // U += E * V ; Z += E * ones   (keys 32hh..32hh+31 => kfu = 2hh, 2hh+1)
#pragma unroll
            for (int j = 0; j < 2; ++j) {
                const int kfu = 2 * hh + j;
                const int kk2 = kfu * 16;
                u32 a[2][4], bv[8][2];
#pragma unroll
                for (int mi = 0; mi < 2; ++mi) {
                    a[mi][0] = eh[mi][2 * j][0];
                    a[mi][1] = eh[mi][2 * j][1];
                    a[mi][2] = eh[mi][2 * j + 1][0];
                    a[mi][3] = eh[mi][2 * j + 1][1];
                }
#pragma unroll
                for (int p = 0; p < 4; ++p)
                    ldsm4(bv[2 * p][0], bv[2 * p][1], bv[2 * p + 1][0], bv[2 * p + 1][1],
                          vbs + ((rowV + p * 16) * VP + wn * 64 + kk2 + colV) * 2);
#pragma unroll
                for (int mi = 0; mi < 2; ++mi) {
#pragma unroll
                    for (int dj = 0; dj < 8; ++dj)
                        hmma(cU[mi][dj], a[mi], bv[dj]);
                    hmma(cUz[mi], a[mi], bz);
                }
            }

            // stream E half to gmem
#pragma unroll
            for (int mi = 0; mi < 2; ++mi) {
                long r0 = ebase + (long)(mi * 16 + gid) * SLEN + hh * 32 + 2 * tg;
#pragma unroll
                for (int nj = 0; nj < 4; ++nj) {
                    *(u32*)&Eg[r0 + nj * 8]             = eh[mi][nj][0];
                    *(u32*)&Eg[r0 + 8L * SLEN + nj * 8] = eh[mi][nj][1];
                }
            }
        }

        __syncthreads();
        if (kt + 2 < NC) issue(kt + 2);
        else cpa_commit();
    }

    // ---- Z from tensor core: cUz col 64 (tg==0) -----------------------------------
    if (tg == 0) {
#pragma unroll
        for (int mi = 0; mi < 2; ++mi) {
            zs[wm][mi * 16 + gid][wn]     = cUz[mi][0];
            zs[wm][mi * 16 + 8 + gid][wn] = cUz[mi][2];
        }
    }
    __syncthreads();
    if (tid < 64) {
        float inv = 1.f / (zs[tid >> 5][tid & 31][0] + zs[tid >> 5][tid & 31][1]);
        siz[tid] = inv;
        rs[(long)bh * SLEN + m0 + tid] = inv;
    }
    __syncthreads();

    // ---- cross-warp U reduce (2-way over wn) through smem ---------------------------
    float* Ured = (float*)smem;
    if (wn == 1) {
#pragma unroll
        for (int mi = 0; mi < 2; ++mi) {
            int r = wm * 32 + mi * 16 + gid;
#pragma unroll
            for (int dj = 0; dj < 8; ++dj) {
                int n = dj * 8 + 2 * tg;
                *(float2*)&Ured[r * 68 + n]       = make_float2(cU[mi][dj][0], cU[mi][dj][1]);
                *(float2*)&Ured[(r + 8) * 68 + n] = make_float2(cU[mi][dj][2], cU[mi][dj][3]);
            }
        }
    }
    __syncthreads();
    if (wn == 0) {
#pragma unroll
        for (int mi = 0; mi < 2; ++mi) {
            int r = wm * 32 + mi * 16 + gid;
            float iz0 = siz[r], iz1 = siz[r + 8];
            __half* C0 = ctx + ((long)b * SLEN + m0 + r) * DDIM + h * HDIM;
#pragma unroll
            for (int dj = 0; dj < 8; ++dj) {
                int n = dj * 8 + 2 * tg;
                float2 u0 = *(const float2*)&Ured[r * 68 + n];
                float2 u1 = *(const float2*)&Ured[(r + 8) * 68 + n];
                *(u32*)&C0[n] = pkh2((cU[mi][dj][0] + u0.x) * iz0,
                                     (cU[mi][dj][1] + u0.y) * iz0);
                *(u32*)&C0[8L * DDIM + n] = pkh2((cU[mi][dj][2] + u1.x) * iz1,
                                                 (cU[mi][dj][3] + u1.y) * iz1);
            }
        }
    }
}

// ---------------- prep kernels ----------------------------------------------------
__global__ void __launch_bounds__(256)
prep_w(const float* __restrict__ W0, const float* __restrict__ W1,
       const float* __restrict__ W2, const float* __restrict__ W3,
       __half* __restrict__ Wt)
{
    const int z = blockIdx.z;
    const float* W = (z == 0) ? W0 : (z == 1) ? W1 : (z == 2) ? W2 : W3;
    __half* T = Wt + (long)z * DDIM * DDIM;
    __shared__ float t[32][33];
    const int tx = threadIdx.x, ty = threadIdx.y;
    const int n0 = blockIdx.x * 32, k0 = blockIdx.y * 32;
#pragma unroll
    for (int i = 0; i < 4; ++i)
        t[tx][ty + 8 * i] = W[(long)(k0 + ty + 8 * i) * DDIM + n0 + tx];
    __syncthreads();
#pragma unroll
    for (int i = 0; i < 4; ++i)
        T[(long)(n0 + ty + 8 * i) * DDIM + k0 + tx] = __float2half(t[ty + 8 * i][tx]);
}

__global__ void __launch_bounds__(256)
prep_x(const float* __restrict__ x, __half* __restrict__ xh)
{
    long i = ((long)blockIdx.x * 256 + threadIdx.x) * 8;
    float4 f0 = *(const float4*)(x + i);
    float4 f1 = *(const float4*)(x + i + 4);
    uint4 u;
    u.x = pkh2(f0.x, f0.y); u.y = pkh2(f0.z, f0.w);
    u.z = pkh2(f1.x, f1.y); u.w = pkh2(f1.z, f1.w);
    *(uint4*)(xh + i) = u;
}

// ---------------- launch -----------------------------------------------------------
extern "C" void kernel_launch(void* const* d_in, const int* in_sizes, int n_in,
                              void* d_out, int out_size)
{
    const float* x  = (const float*)d_in[0];
    const float* Wq = (const float*)d_in[1];
    const float* bq = (const float*)d_in[2];
    const float* Wk = (const float*)d_in[3];
    const float* bk = (const float*)d_in[4];
    const float* Wv = (const float*)d_in[5];
    const float* bv = (const float*)d_in[6];
    const float* Wo = (const float*)d_in[7];
    const float* bo = (const float*)d_in[8];
    float* out = (float*)d_out;

    const int Bsz = in_sizes[0] / (SLEN * DDIM);   // = 2
    const int BS  = Bsz * SLEN;
    const long NB = (long)BS * DDIM;

    __half *wt, *xh, *qk, *vt, *E, *ctx;
    float *b3, *rs;
    cudaGetSymbolAddress((void**)&wt,  g_wt);
    cudaGetSymbolAddress((void**)&b3,  g_b3);
    cudaGetSymbolAddress((void**)&xh,  g_xh);
    cudaGetSymbolAddress((void**)&qk,  g_qk);
    cudaGetSymbolAddress((void**)&vt,  g_vt);
    cudaGetSymbolAddress((void**)&E,   g_E);
    cudaGetSymbolAddress((void**)&ctx, g_ctx);
    cudaGetSymbolAddress((void**)&rs,  g_rs);

    const int SM_P = 3 * 2 * 128 * 72 * 2;                        // 110592 (gemm core)
    const int SM_F = (64 * 72 + 2 * 128 * 72 + 2 * 64 * 136) * 2; // 80896 (fused v4)
    cudaFuncSetAttribute(qkv_proj,   cudaFuncAttributeMaxDynamicSharedMemorySize, SM_P);
    cudaFuncSetAttribute(outmerge,   cudaFuncAttributeMaxDynamicSharedMemorySize, SM_P);
    cudaFuncSetAttribute(fused_attn, cudaFuncAttributeMaxDynamicSharedMemorySize, SM_F);

    cudaMemcpyAsync(b3,            bq, sizeof(float) * DDIM, cudaMemcpyDeviceToDevice);
    cudaMemcpyAsync(b3 + DDIM,     bk, sizeof(float) * DDIM, cudaMemcpyDeviceToDevice);
    cudaMemcpyAsync(b3 + 2 * DDIM, bv, sizeof(float) * DDIM, cudaMemcpyDeviceToDevice);

    prep_x<<<(unsigned)(NB / (256 * 8)), 256>>>(x, xh);
    prep_w<<<dim3(32, 32, 4), dim3(32, 8)>>>(Wq, Wk, Wv, Wo, wt);

    const long QKoff = (long)BS * DDIM;

    qkv_proj<<<dim3(8, BS / 128, 3), 256, SM_P>>>(xh, wt, b3, qk, vt, QKoff);

    fused_attn<<<dim3(SLEN / 64, Bsz * NHEAD), 128, SM_F>>>(
        qk, qk + QKoff, vt, E, ctx, rs);

    outmerge<<<256 + BS, 256, SM_P>>>(
        ctx, wt + 3L * DDIM * DDIM, bo, out, E, rs, out + NB);
}